// round 8
// baseline (speedup 1.0000x reference)
#include <cuda_runtime.h>
#include <cuda_bf16.h>
#include <cstdint>
#include <cstddef>

#define NPIX 200

// ---- gmem scratch (static; zero-initialized at load — pad rows rely on it) --
__device__ __align__(16) uint8_t g_wh[3u*4*16*10240];          //  2 MB
__device__ __align__(16) uint8_t g_wl[3u*4*16*10240];
__device__ __align__(16) uint8_t g_finh[3u*128*16*17920];      // 110 MB
__device__ __align__(16) uint8_t g_finl[3u*128*16*17920];
__device__ __align__(16) uint8_t g_fouth[3u*128*16*20480];     // 126 MB
__device__ __align__(16) uint8_t g_foutl[3u*128*16*20480];
__device__ float g_gram[3u*128*200*200];                       //  61 MB
__device__ float g_corrvec[128*600];
__device__ float g_catvec[128*600];

// smem: 3 stages of 56320: AH(10240) AL(10240) BH(17920) BL(17920); ctrl after.
#define STAGE_B   56320
#define SM_CTRL   168960
#define GEMM_SMEM (SM_CTRL + 64)

__device__ __forceinline__ uint32_t smem_u32(const void* p) {
    uint32_t r;
    asm("{ .reg .u64 t; cvta.to.shared.u64 t, %1; cvt.u32.u64 %0, t; }" : "=r"(r) : "l"(p));
    return r;
}
#define MBAR_INIT(a, c) asm volatile("mbarrier.init.shared.b64 [%0], %1;" :: "r"(a), "r"(c) : "memory")
#define MBAR_EXPECT(a, n) asm volatile("mbarrier.arrive.expect_tx.shared.b64 _, [%0], %1;" :: "r"(a), "r"(n) : "memory")
#define MBAR_ARRIVE(a) asm volatile("mbarrier.arrive.shared.b64 _, [%0];" :: "r"(a) : "memory")
#define MBAR_WAIT(a, ph) \
    asm volatile("{\n\t.reg .pred P;\n\tW_%=:\n\t" \
                 "mbarrier.try_wait.parity.acquire.cta.shared::cta.b64 P, [%0], %1, 0x989680;\n\t" \
                 "@!P bra W_%=;\n\t}" :: "r"(a), "r"(ph) : "memory")
#define BULK_G2S(dst, src, bytes, mbar) \
    asm volatile("cp.async.bulk.shared::cluster.global.mbarrier::complete_tx::bytes [%0], [%1], %2, [%3];" \
                 :: "r"(dst), "l"(src), "r"(bytes), "r"(mbar) : "memory")

__device__ __forceinline__ void ldsm4(uint32_t* r, uint32_t a) {
    asm volatile("ldmatrix.sync.aligned.m8n8.x4.shared.b16 {%0,%1,%2,%3}, [%4];"
        : "=r"(r[0]), "=r"(r[1]), "=r"(r[2]), "=r"(r[3]) : "r"(a));
}
__device__ __forceinline__ void ldsm2(uint32_t* r, uint32_t a) {
    asm volatile("ldmatrix.sync.aligned.m8n8.x2.shared.b16 {%0,%1}, [%2];"
        : "=r"(r[0]), "=r"(r[1]) : "r"(a));
}
__device__ __forceinline__ void mma16816(float* c, const uint32_t* a, const uint32_t* b) {
    asm volatile("mma.sync.aligned.m16n8k16.row.col.f32.bf16.bf16.f32 "
        "{%0,%1,%2,%3}, {%4,%5,%6,%7}, {%8,%9}, {%0,%1,%2,%3};"
        : "+f"(c[0]), "+f"(c[1]), "+f"(c[2]), "+f"(c[3])
        : "r"(a[0]), "r"(a[1]), "r"(a[2]), "r"(a[3]), "r"(b[0]), "r"(b[1]));
}
__device__ __forceinline__ void pack8(const float* v, uint4& h, uint4& l) {
    __align__(16) __nv_bfloat16 hb[8], lb[8];
#pragma unroll
    for (int u = 0; u < 8; u++) {
        hb[u] = __float2bfloat16_rn(v[u]);
        lb[u] = __float2bfloat16_rn(v[u] - __bfloat162float(hb[u]));
    }
    h = *reinterpret_cast<uint4*>(hb);
    l = *reinterpret_cast<uint4*>(lb);
}
__device__ __forceinline__ float2 bf2f(uint32_t u) {
    __nv_bfloat162 h = *reinterpret_cast<__nv_bfloat162*>(&u);
    return __bfloat1622float2(h);
}

// ---- weights W[m][k] fp32 -> hi/lo bf16, [t][mt][slab16][row128][40 halves] --
__global__ __launch_bounds__(256) void convert_w_kernel(
    const float* __restrict__ Wa, const float* __restrict__ Wb, const float* __restrict__ Wc,
    uint8_t* __restrict__ oh, uint8_t* __restrict__ ol)
{
    int idx = blockIdx.x * 256 + threadIdx.x;   // 3*512*64 = 98304
    int t = idx / 32768, r = idx - t * 32768;
    int m = r >> 6, g8 = r & 63;
    const float* W = (t == 0) ? Wa : ((t == 1) ? Wb : Wc);
    float v[8];
#pragma unroll
    for (int u = 0; u < 8; u++) v[u] = W[m * 512 + g8 * 8 + u];
    uint4 vh, vl; pack8(v, vh, vl);
    int mt = m >> 7, mr = m & 127, slab = g8 >> 2, c8 = g8 & 3;
    size_t off = ((size_t)(t * 4 + mt) * 16 + slab) * 10240 + mr * 80 + c8 * 16;
    *(uint4*)(oh + off) = vh;
    *(uint4*)(ol + off) = vl;
}

// ---- input feats [b][c][p] -> transposed [t][b][slab16][row p][40 halves] ----
__global__ __launch_bounds__(256) void convert_feat_kernel(
    const float* __restrict__ f1, const float* __restrict__ f2, const float* __restrict__ f3,
    uint8_t* __restrict__ oh, uint8_t* __restrict__ ol)
{
    __shared__ float s[32 * 201];
    const int b = blockIdx.x, t = blockIdx.y, tid = threadIdx.x;
    const float* F = ((t == 0) ? f1 : ((t == 1) ? f2 : f3)) + (size_t)b * 102400;
    uint8_t* obh = oh + ((size_t)t * 128 + b) * 286720;
    uint8_t* obl = ol + ((size_t)t * 128 + b) * 286720;
    for (int c = 0; c < 16; c++) {
        __syncthreads();
        for (int e = tid; e < 32 * 200; e += 256) {
            int kk = e / 200, n = e - kk * 200;
            s[kk * 201 + n] = F[(size_t)(c * 32 + kk) * 200 + n];
        }
        __syncthreads();
        for (int i = tid; i < 800; i += 256) {
            int p = i >> 2, g8 = i & 3;
            float v[8];
#pragma unroll
            for (int u = 0; u < 8; u++) v[u] = s[(g8 * 8 + u) * 201 + p];
            uint4 vh, vl; pack8(v, vh, vl);
            size_t off = (size_t)c * 17920 + p * 80 + g8 * 16;
            *(uint4*)(obh + off) = vh;
            *(uint4*)(obl + off) = vl;
        }
    }
}

// ---- hi/lo split bf16 GEMM via mma.sync: 512 thr, 16 warps (4Mx4N), 3 stages -
// MODE0 conv1x1: C[m,p] = W·F + bias -> transposed bf16 hi/lo slab output
// MODE1 gram:    C[p1,p2] -> fp32 G   (Mvalid masks rows >= 200)
template <int MODE>
__global__ __launch_bounds__(512) void gemm_mma_kernel(
    const uint8_t* __restrict__ Ah, const uint8_t* __restrict__ Al,
    const uint8_t* __restrict__ Bh, const uint8_t* __restrict__ Bl,
    const float* __restrict__ b0, const float* __restrict__ b1, const float* __restrict__ b2,
    float* __restrict__ G, uint8_t* __restrict__ Oh, uint8_t* __restrict__ Ol)
{
    extern __shared__ __align__(128) uint8_t smem[];
    const int tid = threadIdx.x;
    const int mt = blockIdx.x, b = blockIdx.y, z = blockIdx.z;
    const uint32_t sb = smem_u32(smem);
    const int warp = tid >> 5, lane = tid & 31;
    const int warpM = warp & 3, warpN = warp >> 2;
    const int Mvalid = (MODE == 0) ? 128 : (200 - mt * 128);

    const uint32_t CTRL = sb + SM_CTRL;
    if (tid == 0) {
#pragma unroll
        for (int p = 0; p < 3; p++) {
            MBAR_INIT(CTRL + p * 8, 1);        // FULL[p]
            MBAR_INIT(CTRL + 24 + p * 8, 512); // CONS[p]
        }
    }
    __syncthreads();

    const uint8_t *pAh, *pAl, *pBh, *pBl;
    size_t aStep, bStep;
    if (MODE == 0) {
        size_t ao = (size_t)(z * 4 + mt) * 163840;
        size_t bo = (size_t)(z * 128 + b) * 286720;
        pAh = Ah + ao; pAl = Al + ao; pBh = Bh + bo; pBl = Bl + bo;
        aStep = 10240; bStep = 17920;
    } else {
        int pa = (z == 2) ? 1 : 0, pb = (z == 0) ? 1 : 2;
        size_t ao = (size_t)(pa * 128 + b) * 327680 + (size_t)mt * 10240;
        size_t bo = (size_t)(pb * 128 + b) * 327680;
        pAh = Ah + ao; pAl = Al + ao; pBh = Bh + bo; pBl = Bl + bo;
        aStep = 20480; bStep = 20480;
    }

    float c[2][7][4];
#pragma unroll
    for (int i = 0; i < 2; i++)
#pragma unroll
        for (int j = 0; j < 7; j++)
#pragma unroll
            for (int k = 0; k < 4; k++) c[i][j][k] = 0.f;

    int phF[3] = {0, 0, 0}, phC[3] = {0, 0, 0};
    for (int s = 0; s < 16; s++) {
        const int p = (s >= 15) ? (s - 15) : (s >= 12 ? s - 12 : (s >= 9 ? s - 9 : (s >= 6 ? s - 6 : (s >= 3 ? s - 3 : s))));
        const uint32_t st = sb + p * STAGE_B;
        if (tid == 0) {
            if (s >= 3) { MBAR_WAIT(CTRL + 24 + p * 8, phC[p]); phC[p] ^= 1; }
            MBAR_EXPECT(CTRL + p * 8, STAGE_B);
            BULK_G2S(st,         pAh + (size_t)s * aStep, 10240, CTRL + p * 8);
            BULK_G2S(st + 10240, pAl + (size_t)s * aStep, 10240, CTRL + p * 8);
            BULK_G2S(st + 20480, pBh + (size_t)s * bStep, 17920, CTRL + p * 8);
            BULK_G2S(st + 38400, pBl + (size_t)s * bStep, 17920, CTRL + p * 8);
        }
        MBAR_WAIT(CTRL + p * 8, phF[p]); phF[p] ^= 1;

        const uint32_t aBase = st + (warpM * 32 + (lane & 15)) * 80 + (lane & 16);
        const uint32_t bBase = st + 20480 + (warpN * 56 + (lane & 7)) * 80 + (lane & 8) * 2;
#pragma unroll
        for (int ks = 0; ks < 2; ks++) {
            const uint32_t kb = ks * 32;
            uint32_t bh[7][2], bl[7][2];
#pragma unroll
            for (int ni = 0; ni < 7; ni++) {
                ldsm2(bh[ni], bBase + ni * 640 + kb);
                ldsm2(bl[ni], bBase + 17920 + ni * 640 + kb);
            }
#pragma unroll
            for (int mi = 0; mi < 2; mi++) {
                if (warpM * 32 + mi * 16 >= Mvalid) continue;
                uint32_t ah[4], al[4];
                ldsm4(ah, aBase + mi * 1280 + kb);
                ldsm4(al, aBase + 10240 + mi * 1280 + kb);
#pragma unroll
                for (int ni = 0; ni < 7; ni++) {
                    mma16816(c[mi][ni], ah, bh[ni]);
                    mma16816(c[mi][ni], ah, bl[ni]);
                    mma16816(c[mi][ni], al, bh[ni]);
                }
            }
        }
        MBAR_ARRIVE(CTRL + 24 + p * 8);
    }
    __syncthreads();

    if (MODE == 0) {
        const float* bias = (z == 0) ? b0 : ((z == 1) ? b1 : b2);
        __nv_bfloat16* sH = reinterpret_cast<__nv_bfloat16*>(smem);   // [p<200][m128]
        __nv_bfloat16* sL = sH + 25600;
#pragma unroll
        for (int mi = 0; mi < 2; mi++) {
            const int m0 = warpM * 32 + mi * 16 + (lane >> 2);
            const float bv0 = __ldg(bias + mt * 128 + m0);
            const float bv1 = __ldg(bias + mt * 128 + m0 + 8);
#pragma unroll
            for (int ni = 0; ni < 7; ni++) {
                const int p0 = warpN * 56 + ni * 8 + (lane & 3) * 2;
                if (p0 >= 200) continue;
                float v[4] = {c[mi][ni][0] + bv0, c[mi][ni][1] + bv0,
                              c[mi][ni][2] + bv1, c[mi][ni][3] + bv1};
#pragma unroll
                for (int q = 0; q < 4; q++) {
                    const int pp = p0 + (q & 1), mm = m0 + (q < 2 ? 0 : 8);
                    __nv_bfloat16 h = __float2bfloat16_rn(v[q]);
                    sH[pp * 128 + mm] = h;
                    sL[pp * 128 + mm] = __float2bfloat16_rn(v[q] - __bfloat162float(h));
                }
            }
        }
        __syncthreads();
        uint8_t* ohB = Oh + ((size_t)(z * 128 + b) * 16 + mt * 4) * 20480;
        uint8_t* olB = Ol + ((size_t)(z * 128 + b) * 16 + mt * 4) * 20480;
        for (int g = tid; g < 3200; g += 512) {
            int pp = g >> 4, o = g & 15, q = o >> 2, oo = o & 3;
            uint32_t so = (pp * 128 + q * 32 + oo * 8) * 2;
            size_t dof = (size_t)q * 20480 + pp * 80 + oo * 16;
            *(uint4*)(ohB + dof) = *(uint4*)((uint8_t*)sH + so);
            *(uint4*)(olB + dof) = *(uint4*)((uint8_t*)sL + so);
        }
    } else {
        float* Gb = G + ((size_t)z * 128 + b) * 40000;
#pragma unroll
        for (int mi = 0; mi < 2; mi++) {
            const int m0 = mt * 128 + warpM * 32 + mi * 16 + (lane >> 2);
#pragma unroll
            for (int ni = 0; ni < 7; ni++) {
                const int n0 = warpN * 56 + ni * 8 + (lane & 3) * 2;
                if (n0 >= 200) continue;
                if (m0 < 200)
                    *(float2*)(Gb + (size_t)m0 * 200 + n0) = make_float2(c[mi][ni][0], c[mi][ni][1]);
                if (m0 + 8 < 200)
                    *(float2*)(Gb + (size_t)(m0 + 8) * 200 + n0) = make_float2(c[mi][ni][2], c[mi][ni][3]);
            }
        }
    }
}

// ---- corr head: gather from Gram + leaky + conv3x3 + relu -------------------
__global__ __launch_bounds__(256)
void corr_head_kernel(const float* __restrict__ Gram, const float* __restrict__ Wcorr,
                      const float* __restrict__ bcorr, float* __restrict__ corrvec)
{
    extern __shared__ float sh[];
    float* sG = sh;
    float* sW = sh + 40000;
    const int b = blockIdx.x, tid = threadIdx.x;
    const int y = tid / 20, x = tid - y * 20;
    float acc0 = 0.f, acc1 = 0.f, acc2 = 0.f;

    for (int pair = 0; pair < 3; pair++) {
        __syncthreads();
        const float4* G4 = reinterpret_cast<const float4*>(Gram + ((size_t)pair * 128 + b) * 40000);
        float4* sG4 = reinterpret_cast<float4*>(sG);
        for (int i = tid; i < 10000; i += 256) sG4[i] = G4[i];
        for (int i = tid; i < 11907; i += 256) {
            int o = i / 3969, r = i - o * 3969;
            sW[i] = Wcorr[o * 11907 + pair * 3969 + r];
        }
        __syncthreads();
        if (tid < NPIX) {
            for (int ky = 0; ky < 3; ky++) {
                int sy = y + ky - 1;
                if ((unsigned)sy >= 10u) continue;
                for (int kx = 0; kx < 3; kx++) {
                    int sx = x + kx - 1;
                    if ((unsigned)sx >= 20u) continue;
                    const float* grow0 = sG + (sy * 20 + sx) * 200;
                    const int tap = ky * 3 + kx;
                    const int dyi0 = (21 - sy) >> 1, dxi0 = (21 - sx) >> 1;
                    const int p2y0 = sy + 2 * dyi0 - 20, p2x0 = sx + 2 * dxi0 - 20;
                    for (int iy = 0; iy < 5; iy++) {
                        const float* grow = grow0 + (p2y0 + 2 * iy) * 20 + p2x0;
                        const float* wrow = sW + ((dyi0 + iy) * 21 + dxi0) * 9 + tap;
#pragma unroll
                        for (int ix = 0; ix < 10; ix++) {
                            float g = grow[2 * ix] * (1.f / 512.f);
                            float v = g > 0.f ? g : 0.1f * g;
                            acc0 += v * wrow[ix * 9];
                            acc1 += v * wrow[3969 + ix * 9];
                            acc2 += v * wrow[7938 + ix * 9];
                        }
                    }
                }
            }
        }
    }
    if (tid < NPIX) {
        corrvec[b * 600 + tid]       = fmaxf(acc0 + bcorr[0], 0.f);
        corrvec[b * 600 + 200 + tid] = fmaxf(acc1 + bcorr[1], 0.f);
        corrvec[b * 600 + 400 + tid] = fmaxf(acc2 + bcorr[2], 0.f);
    }
}

// ---- cat head: conv3x3 over concat(f1,f2,f3) from hi/lo slab layout ---------
__global__ __launch_bounds__(256)
void cat_head_kernel(const uint8_t* __restrict__ Fh, const uint8_t* __restrict__ Fl,
                     const float* __restrict__ Wcat, const float* __restrict__ bcat,
                     float* __restrict__ catvec)
{
    extern __shared__ float sh[];
    float* sF = sh;             // [(t*200+p)*68 + c]
    float* sW = sh + 40800;
    const int b = blockIdx.x, tid = threadIdx.x;
    const int y = tid / 20, x = tid - y * 20;
    float acc0 = 0.f, acc1 = 0.f, acc2 = 0.f;

    for (int cc = 0; cc < 512; cc += 64) {
        __syncthreads();
        for (int g = tid; g < 4800; g += 256) {
            int t = g / 1600, r = g - t * 1600, p = r >> 3, g8 = r & 7;
            int slab = (cc >> 5) + (g8 >> 2);
            size_t base = (((size_t)t * 128 + b) * 16 + slab) * 20480 + p * 80 + (g8 & 3) * 16;
            uint4 vh = *(const uint4*)(Fh + base);
            uint4 vl = *(const uint4*)(Fl + base);
            float* d = &sF[(t * 200 + p) * 68 + g8 * 8];
            float2 a0 = bf2f(vh.x), c0 = bf2f(vl.x); d[0] = a0.x + c0.x; d[1] = a0.y + c0.y;
            float2 a1 = bf2f(vh.y), c1 = bf2f(vl.y); d[2] = a1.x + c1.x; d[3] = a1.y + c1.y;
            float2 a2 = bf2f(vh.z), c2 = bf2f(vl.z); d[4] = a2.x + c2.x; d[5] = a2.y + c2.y;
            float2 a3 = bf2f(vh.w), c3 = bf2f(vl.w); d[6] = a3.x + c3.x; d[7] = a3.y + c3.y;
        }
        for (int i = tid; i < 5184; i += 256) {
            int o = i / 1728, r = i - o * 1728, t = r / 576, r2 = r - t * 576;
            int tap = r2 >> 6, cch = r2 & 63;
            sW[i] = Wcat[(size_t)(o * 1536 + t * 512 + cc + cch) * 9 + tap];
        }
        __syncthreads();
        if (tid < NPIX) {
            for (int t = 0; t < 3; t++)
                for (int ky = 0; ky < 3; ky++) {
                    int sy = y + ky - 1;
                    if ((unsigned)sy >= 10u) continue;
                    for (int kx = 0; kx < 3; kx++) {
                        int sx = x + kx - 1;
                        if ((unsigned)sx >= 20u) continue;
                        const float4* v4 = reinterpret_cast<const float4*>(sF + (t * 200 + sy * 20 + sx) * 68);
                        int tap = ky * 3 + kx;
                        const float4* w0 = reinterpret_cast<const float4*>(sW + (t * 9 + tap) * 64);
                        const float4* w1 = reinterpret_cast<const float4*>(sW + 1728 + (t * 9 + tap) * 64);
                        const float4* w2 = reinterpret_cast<const float4*>(sW + 3456 + (t * 9 + tap) * 64);
#pragma unroll
                        for (int c4 = 0; c4 < 16; c4++) {
                            float4 v = v4[c4];
                            float4 a = w0[c4], bq = w1[c4], cq = w2[c4];
                            acc0 += v.x * a.x + v.y * a.y + v.z * a.z + v.w * a.w;
                            acc1 += v.x * bq.x + v.y * bq.y + v.z * bq.z + v.w * bq.w;
                            acc2 += v.x * cq.x + v.y * cq.y + v.z * cq.z + v.w * cq.w;
                        }
                    }
                }
        }
    }
    if (tid < NPIX) {
        catvec[b * 600 + tid]       = acc0 + bcat[0];
        catvec[b * 600 + 200 + tid] = acc1 + bcat[1];
        catvec[b * 600 + 400 + tid] = acc2 + bcat[2];
    }
}

// ---- MLP heads + final linear ------------------------------------------------
__global__ __launch_bounds__(256)
void mlp_kernel(const float* __restrict__ corrvec, const float* __restrict__ catvec,
                const float* __restrict__ cf_w1, const float* __restrict__ cf_b1,
                const float* __restrict__ cf_w2, const float* __restrict__ cf_b2,
                const float* __restrict__ ccf_w1, const float* __restrict__ ccf_b1,
                const float* __restrict__ ccf_w2, const float* __restrict__ ccf_b2,
                const float* __restrict__ Wout, const float* __restrict__ bout,
                float* __restrict__ out)
{
    __shared__ float sx[600];
    __shared__ float h1[256];
    __shared__ float h2[2][128];
    const int b = blockIdx.x, tid = threadIdx.x;

    for (int path = 0; path < 2; path++) {
        const float* xv = (path == 0 ? corrvec : catvec) + b * 600;
        const float* w1 = path == 0 ? cf_w1 : ccf_w1;
        const float* b1 = path == 0 ? cf_b1 : ccf_b1;
        const float* w2 = path == 0 ? cf_w2 : ccf_w2;
        const float* b2 = path == 0 ? cf_b2 : ccf_b2;
        __syncthreads();
        for (int i = tid; i < 600; i += 256) sx[i] = xv[i];
        __syncthreads();
        {
            float s = b1[tid];
            const float4* wr = reinterpret_cast<const float4*>(w1 + (size_t)tid * 600);
#pragma unroll 4
            for (int k = 0; k < 150; k++) {
                float4 w = wr[k];
                s += w.x * sx[4*k] + w.y * sx[4*k+1] + w.z * sx[4*k+2] + w.w * sx[4*k+3];
            }
            h1[tid] = fmaxf(s, 0.f);
        }
        __syncthreads();
        if (tid < 128) {
            float s = b2[tid];
            const float4* wr = reinterpret_cast<const float4*>(w2 + (size_t)tid * 256);
#pragma unroll 4
            for (int k = 0; k < 64; k++) {
                float4 w = wr[k];
                s += w.x * h1[4*k] + w.y * h1[4*k+1] + w.z * h1[4*k+2] + w.w * h1[4*k+3];
            }
            h2[path][tid] = fmaxf(s, 0.f);
        }
    }
    __syncthreads();
    if (tid < 2) {
        float s = bout[tid];
        const float* wr = Wout + tid * 256;
        for (int i = 0; i < 128; i++)
            s += h2[0][i] * wr[i] + h2[1][i] * wr[128 + i];
        out[b * 2 + tid] = s;
    }
}

// ---- launch -------------------------------------------------------------------
extern "C" void kernel_launch(void* const* d_in, const int* in_sizes, int n_in,
                              void* d_out, int out_size)
{
    (void)in_sizes; (void)n_in; (void)out_size;
    const float* feat1 = (const float*)d_in[0];
    const float* feat2 = (const float*)d_in[1];
    const float* feat3 = (const float*)d_in[2];
    const float* Wa = (const float*)d_in[3];   const float* ba = (const float*)d_in[4];
    const float* Wb = (const float*)d_in[5];   const float* bb = (const float*)d_in[6];
    const float* Wc = (const float*)d_in[7];   const float* bc = (const float*)d_in[8];
    const float* Wcorr = (const float*)d_in[9];  const float* bcorr = (const float*)d_in[10];
    const float* Wcat = (const float*)d_in[11];  const float* bcat = (const float*)d_in[12];
    const float* cf_w1 = (const float*)d_in[13]; const float* cf_b1 = (const float*)d_in[14];
    const float* cf_w2 = (const float*)d_in[15]; const float* cf_b2 = (const float*)d_in[16];
    const float* ccf_w1 = (const float*)d_in[17]; const float* ccf_b1 = (const float*)d_in[18];
    const float* ccf_w2 = (const float*)d_in[19]; const float* ccf_b2 = (const float*)d_in[20];
    const float* Wout = (const float*)d_in[21];  const float* bout = (const float*)d_in[22];

    uint8_t *wh, *wl, *fih, *fil, *foh, *fol;
    float *G, *cv, *tv;
    cudaGetSymbolAddress((void**)&wh,  g_wh);
    cudaGetSymbolAddress((void**)&wl,  g_wl);
    cudaGetSymbolAddress((void**)&fih, g_finh);
    cudaGetSymbolAddress((void**)&fil, g_finl);
    cudaGetSymbolAddress((void**)&foh, g_fouth);
    cudaGetSymbolAddress((void**)&fol, g_foutl);
    cudaGetSymbolAddress((void**)&G,   g_gram);
    cudaGetSymbolAddress((void**)&cv,  g_corrvec);
    cudaGetSymbolAddress((void**)&tv,  g_catvec);

    cudaFuncSetAttribute(gemm_mma_kernel<0>, cudaFuncAttributeMaxDynamicSharedMemorySize, GEMM_SMEM);
    cudaFuncSetAttribute(gemm_mma_kernel<1>, cudaFuncAttributeMaxDynamicSharedMemorySize, GEMM_SMEM);

    convert_w_kernel<<<384, 256>>>(Wa, Wb, Wc, wh, wl);
    convert_feat_kernel<<<dim3(128, 3), 256>>>(feat1, feat2, feat3, fih, fil);

    // conv1x1 per (mtile4, batch, tensor)
    gemm_mma_kernel<0><<<dim3(4, 128, 3), 512, GEMM_SMEM>>>(
        wh, wl, fih, fil, ba, bb, bc, nullptr, foh, fol);

    // Gram per (mtile2, batch, pair)
    gemm_mma_kernel<1><<<dim3(2, 128, 3), 512, GEMM_SMEM>>>(
        foh, fol, foh, fol, nullptr, nullptr, nullptr, G, nullptr, nullptr);

    const int CORR_SMEM = (40000 + 11907) * 4;
    cudaFuncSetAttribute(corr_head_kernel, cudaFuncAttributeMaxDynamicSharedMemorySize, CORR_SMEM);
    corr_head_kernel<<<128, 256, CORR_SMEM>>>(G, Wcorr, bcorr, cv);

    const int CAT_SMEM = (40800 + 5184) * 4;
    cudaFuncSetAttribute(cat_head_kernel, cudaFuncAttributeMaxDynamicSharedMemorySize, CAT_SMEM);
    cat_head_kernel<<<128, 256, CAT_SMEM>>>(foh, fol, Wcat, bcat, tv);

    mlp_kernel<<<128, 256>>>(cv, tv, cf_w1, cf_b1, cf_w2, cf_b2,
                             ccf_w1, ccf_b1, ccf_w2, ccf_b2, Wout, bout, (float*)d_out);
}

// round 9
// speedup vs baseline: 1.2248x; 1.2248x over previous
#include <cuda_runtime.h>
#include <cuda_bf16.h>
#include <cstdint>
#include <cstddef>

#define NPIX 200

// ---- gmem scratch (static; zero-initialized at load — pad rows rely on it) --
__device__ __align__(16) uint8_t g_wh[3u*4*16*10240];          //  2 MB
__device__ __align__(16) uint8_t g_wl[3u*4*16*10240];
__device__ __align__(16) uint8_t g_finh[3u*128*16*17920];      // 110 MB
__device__ __align__(16) uint8_t g_finl[3u*128*16*17920];
__device__ __align__(16) uint8_t g_fouth[3u*128*16*20480];     // 126 MB
__device__ __align__(16) uint8_t g_foutl[3u*128*16*20480];
__device__ float g_gram[3u*128*200*200];                       //  61 MB
__device__ float g_corrvec[128*600];
__device__ float g_catvec[128*600];

// smem: 3 stages of 56320: AH(10240) AL(10240) BH(17920) BL(17920); ctrl after.
#define STAGE_B   56320
#define SM_CTRL   168960
#define GEMM_SMEM (SM_CTRL + 64)

__device__ __forceinline__ uint32_t smem_u32(const void* p) {
    uint32_t r;
    asm("{ .reg .u64 t; cvta.to.shared.u64 t, %1; cvt.u32.u64 %0, t; }" : "=r"(r) : "l"(p));
    return r;
}
#define MBAR_INIT(a, c) asm volatile("mbarrier.init.shared.b64 [%0], %1;" :: "r"(a), "r"(c) : "memory")
#define MBAR_EXPECT(a, n) asm volatile("mbarrier.arrive.expect_tx.shared.b64 _, [%0], %1;" :: "r"(a), "r"(n) : "memory")
#define MBAR_WAIT(a, ph) \
    asm volatile("{\n\t.reg .pred P;\n\tW_%=:\n\t" \
                 "mbarrier.try_wait.parity.acquire.cta.shared::cta.b64 P, [%0], %1, 0x989680;\n\t" \
                 "@!P bra W_%=;\n\t}" :: "r"(a), "r"(ph) : "memory")
#define BULK_G2S(dst, src, bytes, mbar) \
    asm volatile("cp.async.bulk.shared::cluster.global.mbarrier::complete_tx::bytes [%0], [%1], %2, [%3];" \
                 :: "r"(dst), "l"(src), "r"(bytes), "r"(mbar) : "memory")

__device__ __forceinline__ void ldsm4(uint32_t* r, uint32_t a) {
    asm volatile("ldmatrix.sync.aligned.m8n8.x4.shared.b16 {%0,%1,%2,%3}, [%4];"
        : "=r"(r[0]), "=r"(r[1]), "=r"(r[2]), "=r"(r[3]) : "r"(a));
}
__device__ __forceinline__ void ldsm2(uint32_t* r, uint32_t a) {
    asm volatile("ldmatrix.sync.aligned.m8n8.x2.shared.b16 {%0,%1}, [%2];"
        : "=r"(r[0]), "=r"(r[1]) : "r"(a));
}
__device__ __forceinline__ void mma16816(float* c, const uint32_t* a, const uint32_t* b) {
    asm volatile("mma.sync.aligned.m16n8k16.row.col.f32.bf16.bf16.f32 "
        "{%0,%1,%2,%3}, {%4,%5,%6,%7}, {%8,%9}, {%0,%1,%2,%3};"
        : "+f"(c[0]), "+f"(c[1]), "+f"(c[2]), "+f"(c[3])
        : "r"(a[0]), "r"(a[1]), "r"(a[2]), "r"(a[3]), "r"(b[0]), "r"(b[1]));
}
__device__ __forceinline__ void pack8(const float* v, uint4& h, uint4& l) {
    __align__(16) __nv_bfloat16 hb[8], lb[8];
#pragma unroll
    for (int u = 0; u < 8; u++) {
        hb[u] = __float2bfloat16_rn(v[u]);
        lb[u] = __float2bfloat16_rn(v[u] - __bfloat162float(hb[u]));
    }
    h = *reinterpret_cast<uint4*>(hb);
    l = *reinterpret_cast<uint4*>(lb);
}
__device__ __forceinline__ float2 bf2f(uint32_t u) {
    __nv_bfloat162 h = *reinterpret_cast<__nv_bfloat162*>(&u);
    return __bfloat1622float2(h);
}

// ---- weights W[m][k] fp32 -> hi/lo bf16, [t][mt][slab16][row128][40 halves] --
__global__ __launch_bounds__(256) void convert_w_kernel(
    const float* __restrict__ Wa, const float* __restrict__ Wb, const float* __restrict__ Wc,
    uint8_t* __restrict__ oh, uint8_t* __restrict__ ol)
{
    int idx = blockIdx.x * 256 + threadIdx.x;   // 3*512*64 = 98304
    int t = idx / 32768, r = idx - t * 32768;
    int m = r >> 6, g8 = r & 63;
    const float* W = (t == 0) ? Wa : ((t == 1) ? Wb : Wc);
    float v[8];
#pragma unroll
    for (int u = 0; u < 8; u++) v[u] = W[m * 512 + g8 * 8 + u];
    uint4 vh, vl; pack8(v, vh, vl);
    int mt = m >> 7, mr = m & 127, slab = g8 >> 2, c8 = g8 & 3;
    size_t off = ((size_t)(t * 4 + mt) * 16 + slab) * 10240 + mr * 80 + c8 * 16;
    *(uint4*)(oh + off) = vh;
    *(uint4*)(ol + off) = vl;
}

// ---- input feats [b][c][p] -> transposed [t][b][slab16][row p][40 halves] ----
__global__ __launch_bounds__(256) void convert_feat_kernel(
    const float* __restrict__ f1, const float* __restrict__ f2, const float* __restrict__ f3,
    uint8_t* __restrict__ oh, uint8_t* __restrict__ ol)
{
    __shared__ float s[32 * 201];
    const int b = blockIdx.x, t = blockIdx.y, tid = threadIdx.x;
    const float* F = ((t == 0) ? f1 : ((t == 1) ? f2 : f3)) + (size_t)b * 102400;
    uint8_t* obh = oh + ((size_t)t * 128 + b) * 286720;
    uint8_t* obl = ol + ((size_t)t * 128 + b) * 286720;
    for (int c = 0; c < 16; c++) {
        __syncthreads();
        for (int e = tid; e < 32 * 200; e += 256) {
            int kk = e / 200, n = e - kk * 200;
            s[kk * 201 + n] = F[(size_t)(c * 32 + kk) * 200 + n];
        }
        __syncthreads();
        for (int i = tid; i < 800; i += 256) {
            int p = i >> 2, g8 = i & 3;
            float v[8];
#pragma unroll
            for (int u = 0; u < 8; u++) v[u] = s[(g8 * 8 + u) * 201 + p];
            uint4 vh, vl; pack8(v, vh, vl);
            size_t off = (size_t)c * 17920 + p * 80 + g8 * 16;
            *(uint4*)(obh + off) = vh;
            *(uint4*)(obl + off) = vl;
        }
    }
}

// ---- hi/lo split bf16 GEMM via mma.sync: 256 thr / 8 warps (2Mx4N),
//      3-stage pipeline with copies issued AHEAD of compute. ------------------
// MODE0 conv1x1: C[m,p] = W·F + bias -> transposed bf16 hi/lo slab output
// MODE1 gram:    C[p1,p2] -> fp32 G   (Mvalid masks rows >= 200)
template <int MODE>
__global__ __launch_bounds__(256) void gemm_mma_kernel(
    const uint8_t* __restrict__ Ah, const uint8_t* __restrict__ Al,
    const uint8_t* __restrict__ Bh, const uint8_t* __restrict__ Bl,
    const float* __restrict__ b0, const float* __restrict__ b1, const float* __restrict__ b2,
    float* __restrict__ G, uint8_t* __restrict__ Oh, uint8_t* __restrict__ Ol)
{
    extern __shared__ __align__(128) uint8_t smem[];
    const int tid = threadIdx.x;
    const int mt = blockIdx.x, b = blockIdx.y, z = blockIdx.z;
    const uint32_t sb = smem_u32(smem);
    const int warp = tid >> 5, lane = tid & 31;
    const int warpM = warp & 1, warpN = warp >> 1;
    const int Mvalid = (MODE == 0) ? 128 : (200 - mt * 128);

    const uint32_t CTRL = sb + SM_CTRL;
    if (tid == 0) {
#pragma unroll
        for (int p = 0; p < 3; p++) MBAR_INIT(CTRL + p * 8, 1);   // FULL[p]
    }
    __syncthreads();

    const uint8_t *pAh, *pAl, *pBh, *pBl;
    size_t aStep, bStep;
    if (MODE == 0) {
        size_t ao = (size_t)(z * 4 + mt) * 163840;
        size_t bo = (size_t)(z * 128 + b) * 286720;
        pAh = Ah + ao; pAl = Al + ao; pBh = Bh + bo; pBl = Bl + bo;
        aStep = 10240; bStep = 17920;
    } else {
        int pa = (z == 2) ? 1 : 0, pb = (z == 0) ? 1 : 2;
        size_t ao = (size_t)(pa * 128 + b) * 327680 + (size_t)mt * 10240;
        size_t bo = (size_t)(pb * 128 + b) * 327680;
        pAh = Ah + ao; pAl = Al + ao; pBh = Bh + bo; pBl = Bl + bo;
        aStep = 20480; bStep = 20480;
    }

    // prologue: issue copies for stages 0..2
    if (tid == 0) {
#pragma unroll
        for (int s = 0; s < 3; s++) {
            const uint32_t st = sb + s * STAGE_B;
            MBAR_EXPECT(CTRL + s * 8, STAGE_B);
            BULK_G2S(st,         pAh + (size_t)s * aStep, 10240, CTRL + s * 8);
            BULK_G2S(st + 10240, pAl + (size_t)s * aStep, 10240, CTRL + s * 8);
            BULK_G2S(st + 20480, pBh + (size_t)s * bStep, 17920, CTRL + s * 8);
            BULK_G2S(st + 38400, pBl + (size_t)s * bStep, 17920, CTRL + s * 8);
        }
    }

    float c[4][7][4];
#pragma unroll
    for (int i = 0; i < 4; i++)
#pragma unroll
        for (int j = 0; j < 7; j++)
#pragma unroll
            for (int k = 0; k < 4; k++) c[i][j][k] = 0.f;

    int phF[3] = {0, 0, 0};
    int p = 0;
    for (int s = 0; s < 16; s++) {
        const uint32_t st = sb + p * STAGE_B;
        MBAR_WAIT(CTRL + p * 8, phF[p]); phF[p] ^= 1;

        const uint32_t aBase = st + (warpM * 64 + (lane & 15)) * 80 + (lane & 16);
        const uint32_t bBase = st + 20480 + (warpN * 56 + (lane & 7)) * 80 + (lane & 8) * 2;
#pragma unroll
        for (int ks = 0; ks < 2; ks++) {
            const uint32_t kb = ks * 32;
            uint32_t afh[4][4], afl[4][4];
#pragma unroll
            for (int mi = 0; mi < 4; mi++) {
                if (warpM * 64 + mi * 16 >= Mvalid) continue;
                ldsm4(afh[mi], aBase + mi * 1280 + kb);
                ldsm4(afl[mi], aBase + 10240 + mi * 1280 + kb);
            }
#pragma unroll
            for (int ni = 0; ni < 7; ni++) {
                uint32_t bfh[2], bfl[2];
                ldsm2(bfh, bBase + ni * 640 + kb);
                ldsm2(bfl, bBase + 17920 + ni * 640 + kb);
#pragma unroll
                for (int mi = 0; mi < 4; mi++) {
                    if (warpM * 64 + mi * 16 >= Mvalid) continue;
                    mma16816(c[mi][ni], afh[mi], bfh);
                    mma16816(c[mi][ni], afh[mi], bfl);
                    mma16816(c[mi][ni], afl[mi], bfh);
                }
            }
        }
        __syncthreads();                 // all warps done with buffer p
        if (tid == 0 && s + 3 < 16) {    // refill p with stage s+3 (runs behind compute)
            const int sn = s + 3;
            MBAR_EXPECT(CTRL + p * 8, STAGE_B);
            BULK_G2S(st,         pAh + (size_t)sn * aStep, 10240, CTRL + p * 8);
            BULK_G2S(st + 10240, pAl + (size_t)sn * aStep, 10240, CTRL + p * 8);
            BULK_G2S(st + 20480, pBh + (size_t)sn * bStep, 17920, CTRL + p * 8);
            BULK_G2S(st + 38400, pBl + (size_t)sn * bStep, 17920, CTRL + p * 8);
        }
        p = (p == 2) ? 0 : p + 1;
    }
    __syncthreads();

    if (MODE == 0) {
        const float* bias = (z == 0) ? b0 : ((z == 1) ? b1 : b2);
        __nv_bfloat16* sH = reinterpret_cast<__nv_bfloat16*>(smem);   // [p<200][m128]
        __nv_bfloat16* sL = sH + 25600;
#pragma unroll
        for (int mi = 0; mi < 4; mi++) {
            const int m0 = warpM * 64 + mi * 16 + (lane >> 2);
            const float bv0 = __ldg(bias + mt * 128 + m0);
            const float bv1 = __ldg(bias + mt * 128 + m0 + 8);
#pragma unroll
            for (int ni = 0; ni < 7; ni++) {
                const int p0 = warpN * 56 + ni * 8 + (lane & 3) * 2;
                if (p0 >= 200) continue;
                float v[4] = {c[mi][ni][0] + bv0, c[mi][ni][1] + bv0,
                              c[mi][ni][2] + bv1, c[mi][ni][3] + bv1};
#pragma unroll
                for (int q = 0; q < 4; q++) {
                    const int pp = p0 + (q & 1), mm = m0 + (q < 2 ? 0 : 8);
                    __nv_bfloat16 h = __float2bfloat16_rn(v[q]);
                    sH[pp * 128 + mm] = h;
                    sL[pp * 128 + mm] = __float2bfloat16_rn(v[q] - __bfloat162float(h));
                }
            }
        }
        __syncthreads();
        uint8_t* ohB = Oh + ((size_t)(z * 128 + b) * 16 + mt * 4) * 20480;
        uint8_t* olB = Ol + ((size_t)(z * 128 + b) * 16 + mt * 4) * 20480;
        for (int g = tid; g < 3200; g += 256) {
            int pp = g >> 4, o = g & 15, q = o >> 2, oo = o & 3;
            uint32_t so = (pp * 128 + q * 32 + oo * 8) * 2;
            size_t dof = (size_t)q * 20480 + pp * 80 + oo * 16;
            *(uint4*)(ohB + dof) = *(uint4*)((uint8_t*)sH + so);
            *(uint4*)(olB + dof) = *(uint4*)((uint8_t*)sL + so);
        }
    } else {
        float* Gb = G + ((size_t)z * 128 + b) * 40000;
#pragma unroll
        for (int mi = 0; mi < 4; mi++) {
            const int m0 = mt * 128 + warpM * 64 + mi * 16 + (lane >> 2);
#pragma unroll
            for (int ni = 0; ni < 7; ni++) {
                const int n0 = warpN * 56 + ni * 8 + (lane & 3) * 2;
                if (n0 >= 200) continue;
                if (m0 < 200)
                    *(float2*)(Gb + (size_t)m0 * 200 + n0) = make_float2(c[mi][ni][0], c[mi][ni][1]);
                if (m0 + 8 < 200)
                    *(float2*)(Gb + (size_t)(m0 + 8) * 200 + n0) = make_float2(c[mi][ni][2], c[mi][ni][3]);
            }
        }
    }
}

// ---- corr head: gather from Gram + leaky + conv3x3 + relu -------------------
__global__ __launch_bounds__(256)
void corr_head_kernel(const float* __restrict__ Gram, const float* __restrict__ Wcorr,
                      const float* __restrict__ bcorr, float* __restrict__ corrvec)
{
    extern __shared__ float sh[];
    float* sG = sh;
    float* sW = sh + 40000;
    const int b = blockIdx.x, tid = threadIdx.x;
    const int y = tid / 20, x = tid - y * 20;
    float acc0 = 0.f, acc1 = 0.f, acc2 = 0.f;

    for (int pair = 0; pair < 3; pair++) {
        __syncthreads();
        const float4* G4 = reinterpret_cast<const float4*>(Gram + ((size_t)pair * 128 + b) * 40000);
        float4* sG4 = reinterpret_cast<float4*>(sG);
        for (int i = tid; i < 10000; i += 256) sG4[i] = G4[i];
        for (int i = tid; i < 11907; i += 256) {
            int o = i / 3969, r = i - o * 3969;
            sW[i] = Wcorr[o * 11907 + pair * 3969 + r];
        }
        __syncthreads();
        if (tid < NPIX) {
            for (int ky = 0; ky < 3; ky++) {
                int sy = y + ky - 1;
                if ((unsigned)sy >= 10u) continue;
                for (int kx = 0; kx < 3; kx++) {
                    int sx = x + kx - 1;
                    if ((unsigned)sx >= 20u) continue;
                    const float* grow0 = sG + (sy * 20 + sx) * 200;
                    const int tap = ky * 3 + kx;
                    const int dyi0 = (21 - sy) >> 1, dxi0 = (21 - sx) >> 1;
                    const int p2y0 = sy + 2 * dyi0 - 20, p2x0 = sx + 2 * dxi0 - 20;
                    for (int iy = 0; iy < 5; iy++) {
                        const float* grow = grow0 + (p2y0 + 2 * iy) * 20 + p2x0;
                        const float* wrow = sW + ((dyi0 + iy) * 21 + dxi0) * 9 + tap;
#pragma unroll
                        for (int ix = 0; ix < 10; ix++) {
                            float g = grow[2 * ix] * (1.f / 512.f);
                            float v = g > 0.f ? g : 0.1f * g;
                            acc0 += v * wrow[ix * 9];
                            acc1 += v * wrow[3969 + ix * 9];
                            acc2 += v * wrow[7938 + ix * 9];
                        }
                    }
                }
            }
        }
    }
    if (tid < NPIX) {
        corrvec[b * 600 + tid]       = fmaxf(acc0 + bcorr[0], 0.f);
        corrvec[b * 600 + 200 + tid] = fmaxf(acc1 + bcorr[1], 0.f);
        corrvec[b * 600 + 400 + tid] = fmaxf(acc2 + bcorr[2], 0.f);
    }
}

// ---- cat head: conv3x3 over concat(f1,f2,f3) from hi/lo slab layout ---------
__global__ __launch_bounds__(256)
void cat_head_kernel(const uint8_t* __restrict__ Fh, const uint8_t* __restrict__ Fl,
                     const float* __restrict__ Wcat, const float* __restrict__ bcat,
                     float* __restrict__ catvec)
{
    extern __shared__ float sh[];
    float* sF = sh;             // [(t*200+p)*68 + c]
    float* sW = sh + 40800;
    const int b = blockIdx.x, tid = threadIdx.x;
    const int y = tid / 20, x = tid - y * 20;
    float acc0 = 0.f, acc1 = 0.f, acc2 = 0.f;

    for (int cc = 0; cc < 512; cc += 64) {
        __syncthreads();
        for (int g = tid; g < 4800; g += 256) {
            int t = g / 1600, r = g - t * 1600, p = r >> 3, g8 = r & 7;
            int slab = (cc >> 5) + (g8 >> 2);
            size_t base = (((size_t)t * 128 + b) * 16 + slab) * 20480 + p * 80 + (g8 & 3) * 16;
            uint4 vh = *(const uint4*)(Fh + base);
            uint4 vl = *(const uint4*)(Fl + base);
            float* d = &sF[(t * 200 + p) * 68 + g8 * 8];
            float2 a0 = bf2f(vh.x), c0 = bf2f(vl.x); d[0] = a0.x + c0.x; d[1] = a0.y + c0.y;
            float2 a1 = bf2f(vh.y), c1 = bf2f(vl.y); d[2] = a1.x + c1.x; d[3] = a1.y + c1.y;
            float2 a2 = bf2f(vh.z), c2 = bf2f(vl.z); d[4] = a2.x + c2.x; d[5] = a2.y + c2.y;
            float2 a3 = bf2f(vh.w), c3 = bf2f(vl.w); d[6] = a3.x + c3.x; d[7] = a3.y + c3.y;
        }
        for (int i = tid; i < 5184; i += 256) {
            int o = i / 1728, r = i - o * 1728, t = r / 576, r2 = r - t * 576;
            int tap = r2 >> 6, cch = r2 & 63;
            sW[i] = Wcat[(size_t)(o * 1536 + t * 512 + cc + cch) * 9 + tap];
        }
        __syncthreads();
        if (tid < NPIX) {
            for (int t = 0; t < 3; t++)
                for (int ky = 0; ky < 3; ky++) {
                    int sy = y + ky - 1;
                    if ((unsigned)sy >= 10u) continue;
                    for (int kx = 0; kx < 3; kx++) {
                        int sx = x + kx - 1;
                        if ((unsigned)sx >= 20u) continue;
                        const float4* v4 = reinterpret_cast<const float4*>(sF + (t * 200 + sy * 20 + sx) * 68);
                        int tap = ky * 3 + kx;
                        const float4* w0 = reinterpret_cast<const float4*>(sW + (t * 9 + tap) * 64);
                        const float4* w1 = reinterpret_cast<const float4*>(sW + 1728 + (t * 9 + tap) * 64);
                        const float4* w2 = reinterpret_cast<const float4*>(sW + 3456 + (t * 9 + tap) * 64);
#pragma unroll
                        for (int c4 = 0; c4 < 16; c4++) {
                            float4 v = v4[c4];
                            float4 a = w0[c4], bq = w1[c4], cq = w2[c4];
                            acc0 += v.x * a.x + v.y * a.y + v.z * a.z + v.w * a.w;
                            acc1 += v.x * bq.x + v.y * bq.y + v.z * bq.z + v.w * bq.w;
                            acc2 += v.x * cq.x + v.y * cq.y + v.z * cq.z + v.w * cq.w;
                        }
                    }
                }
        }
    }
    if (tid < NPIX) {
        catvec[b * 600 + tid]       = acc0 + bcat[0];
        catvec[b * 600 + 200 + tid] = acc1 + bcat[1];
        catvec[b * 600 + 400 + tid] = acc2 + bcat[2];
    }
}

// ---- MLP heads + final linear ------------------------------------------------
__global__ __launch_bounds__(256)
void mlp_kernel(const float* __restrict__ corrvec, const float* __restrict__ catvec,
                const float* __restrict__ cf_w1, const float* __restrict__ cf_b1,
                const float* __restrict__ cf_w2, const float* __restrict__ cf_b2,
                const float* __restrict__ ccf_w1, const float* __restrict__ ccf_b1,
                const float* __restrict__ ccf_w2, const float* __restrict__ ccf_b2,
                const float* __restrict__ Wout, const float* __restrict__ bout,
                float* __restrict__ out)
{
    __shared__ float sx[600];
    __shared__ float h1[256];
    __shared__ float h2[2][128];
    const int b = blockIdx.x, tid = threadIdx.x;

    for (int path = 0; path < 2; path++) {
        const float* xv = (path == 0 ? corrvec : catvec) + b * 600;
        const float* w1 = path == 0 ? cf_w1 : ccf_w1;
        const float* b1 = path == 0 ? cf_b1 : ccf_b1;
        const float* w2 = path == 0 ? cf_w2 : ccf_w2;
        const float* b2 = path == 0 ? cf_b2 : ccf_b2;
        __syncthreads();
        for (int i = tid; i < 600; i += 256) sx[i] = xv[i];
        __syncthreads();
        {
            float s = b1[tid];
            const float4* wr = reinterpret_cast<const float4*>(w1 + (size_t)tid * 600);
#pragma unroll 4
            for (int k = 0; k < 150; k++) {
                float4 w = wr[k];
                s += w.x * sx[4*k] + w.y * sx[4*k+1] + w.z * sx[4*k+2] + w.w * sx[4*k+3];
            }
            h1[tid] = fmaxf(s, 0.f);
        }
        __syncthreads();
        if (tid < 128) {
            float s = b2[tid];
            const float4* wr = reinterpret_cast<const float4*>(w2 + (size_t)tid * 256);
#pragma unroll 4
            for (int k = 0; k < 64; k++) {
                float4 w = wr[k];
                s += w.x * h1[4*k] + w.y * h1[4*k+1] + w.z * h1[4*k+2] + w.w * h1[4*k+3];
            }
            h2[path][tid] = fmaxf(s, 0.f);
        }
    }
    __syncthreads();
    if (tid < 2) {
        float s = bout[tid];
        const float* wr = Wout + tid * 256;
        for (int i = 0; i < 128; i++)
            s += h2[0][i] * wr[i] + h2[1][i] * wr[128 + i];
        out[b * 2 + tid] = s;
    }
}

// ---- launch -------------------------------------------------------------------
extern "C" void kernel_launch(void* const* d_in, const int* in_sizes, int n_in,
                              void* d_out, int out_size)
{
    (void)in_sizes; (void)n_in; (void)out_size;
    const float* feat1 = (const float*)d_in[0];
    const float* feat2 = (const float*)d_in[1];
    const float* feat3 = (const float*)d_in[2];
    const float* Wa = (const float*)d_in[3];   const float* ba = (const float*)d_in[4];
    const float* Wb = (const float*)d_in[5];   const float* bb = (const float*)d_in[6];
    const float* Wc = (const float*)d_in[7];   const float* bc = (const float*)d_in[8];
    const float* Wcorr = (const float*)d_in[9];  const float* bcorr = (const float*)d_in[10];
    const float* Wcat = (const float*)d_in[11];  const float* bcat = (const float*)d_in[12];
    const float* cf_w1 = (const float*)d_in[13]; const float* cf_b1 = (const float*)d_in[14];
    const float* cf_w2 = (const float*)d_in[15]; const float* cf_b2 = (const float*)d_in[16];
    const float* ccf_w1 = (const float*)d_in[17]; const float* ccf_b1 = (const float*)d_in[18];
    const float* ccf_w2 = (const float*)d_in[19]; const float* ccf_b2 = (const float*)d_in[20];
    const float* Wout = (const float*)d_in[21];  const float* bout = (const float*)d_in[22];

    uint8_t *wh, *wl, *fih, *fil, *foh, *fol;
    float *G, *cv, *tv;
    cudaGetSymbolAddress((void**)&wh,  g_wh);
    cudaGetSymbolAddress((void**)&wl,  g_wl);
    cudaGetSymbolAddress((void**)&fih, g_finh);
    cudaGetSymbolAddress((void**)&fil, g_finl);
    cudaGetSymbolAddress((void**)&foh, g_fouth);
    cudaGetSymbolAddress((void**)&fol, g_foutl);
    cudaGetSymbolAddress((void**)&G,   g_gram);
    cudaGetSymbolAddress((void**)&cv,  g_corrvec);
    cudaGetSymbolAddress((void**)&tv,  g_catvec);

    cudaFuncSetAttribute(gemm_mma_kernel<0>, cudaFuncAttributeMaxDynamicSharedMemorySize, GEMM_SMEM);
    cudaFuncSetAttribute(gemm_mma_kernel<1>, cudaFuncAttributeMaxDynamicSharedMemorySize, GEMM_SMEM);

    convert_w_kernel<<<384, 256>>>(Wa, Wb, Wc, wh, wl);
    convert_feat_kernel<<<dim3(128, 3), 256>>>(feat1, feat2, feat3, fih, fil);

    // conv1x1 per (mtile4, batch, tensor)
    gemm_mma_kernel<0><<<dim3(4, 128, 3), 256, GEMM_SMEM>>>(
        wh, wl, fih, fil, ba, bb, bc, nullptr, foh, fol);

    // Gram per (mtile2, batch, pair)
    gemm_mma_kernel<1><<<dim3(2, 128, 3), 256, GEMM_SMEM>>>(
        foh, fol, foh, fol, nullptr, nullptr, nullptr, G, nullptr, nullptr);

    const int CORR_SMEM = (40000 + 11907) * 4;
    cudaFuncSetAttribute(corr_head_kernel, cudaFuncAttributeMaxDynamicSharedMemorySize, CORR_SMEM);
    corr_head_kernel<<<128, 256, CORR_SMEM>>>(G, Wcorr, bcorr, cv);

    const int CAT_SMEM = (40800 + 5184) * 4;
    cudaFuncSetAttribute(cat_head_kernel, cudaFuncAttributeMaxDynamicSharedMemorySize, CAT_SMEM);
    cat_head_kernel<<<128, 256, CAT_SMEM>>>(foh, fol, Wcat, bcat, tv);

    mlp_kernel<<<128, 256>>>(cv, tv, cf_w1, cf_b1, cf_w2, cf_b2,
                             ccf_w1, ccf_b1, ccf_w2, ccf_b2, Wout, bout, (float*)d_out);
}

// round 10
// speedup vs baseline: 1.2638x; 1.0319x over previous
#include <cuda_runtime.h>
#include <cuda_bf16.h>
#include <cstdint>
#include <cstddef>

#define NPIX 200

// ---- gmem scratch (static; zero-initialized at load — pad rows rely on it) --
__device__ __align__(16) uint8_t g_wh[3u*4*16*10240];          //  2 MB
__device__ __align__(16) uint8_t g_wl[3u*4*16*10240];
__device__ __align__(16) uint8_t g_finh[3u*128*16*17920];      // 110 MB
__device__ __align__(16) uint8_t g_finl[3u*128*16*17920];
__device__ __align__(16) uint8_t g_fouth[3u*128*16*20480];     // 126 MB
__device__ __align__(16) uint8_t g_foutl[3u*128*16*20480];
__device__ float g_gram[3u*128*200*200];                       //  61 MB
__device__ float g_corrvec[128*600];
__device__ float g_catvec[128*600];

// smem: 2 stages of 38400: AH(10240) AL(10240) BH(8960) BL(8960); ctrl after.
#define STAGE_B   38400
#define SM_CTRL   76800
#define GEMM_SMEM (SM_CTRL + 32)

__device__ __forceinline__ uint32_t smem_u32(const void* p) {
    uint32_t r;
    asm("{ .reg .u64 t; cvta.to.shared.u64 t, %1; cvt.u32.u64 %0, t; }" : "=r"(r) : "l"(p));
    return r;
}
#define MBAR_INIT(a, c) asm volatile("mbarrier.init.shared.b64 [%0], %1;" :: "r"(a), "r"(c) : "memory")
#define MBAR_EXPECT(a, n) asm volatile("mbarrier.arrive.expect_tx.shared.b64 _, [%0], %1;" :: "r"(a), "r"(n) : "memory")
#define MBAR_WAIT(a, ph) \
    asm volatile("{\n\t.reg .pred P;\n\tW_%=:\n\t" \
                 "mbarrier.try_wait.parity.acquire.cta.shared::cta.b64 P, [%0], %1, 0x989680;\n\t" \
                 "@!P bra W_%=;\n\t}" :: "r"(a), "r"(ph) : "memory")
#define BULK_G2S(dst, src, bytes, mbar) \
    asm volatile("cp.async.bulk.shared::cluster.global.mbarrier::complete_tx::bytes [%0], [%1], %2, [%3];" \
                 :: "r"(dst), "l"(src), "r"(bytes), "r"(mbar) : "memory")

__device__ __forceinline__ void ldsm4(uint32_t* r, uint32_t a) {
    asm volatile("ldmatrix.sync.aligned.m8n8.x4.shared.b16 {%0,%1,%2,%3}, [%4];"
        : "=r"(r[0]), "=r"(r[1]), "=r"(r[2]), "=r"(r[3]) : "r"(a));
}
__device__ __forceinline__ void ldsm2(uint32_t* r, uint32_t a) {
    asm volatile("ldmatrix.sync.aligned.m8n8.x2.shared.b16 {%0,%1}, [%2];"
        : "=r"(r[0]), "=r"(r[1]) : "r"(a));
}
__device__ __forceinline__ void mma16816(float* c, const uint32_t* a, const uint32_t* b) {
    asm volatile("mma.sync.aligned.m16n8k16.row.col.f32.bf16.bf16.f32 "
        "{%0,%1,%2,%3}, {%4,%5,%6,%7}, {%8,%9}, {%0,%1,%2,%3};"
        : "+f"(c[0]), "+f"(c[1]), "+f"(c[2]), "+f"(c[3])
        : "r"(a[0]), "r"(a[1]), "r"(a[2]), "r"(a[3]), "r"(b[0]), "r"(b[1]));
}
__device__ __forceinline__ void pack8(const float* v, uint4& h, uint4& l) {
    __align__(16) __nv_bfloat16 hb[8], lb[8];
#pragma unroll
    for (int u = 0; u < 8; u++) {
        hb[u] = __float2bfloat16_rn(v[u]);
        lb[u] = __float2bfloat16_rn(v[u] - __bfloat162float(hb[u]));
    }
    h = *reinterpret_cast<uint4*>(hb);
    l = *reinterpret_cast<uint4*>(lb);
}
__device__ __forceinline__ float2 bf2f(uint32_t u) {
    __nv_bfloat162 h = *reinterpret_cast<__nv_bfloat162*>(&u);
    return __bfloat1622float2(h);
}

// ---- weights W[m][k] fp32 -> hi/lo bf16, [t][mt][slab16][row128][40 halves] --
__global__ __launch_bounds__(256) void convert_w_kernel(
    const float* __restrict__ Wa, const float* __restrict__ Wb, const float* __restrict__ Wc,
    uint8_t* __restrict__ oh, uint8_t* __restrict__ ol)
{
    int idx = blockIdx.x * 256 + threadIdx.x;   // 3*512*64 = 98304
    int t = idx / 32768, r = idx - t * 32768;
    int m = r >> 6, g8 = r & 63;
    const float* W = (t == 0) ? Wa : ((t == 1) ? Wb : Wc);
    float v[8];
#pragma unroll
    for (int u = 0; u < 8; u++) v[u] = W[m * 512 + g8 * 8 + u];
    uint4 vh, vl; pack8(v, vh, vl);
    int mt = m >> 7, mr = m & 127, slab = g8 >> 2, c8 = g8 & 3;
    size_t off = ((size_t)(t * 4 + mt) * 16 + slab) * 10240 + mr * 80 + c8 * 16;
    *(uint4*)(oh + off) = vh;
    *(uint4*)(ol + off) = vl;
}

// ---- input feats [b][c][p] -> transposed [t][b][slab16][row p][40 halves] ----
__global__ __launch_bounds__(256) void convert_feat_kernel(
    const float* __restrict__ f1, const float* __restrict__ f2, const float* __restrict__ f3,
    uint8_t* __restrict__ oh, uint8_t* __restrict__ ol)
{
    __shared__ float s[32 * 201];
    const int b = blockIdx.x, t = blockIdx.y, tid = threadIdx.x;
    const float* F = ((t == 0) ? f1 : ((t == 1) ? f2 : f3)) + (size_t)b * 102400;
    uint8_t* obh = oh + ((size_t)t * 128 + b) * 286720;
    uint8_t* obl = ol + ((size_t)t * 128 + b) * 286720;
    for (int c = 0; c < 16; c++) {
        __syncthreads();
        for (int e = tid; e < 32 * 200; e += 256) {
            int kk = e / 200, n = e - kk * 200;
            s[kk * 201 + n] = F[(size_t)(c * 32 + kk) * 200 + n];
        }
        __syncthreads();
        for (int i = tid; i < 800; i += 256) {
            int p = i >> 2, g8 = i & 3;
            float v[8];
#pragma unroll
            for (int u = 0; u < 8; u++) v[u] = s[(g8 * 8 + u) * 201 + p];
            uint4 vh, vl; pack8(v, vh, vl);
            size_t off = (size_t)c * 17920 + p * 80 + g8 * 16;
            *(uint4*)(obh + off) = vh;
            *(uint4*)(obl + off) = vl;
        }
    }
}

// ---- hi/lo split bf16 GEMM via mma.sync: 256 thr / 8 warps (4Mx2N),
//      N split in two tiles per CTA (112/88) so 2 CTAs fit per SM. ------------
// MODE0 conv1x1: C[m,p] = W·F + bias -> transposed bf16 hi/lo slab output
// MODE1 gram:    C[p1,p2] -> fp32 G
template <int MODE>
__global__ __launch_bounds__(256, 2) void gemm_mma_kernel(
    const uint8_t* __restrict__ Ah, const uint8_t* __restrict__ Al,
    const uint8_t* __restrict__ Bh, const uint8_t* __restrict__ Bl,
    const float* __restrict__ b0, const float* __restrict__ b1, const float* __restrict__ b2,
    float* __restrict__ G, uint8_t* __restrict__ Oh, uint8_t* __restrict__ Ol)
{
    extern __shared__ __align__(128) uint8_t smem[];
    const int tid = threadIdx.x;
    const int mt = blockIdx.x >> 1, nt = blockIdx.x & 1;
    const int b = blockIdx.y, z = blockIdx.z;
    const uint32_t sb = smem_u32(smem);
    const int warp = tid >> 5, lane = tid & 31;
    const int warpM = warp & 3, warpN = warp >> 2;
    const int Mvalid = (MODE == 0) ? 128 : (200 - mt * 128);
    const int nvalid = nt ? 88 : 112;
    const uint32_t TXB = 20480 + 160u * nvalid;

    const uint32_t CTRL = sb + SM_CTRL;
    if (tid == 0) { MBAR_INIT(CTRL, 1); MBAR_INIT(CTRL + 8, 1); }
    __syncthreads();

    const uint8_t *pAh, *pAl, *pBh, *pBl;
    size_t aStep, bStep;
    if (MODE == 0) {
        size_t ao = (size_t)(z * 4 + mt) * 163840;
        size_t bo = (size_t)(z * 128 + b) * 286720 + (size_t)nt * 112 * 80;
        pAh = Ah + ao; pAl = Al + ao; pBh = Bh + bo; pBl = Bl + bo;
        aStep = 10240; bStep = 17920;
    } else {
        int pa = (z == 2) ? 1 : 0, pb = (z == 0) ? 1 : 2;
        size_t ao = (size_t)(pa * 128 + b) * 327680 + (size_t)mt * 10240;
        size_t bo = (size_t)(pb * 128 + b) * 327680 + (size_t)nt * 112 * 80;
        pAh = Ah + ao; pAl = Al + ao; pBh = Bh + bo; pBl = Bl + bo;
        aStep = 20480; bStep = 20480;
    }
    const uint32_t bBytes = nvalid * 80;

    // prologue: stages 0,1
    if (tid == 0) {
#pragma unroll
        for (int s = 0; s < 2; s++) {
            const uint32_t st = sb + s * STAGE_B;
            MBAR_EXPECT(CTRL + s * 8, TXB);
            BULK_G2S(st,         pAh + (size_t)s * aStep, 10240, CTRL + s * 8);
            BULK_G2S(st + 10240, pAl + (size_t)s * aStep, 10240, CTRL + s * 8);
            BULK_G2S(st + 20480, pBh + (size_t)s * bStep, bBytes, CTRL + s * 8);
            BULK_G2S(st + 29440, pBl + (size_t)s * bStep, bBytes, CTRL + s * 8);
        }
    }

    float c[2][7][4];
#pragma unroll
    for (int i = 0; i < 2; i++)
#pragma unroll
        for (int j = 0; j < 7; j++)
#pragma unroll
            for (int k = 0; k < 4; k++) c[i][j][k] = 0.f;

    int phF[2] = {0, 0};
    for (int s = 0; s < 16; s++) {
        const int p = s & 1;
        const uint32_t st = sb + p * STAGE_B;
        MBAR_WAIT(CTRL + p * 8, phF[p]); phF[p] ^= 1;

        const uint32_t aBase = st + (warpM * 32 + (lane & 15)) * 80 + (lane & 16);
        const uint32_t bBase = st + 20480 + (warpN * 56 + (lane & 7)) * 80 + (lane & 8) * 2;
#pragma unroll
        for (int ks = 0; ks < 2; ks++) {
            const uint32_t kb = ks * 32;
            uint32_t afh[2][4], afl[2][4];
#pragma unroll
            for (int mi = 0; mi < 2; mi++) {
                if (warpM * 32 + mi * 16 >= Mvalid) continue;
                ldsm4(afh[mi], aBase + mi * 1280 + kb);
                ldsm4(afl[mi], aBase + 10240 + mi * 1280 + kb);
            }
#pragma unroll
            for (int ni = 0; ni < 7; ni++) {
                if (warpN * 56 + ni * 8 >= nvalid) continue;
                uint32_t bfh[2], bfl[2];
                ldsm2(bfh, bBase + ni * 640 + kb);
                ldsm2(bfl, bBase + 8960 + ni * 640 + kb);
#pragma unroll
                for (int mi = 0; mi < 2; mi++) {
                    if (warpM * 32 + mi * 16 >= Mvalid) continue;
                    mma16816(c[mi][ni], afh[mi], bfh);
                    mma16816(c[mi][ni], afh[mi], bfl);
                    mma16816(c[mi][ni], afl[mi], bfh);
                }
            }
        }
        __syncthreads();                 // all warps done with buffer p
        if (tid == 0 && s + 2 < 16) {    // refill p with stage s+2
            const int sn = s + 2;
            MBAR_EXPECT(CTRL + p * 8, TXB);
            BULK_G2S(st,         pAh + (size_t)sn * aStep, 10240, CTRL + p * 8);
            BULK_G2S(st + 10240, pAl + (size_t)sn * aStep, 10240, CTRL + p * 8);
            BULK_G2S(st + 20480, pBh + (size_t)sn * bStep, bBytes, CTRL + p * 8);
            BULK_G2S(st + 29440, pBl + (size_t)sn * bStep, bBytes, CTRL + p * 8);
        }
    }
    __syncthreads();

    if (MODE == 0) {
        const float* bias = (z == 0) ? b0 : ((z == 1) ? b1 : b2);
        __nv_bfloat16* sH = reinterpret_cast<__nv_bfloat16*>(smem);   // [p<112][m128]
        __nv_bfloat16* sL = sH + 14336;
#pragma unroll
        for (int mi = 0; mi < 2; mi++) {
            const int m0 = warpM * 32 + mi * 16 + (lane >> 2);
            const float bv0 = __ldg(bias + mt * 128 + m0);
            const float bv1 = __ldg(bias + mt * 128 + m0 + 8);
#pragma unroll
            for (int ni = 0; ni < 7; ni++) {
                const int p0 = warpN * 56 + ni * 8 + (lane & 3) * 2;
                if (p0 >= nvalid) continue;
                float v[4] = {c[mi][ni][0] + bv0, c[mi][ni][1] + bv0,
                              c[mi][ni][2] + bv1, c[mi][ni][3] + bv1};
#pragma unroll
                for (int q = 0; q < 4; q++) {
                    const int pp = p0 + (q & 1), mm = m0 + (q < 2 ? 0 : 8);
                    __nv_bfloat16 h = __float2bfloat16_rn(v[q]);
                    sH[pp * 128 + mm] = h;
                    sL[pp * 128 + mm] = __float2bfloat16_rn(v[q] - __bfloat162float(h));
                }
            }
        }
        __syncthreads();
        uint8_t* ohB = Oh + ((size_t)(z * 128 + b) * 16 + mt * 4) * 20480;
        uint8_t* olB = Ol + ((size_t)(z * 128 + b) * 16 + mt * 4) * 20480;
        const int tot = nvalid * 16;
        for (int g = tid; g < tot; g += 256) {
            int pp = g >> 4, o = g & 15, q = o >> 2, oo = o & 3;
            uint32_t so = (pp * 128 + q * 32 + oo * 8) * 2;
            size_t dof = (size_t)q * 20480 + (size_t)(nt * 112 + pp) * 80 + oo * 16;
            *(uint4*)(ohB + dof) = *(uint4*)((uint8_t*)sH + so);
            *(uint4*)(olB + dof) = *(uint4*)((uint8_t*)sL + so);
        }
    } else {
        float* Gb = G + ((size_t)z * 128 + b) * 40000;
#pragma unroll
        for (int mi = 0; mi < 2; mi++) {
            const int m0 = mt * 128 + warpM * 32 + mi * 16 + (lane >> 2);
#pragma unroll
            for (int ni = 0; ni < 7; ni++) {
                const int nl = warpN * 56 + ni * 8 + (lane & 3) * 2;
                if (nl >= nvalid) continue;
                const int n0 = nt * 112 + nl;
                if (m0 < 200)
                    *(float2*)(Gb + (size_t)m0 * 200 + n0) = make_float2(c[mi][ni][0], c[mi][ni][1]);
                if (m0 + 8 < 200)
                    *(float2*)(Gb + (size_t)(m0 + 8) * 200 + n0) = make_float2(c[mi][ni][2], c[mi][ni][3]);
            }
        }
    }
}

// ---- fused heads: blockIdx.y==0 -> corr path, ==1 -> cat path ---------------
__global__ __launch_bounds__(256)
void heads_kernel(const float* __restrict__ Gram, const float* __restrict__ Wcorr,
                  const float* __restrict__ bcorr, float* __restrict__ corrvec,
                  const uint8_t* __restrict__ Fh, const uint8_t* __restrict__ Fl,
                  const float* __restrict__ Wcat, const float* __restrict__ bcat,
                  float* __restrict__ catvec)
{
    extern __shared__ float sh[];
    const int b = blockIdx.x, tid = threadIdx.x;
    const int y = tid / 20, x = tid - y * 20;
    float acc0 = 0.f, acc1 = 0.f, acc2 = 0.f;

    if (blockIdx.y == 0) {
        float* sG = sh;
        float* sW = sh + 40000;
        for (int pair = 0; pair < 3; pair++) {
            __syncthreads();
            const float4* G4 = reinterpret_cast<const float4*>(Gram + ((size_t)pair * 128 + b) * 40000);
            float4* sG4 = reinterpret_cast<float4*>(sG);
            for (int i = tid; i < 10000; i += 256) sG4[i] = G4[i];
            for (int i = tid; i < 11907; i += 256) {
                int o = i / 3969, r = i - o * 3969;
                sW[i] = Wcorr[o * 11907 + pair * 3969 + r];
            }
            __syncthreads();
            if (tid < NPIX) {
                for (int ky = 0; ky < 3; ky++) {
                    int sy = y + ky - 1;
                    if ((unsigned)sy >= 10u) continue;
                    for (int kx = 0; kx < 3; kx++) {
                        int sx = x + kx - 1;
                        if ((unsigned)sx >= 20u) continue;
                        const float* grow0 = sG + (sy * 20 + sx) * 200;
                        const int tap = ky * 3 + kx;
                        const int dyi0 = (21 - sy) >> 1, dxi0 = (21 - sx) >> 1;
                        const int p2y0 = sy + 2 * dyi0 - 20, p2x0 = sx + 2 * dxi0 - 20;
                        for (int iy = 0; iy < 5; iy++) {
                            const float* grow = grow0 + (p2y0 + 2 * iy) * 20 + p2x0;
                            const float* wrow = sW + ((dyi0 + iy) * 21 + dxi0) * 9 + tap;
#pragma unroll
                            for (int ix = 0; ix < 10; ix++) {
                                float g = grow[2 * ix] * (1.f / 512.f);
                                float v = g > 0.f ? g : 0.1f * g;
                                acc0 += v * wrow[ix * 9];
                                acc1 += v * wrow[3969 + ix * 9];
                                acc2 += v * wrow[7938 + ix * 9];
                            }
                        }
                    }
                }
            }
        }
        if (tid < NPIX) {
            corrvec[b * 600 + tid]       = fmaxf(acc0 + bcorr[0], 0.f);
            corrvec[b * 600 + 200 + tid] = fmaxf(acc1 + bcorr[1], 0.f);
            corrvec[b * 600 + 400 + tid] = fmaxf(acc2 + bcorr[2], 0.f);
        }
    } else {
        float* sF = sh;             // [(t*200+p)*68 + c]
        float* sW = sh + 40800;
        for (int cc = 0; cc < 512; cc += 64) {
            __syncthreads();
            for (int g = tid; g < 4800; g += 256) {
                int t = g / 1600, r = g - t * 1600, p = r >> 3, g8 = r & 7;
                int slab = (cc >> 5) + (g8 >> 2);
                size_t base = (((size_t)t * 128 + b) * 16 + slab) * 20480 + p * 80 + (g8 & 3) * 16;
                uint4 vh = *(const uint4*)(Fh + base);
                uint4 vl = *(const uint4*)(Fl + base);
                float* d = &sF[(t * 200 + p) * 68 + g8 * 8];
                float2 a0 = bf2f(vh.x), c0 = bf2f(vl.x); d[0] = a0.x + c0.x; d[1] = a0.y + c0.y;
                float2 a1 = bf2f(vh.y), c1 = bf2f(vl.y); d[2] = a1.x + c1.x; d[3] = a1.y + c1.y;
                float2 a2 = bf2f(vh.z), c2 = bf2f(vl.z); d[4] = a2.x + c2.x; d[5] = a2.y + c2.y;
                float2 a3 = bf2f(vh.w), c3 = bf2f(vl.w); d[6] = a3.x + c3.x; d[7] = a3.y + c3.y;
            }
            for (int i = tid; i < 5184; i += 256) {
                int o = i / 1728, r = i - o * 1728, t = r / 576, r2 = r - t * 576;
                int tap = r2 >> 6, cch = r2 & 63;
                sW[i] = Wcat[(size_t)(o * 1536 + t * 512 + cc + cch) * 9 + tap];
            }
            __syncthreads();
            if (tid < NPIX) {
                for (int t = 0; t < 3; t++)
                    for (int ky = 0; ky < 3; ky++) {
                        int sy = y + ky - 1;
                        if ((unsigned)sy >= 10u) continue;
                        for (int kx = 0; kx < 3; kx++) {
                            int sx = x + kx - 1;
                            if ((unsigned)sx >= 20u) continue;
                            const float4* v4 = reinterpret_cast<const float4*>(sF + (t * 200 + sy * 20 + sx) * 68);
                            int tap = ky * 3 + kx;
                            const float4* w0 = reinterpret_cast<const float4*>(sW + (t * 9 + tap) * 64);
                            const float4* w1 = reinterpret_cast<const float4*>(sW + 1728 + (t * 9 + tap) * 64);
                            const float4* w2 = reinterpret_cast<const float4*>(sW + 3456 + (t * 9 + tap) * 64);
#pragma unroll
                            for (int c4 = 0; c4 < 16; c4++) {
                                float4 v = v4[c4];
                                float4 a = w0[c4], bq = w1[c4], cq = w2[c4];
                                acc0 += v.x * a.x + v.y * a.y + v.z * a.z + v.w * a.w;
                                acc1 += v.x * bq.x + v.y * bq.y + v.z * bq.z + v.w * bq.w;
                                acc2 += v.x * cq.x + v.y * cq.y + v.z * cq.z + v.w * cq.w;
                            }
                        }
                    }
            }
        }
        if (tid < NPIX) {
            catvec[b * 600 + tid]       = acc0 + bcat[0];
            catvec[b * 600 + 200 + tid] = acc1 + bcat[1];
            catvec[b * 600 + 400 + tid] = acc2 + bcat[2];
        }
    }
}

// ---- MLP heads + final linear ------------------------------------------------
__global__ __launch_bounds__(256)
void mlp_kernel(const float* __restrict__ corrvec, const float* __restrict__ catvec,
                const float* __restrict__ cf_w1, const float* __restrict__ cf_b1,
                const float* __restrict__ cf_w2, const float* __restrict__ cf_b2,
                const float* __restrict__ ccf_w1, const float* __restrict__ ccf_b1,
                const float* __restrict__ ccf_w2, const float* __restrict__ ccf_b2,
                const float* __restrict__ Wout, const float* __restrict__ bout,
                float* __restrict__ out)
{
    __shared__ float sx[600];
    __shared__ float h1[256];
    __shared__ float h2[2][128];
    const int b = blockIdx.x, tid = threadIdx.x;

    for (int path = 0; path < 2; path++) {
        const float* xv = (path == 0 ? corrvec : catvec) + b * 600;
        const float* w1 = path == 0 ? cf_w1 : ccf_w1;
        const float* b1 = path == 0 ? cf_b1 : ccf_b1;
        const float* w2 = path == 0 ? cf_w2 : ccf_w2;
        const float* b2 = path == 0 ? cf_b2 : ccf_b2;
        __syncthreads();
        for (int i = tid; i < 600; i += 256) sx[i] = xv[i];
        __syncthreads();
        {
            float s = b1[tid];
            const float4* wr = reinterpret_cast<const float4*>(w1 + (size_t)tid * 600);
#pragma unroll 4
            for (int k = 0; k < 150; k++) {
                float4 w = wr[k];
                s += w.x * sx[4*k] + w.y * sx[4*k+1] + w.z * sx[4*k+2] + w.w * sx[4*k+3];
            }
            h1[tid] = fmaxf(s, 0.f);
        }
        __syncthreads();
        if (tid < 128) {
            float s = b2[tid];
            const float4* wr = reinterpret_cast<const float4*>(w2 + (size_t)tid * 256);
#pragma unroll 4
            for (int k = 0; k < 64; k++) {
                float4 w = wr[k];
                s += w.x * h1[4*k] + w.y * h1[4*k+1] + w.z * h1[4*k+2] + w.w * h1[4*k+3];
            }
            h2[path][tid] = fmaxf(s, 0.f);
        }
    }
    __syncthreads();
    if (tid < 2) {
        float s = bout[tid];
        const float* wr = Wout + tid * 256;
        for (int i = 0; i < 128; i++)
            s += h2[0][i] * wr[i] + h2[1][i] * wr[128 + i];
        out[b * 2 + tid] = s;
    }
}

// ---- launch -------------------------------------------------------------------
extern "C" void kernel_launch(void* const* d_in, const int* in_sizes, int n_in,
                              void* d_out, int out_size)
{
    (void)in_sizes; (void)n_in; (void)out_size;
    const float* feat1 = (const float*)d_in[0];
    const float* feat2 = (const float*)d_in[1];
    const float* feat3 = (const float*)d_in[2];
    const float* Wa = (const float*)d_in[3];   const float* ba = (const float*)d_in[4];
    const float* Wb = (const float*)d_in[5];   const float* bb = (const float*)d_in[6];
    const float* Wc = (const float*)d_in[7];   const float* bc = (const float*)d_in[8];
    const float* Wcorr = (const float*)d_in[9];  const float* bcorr = (const float*)d_in[10];
    const float* Wcat = (const float*)d_in[11];  const float* bcat = (const float*)d_in[12];
    const float* cf_w1 = (const float*)d_in[13]; const float* cf_b1 = (const float*)d_in[14];
    const float* cf_w2 = (const float*)d_in[15]; const float* cf_b2 = (const float*)d_in[16];
    const float* ccf_w1 = (const float*)d_in[17]; const float* ccf_b1 = (const float*)d_in[18];
    const float* ccf_w2 = (const float*)d_in[19]; const float* ccf_b2 = (const float*)d_in[20];
    const float* Wout = (const float*)d_in[21];  const float* bout = (const float*)d_in[22];

    uint8_t *wh, *wl, *fih, *fil, *foh, *fol;
    float *G, *cv, *tv;
    cudaGetSymbolAddress((void**)&wh,  g_wh);
    cudaGetSymbolAddress((void**)&wl,  g_wl);
    cudaGetSymbolAddress((void**)&fih, g_finh);
    cudaGetSymbolAddress((void**)&fil, g_finl);
    cudaGetSymbolAddress((void**)&foh, g_fouth);
    cudaGetSymbolAddress((void**)&fol, g_foutl);
    cudaGetSymbolAddress((void**)&G,   g_gram);
    cudaGetSymbolAddress((void**)&cv,  g_corrvec);
    cudaGetSymbolAddress((void**)&tv,  g_catvec);

    cudaFuncSetAttribute(gemm_mma_kernel<0>, cudaFuncAttributeMaxDynamicSharedMemorySize, GEMM_SMEM);
    cudaFuncSetAttribute(gemm_mma_kernel<1>, cudaFuncAttributeMaxDynamicSharedMemorySize, GEMM_SMEM);

    convert_w_kernel<<<384, 256>>>(Wa, Wb, Wc, wh, wl);
    convert_feat_kernel<<<dim3(128, 3), 256>>>(feat1, feat2, feat3, fih, fil);

    // conv1x1 per (mtile4 x ntile2, batch, tensor)
    gemm_mma_kernel<0><<<dim3(8, 128, 3), 256, GEMM_SMEM>>>(
        wh, wl, fih, fil, ba, bb, bc, nullptr, foh, fol);

    // Gram per (mtile2 x ntile2, batch, pair)
    gemm_mma_kernel<1><<<dim3(4, 128, 3), 256, GEMM_SMEM>>>(
        foh, fol, foh, fol, nullptr, nullptr, nullptr, G, nullptr, nullptr);

    // fused corr + cat heads (overlapped)
    const int HEADS_SMEM = (40000 + 11907) * 4;   // max(corr, cat) = 207628
    cudaFuncSetAttribute(heads_kernel, cudaFuncAttributeMaxDynamicSharedMemorySize, HEADS_SMEM);
    heads_kernel<<<dim3(128, 2), 256, HEADS_SMEM>>>(G, Wcorr, bcorr, cv,
                                                    foh, fol, Wcat, bcat, tv);

    mlp_kernel<<<128, 256>>>(cv, tv, cf_w1, cf_b1, cf_w2, cf_b2,
                             ccf_w1, ccf_b1, ccf_w2, ccf_b2, Wout, bout, (float*)d_out);
}

// round 11
// speedup vs baseline: 1.4948x; 1.1827x over previous
#include <cuda_runtime.h>
#include <cuda_bf16.h>
#include <cstdint>
#include <cstddef>

#define NPIX 200

// ---- gmem scratch (static; zero-initialized at load — pad rows rely on it) --
__device__ __align__(16) uint8_t g_wh[3u*4*16*10240];          //  2 MB
__device__ __align__(16) uint8_t g_wl[3u*4*16*10240];
__device__ __align__(16) uint8_t g_finh[3u*128*16*17920];      // 110 MB
__device__ __align__(16) uint8_t g_finl[3u*128*16*17920];
__device__ __align__(16) uint8_t g_fouth[3u*128*16*20480];     // 126 MB (class-major rows)
__device__ __align__(16) uint8_t g_foutl[3u*128*16*20480];
__device__ float g_gram[3u*128*10400];                         //  16 MB: [pair][b][cls4][50][52]
__device__ float g_corrvec[128*600];
__device__ float g_catvec[128*600];

// conv smem: 3 stages of 37120: AH(10240) AL(10240) B(2x up to 8320); ctrl after.
#define CSTAGE 37120
#define C_CTRL 111360
#define CONV_SMEM (C_CTRL + 24)
// gram smem: 2 stages of 49152 (3 tensors x [H8000 L8000] + ldsm overrun pad)
#define GSTAGE 49152
#define G_CTRL (2*GSTAGE)
#define GRAM_SMEM (G_CTRL + 16)

__device__ __forceinline__ uint32_t smem_u32(const void* p) {
    uint32_t r;
    asm("{ .reg .u64 t; cvta.to.shared.u64 t, %1; cvt.u32.u64 %0, t; }" : "=r"(r) : "l"(p));
    return r;
}
#define MBAR_INIT(a, c) asm volatile("mbarrier.init.shared.b64 [%0], %1;" :: "r"(a), "r"(c) : "memory")
#define MBAR_EXPECT(a, n) asm volatile("mbarrier.arrive.expect_tx.shared.b64 _, [%0], %1;" :: "r"(a), "r"(n) : "memory")
#define MBAR_WAIT(a, ph) \
    asm volatile("{\n\t.reg .pred P;\n\tW_%=:\n\t" \
                 "mbarrier.try_wait.parity.acquire.cta.shared::cta.b64 P, [%0], %1, 0x989680;\n\t" \
                 "@!P bra W_%=;\n\t}" :: "r"(a), "r"(ph) : "memory")
#define BULK_G2S(dst, src, bytes, mbar) \
    asm volatile("cp.async.bulk.shared::cluster.global.mbarrier::complete_tx::bytes [%0], [%1], %2, [%3];" \
                 :: "r"(dst), "l"(src), "r"(bytes), "r"(mbar) : "memory")

__device__ __forceinline__ void ldsm4(uint32_t* r, uint32_t a) {
    asm volatile("ldmatrix.sync.aligned.m8n8.x4.shared.b16 {%0,%1,%2,%3}, [%4];"
        : "=r"(r[0]), "=r"(r[1]), "=r"(r[2]), "=r"(r[3]) : "r"(a));
}
__device__ __forceinline__ void ldsm2(uint32_t* r, uint32_t a) {
    asm volatile("ldmatrix.sync.aligned.m8n8.x2.shared.b16 {%0,%1}, [%2];"
        : "=r"(r[0]), "=r"(r[1]) : "r"(a));
}
__device__ __forceinline__ void mma16816(float* c, const uint32_t* a, const uint32_t* b) {
    asm volatile("mma.sync.aligned.m16n8k16.row.col.f32.bf16.bf16.f32 "
        "{%0,%1,%2,%3}, {%4,%5,%6,%7}, {%8,%9}, {%0,%1,%2,%3};"
        : "+f"(c[0]), "+f"(c[1]), "+f"(c[2]), "+f"(c[3])
        : "r"(a[0]), "r"(a[1]), "r"(a[2]), "r"(a[3]), "r"(b[0]), "r"(b[1]));
}
__device__ __forceinline__ void pack8(const float* v, uint4& h, uint4& l) {
    __align__(16) __nv_bfloat16 hb[8], lb[8];
#pragma unroll
    for (int u = 0; u < 8; u++) {
        hb[u] = __float2bfloat16_rn(v[u]);
        lb[u] = __float2bfloat16_rn(v[u] - __bfloat162float(hb[u]));
    }
    h = *reinterpret_cast<uint4*>(hb);
    l = *reinterpret_cast<uint4*>(lb);
}
__device__ __forceinline__ float2 bf2f(uint32_t u) {
    __nv_bfloat162 h = *reinterpret_cast<__nv_bfloat162*>(&u);
    return __bfloat1622float2(h);
}
// spatial pixel -> class-major row (class = parity pair, idx = halved coords)
__device__ __forceinline__ int perm_px(int p) {
    int y = p / 20, x = p - y * 20;
    return ((y & 1) * 2 + (x & 1)) * 50 + (y >> 1) * 10 + (x >> 1);
}

// ---- feats [b][c][p] -> transposed slab layout; also converts weights -------
__global__ __launch_bounds__(256) void convert_feat_kernel(
    const float* __restrict__ f1, const float* __restrict__ f2, const float* __restrict__ f3,
    uint8_t* __restrict__ oh, uint8_t* __restrict__ ol,
    const float* __restrict__ Wa, const float* __restrict__ Wb, const float* __restrict__ Wc,
    uint8_t* __restrict__ owh, uint8_t* __restrict__ owl)
{
    __shared__ float s[32 * 201];
    const int b = blockIdx.x, t = blockIdx.y, tid = threadIdx.x;

    // fused weight conversion: this block handles one 256-element chunk
    {
        int idx = (t * 128 + b) * 256 + tid;       // 0..98303 = 3*512*64
        int tt = idx / 32768, rr = idx - tt * 32768;
        int m = rr >> 6, g8 = rr & 63;
        const float* W = (tt == 0) ? Wa : ((tt == 1) ? Wb : Wc);
        float v[8];
#pragma unroll
        for (int u = 0; u < 8; u++) v[u] = W[m * 512 + g8 * 8 + u];
        uint4 vh, vl; pack8(v, vh, vl);
        int mt = m >> 7, mr = m & 127, slab = g8 >> 2, c8 = g8 & 3;
        size_t off = ((size_t)(tt * 4 + mt) * 16 + slab) * 10240 + mr * 80 + c8 * 16;
        *(uint4*)(owh + off) = vh;
        *(uint4*)(owl + off) = vl;
    }

    const float* F = ((t == 0) ? f1 : ((t == 1) ? f2 : f3)) + (size_t)b * 102400;
    uint8_t* obh = oh + ((size_t)t * 128 + b) * 286720;
    uint8_t* obl = ol + ((size_t)t * 128 + b) * 286720;
    for (int c = 0; c < 16; c++) {
        __syncthreads();
        for (int e = tid; e < 32 * 200; e += 256) {
            int kk = e / 200, n = e - kk * 200;
            s[kk * 201 + n] = F[(size_t)(c * 32 + kk) * 200 + n];
        }
        __syncthreads();
        for (int i = tid; i < 800; i += 256) {
            int p = i >> 2, g8 = i & 3;
            float v[8];
#pragma unroll
            for (int u = 0; u < 8; u++) v[u] = s[(g8 * 8 + u) * 201 + p];
            uint4 vh, vl; pack8(v, vh, vl);
            size_t off = (size_t)c * 17920 + p * 80 + g8 * 16;
            *(uint4*)(obh + off) = vh;
            *(uint4*)(obl + off) = vl;
        }
    }
}

// ---- conv1x1 GEMM: hi/lo bf16 mma.sync, 8 warps (4Mx2N), 3-stage pipeline ----
__global__ __launch_bounds__(256, 2) void gemm_conv_kernel(
    const uint8_t* __restrict__ Ah, const uint8_t* __restrict__ Al,
    const uint8_t* __restrict__ Bh, const uint8_t* __restrict__ Bl,
    const float* __restrict__ b0, const float* __restrict__ b1, const float* __restrict__ b2,
    uint8_t* __restrict__ Oh, uint8_t* __restrict__ Ol)
{
    extern __shared__ __align__(128) uint8_t smem[];
    const int tid = threadIdx.x;
    const int mt = blockIdx.x >> 1, nt = blockIdx.x & 1;
    const int b = blockIdx.y, z = blockIdx.z;
    const uint32_t sb = smem_u32(smem);
    const int warp = tid >> 5, lane = tid & 31;
    const int warpM = warp & 3, warpN = warp >> 2;
    const int nvalid = nt ? 96 : 104;
    const uint32_t bBytes = nvalid * 80;
    const uint32_t TXB = 20480 + 2 * bBytes;

    const uint32_t CTRL = sb + C_CTRL;
    if (tid == 0) {
#pragma unroll
        for (int p = 0; p < 3; p++) MBAR_INIT(CTRL + p * 8, 1);
    }
    __syncthreads();

    const uint8_t* pAh = Ah + (size_t)(z * 4 + mt) * 163840;
    const uint8_t* pAl = Al + (size_t)(z * 4 + mt) * 163840;
    const uint8_t* pBh = Bh + (size_t)(z * 128 + b) * 286720 + (size_t)nt * 8320;
    const uint8_t* pBl = Bl + (size_t)(z * 128 + b) * 286720 + (size_t)nt * 8320;

    if (tid == 0) {
#pragma unroll
        for (int s = 0; s < 3; s++) {
            const uint32_t st = sb + s * CSTAGE;
            MBAR_EXPECT(CTRL + s * 8, TXB);
            BULK_G2S(st,         pAh + (size_t)s * 10240, 10240, CTRL + s * 8);
            BULK_G2S(st + 10240, pAl + (size_t)s * 10240, 10240, CTRL + s * 8);
            BULK_G2S(st + 20480,          pBh + (size_t)s * 17920, bBytes, CTRL + s * 8);
            BULK_G2S(st + 20480 + bBytes, pBl + (size_t)s * 17920, bBytes, CTRL + s * 8);
        }
    }

    float c[2][7][4];
#pragma unroll
    for (int i = 0; i < 2; i++)
#pragma unroll
        for (int j = 0; j < 7; j++)
#pragma unroll
            for (int k = 0; k < 4; k++) c[i][j][k] = 0.f;

    int phF[3] = {0, 0, 0};
    int p = 0;
    for (int s = 0; s < 16; s++) {
        const uint32_t st = sb + p * CSTAGE;
        MBAR_WAIT(CTRL + p * 8, phF[p]); phF[p] ^= 1;

        const uint32_t aBase = st + (warpM * 32 + (lane & 15)) * 80 + (lane & 16);
        const uint32_t bBase = st + 20480 + (warpN * 56 + (lane & 7)) * 80 + (lane & 8) * 2;
#pragma unroll
        for (int ks = 0; ks < 2; ks++) {
            const uint32_t kb = ks * 32;
            uint32_t afh[2][4], afl[2][4];
#pragma unroll
            for (int mi = 0; mi < 2; mi++) {
                ldsm4(afh[mi], aBase + mi * 1280 + kb);
                ldsm4(afl[mi], aBase + 10240 + mi * 1280 + kb);
            }
#pragma unroll
            for (int ni = 0; ni < 7; ni++) {
                if (warpN * 56 + ni * 8 >= nvalid) continue;
                uint32_t bfh[2], bfl[2];
                ldsm2(bfh, bBase + ni * 640 + kb);
                ldsm2(bfl, bBase + ni * 640 + kb + bBytes);
#pragma unroll
                for (int mi = 0; mi < 2; mi++) {
                    mma16816(c[mi][ni], afh[mi], bfh);
                    mma16816(c[mi][ni], afh[mi], bfl);
                    mma16816(c[mi][ni], afl[mi], bfh);
                }
            }
        }
        __syncthreads();
        if (tid == 0 && s + 3 < 16) {
            const int sn = s + 3;
            MBAR_EXPECT(CTRL + p * 8, TXB);
            BULK_G2S(st,         pAh + (size_t)sn * 10240, 10240, CTRL + p * 8);
            BULK_G2S(st + 10240, pAl + (size_t)sn * 10240, 10240, CTRL + p * 8);
            BULK_G2S(st + 20480,          pBh + (size_t)sn * 17920, bBytes, CTRL + p * 8);
            BULK_G2S(st + 20480 + bBytes, pBl + (size_t)sn * 17920, bBytes, CTRL + p * 8);
        }
        p = (p == 2) ? 0 : p + 1;
    }
    __syncthreads();

    // epilogue: bias, split hi/lo, write rows in CLASS-MAJOR (perm) order
    const float* bias = (z == 0) ? b0 : ((z == 1) ? b1 : b2);
    __nv_bfloat16* sH = reinterpret_cast<__nv_bfloat16*>(smem);   // [pp<104][m128]
    __nv_bfloat16* sL = sH + 13312;
#pragma unroll
    for (int mi = 0; mi < 2; mi++) {
        const int m0 = warpM * 32 + mi * 16 + (lane >> 2);
        const float bv0 = __ldg(bias + mt * 128 + m0);
        const float bv1 = __ldg(bias + mt * 128 + m0 + 8);
#pragma unroll
        for (int ni = 0; ni < 7; ni++) {
            const int p0 = warpN * 56 + ni * 8 + (lane & 3) * 2;
            if (p0 >= nvalid) continue;
            float v[4] = {c[mi][ni][0] + bv0, c[mi][ni][1] + bv0,
                          c[mi][ni][2] + bv1, c[mi][ni][3] + bv1};
#pragma unroll
            for (int q = 0; q < 4; q++) {
                const int pp = p0 + (q & 1), mm = m0 + (q < 2 ? 0 : 8);
                __nv_bfloat16 h = __float2bfloat16_rn(v[q]);
                sH[pp * 128 + mm] = h;
                sL[pp * 128 + mm] = __float2bfloat16_rn(v[q] - __bfloat162float(h));
            }
        }
    }
    __syncthreads();
    uint8_t* ohB = Oh + ((size_t)(z * 128 + b) * 16 + mt * 4) * 20480;
    uint8_t* olB = Ol + ((size_t)(z * 128 + b) * 16 + mt * 4) * 20480;
    const int tot = nvalid * 16;
    for (int g = tid; g < tot; g += 256) {
        int pp = g >> 4, o = g & 15, q = o >> 2, oo = o & 3;
        int pr = perm_px(nt * 104 + pp);
        uint32_t so = (pp * 128 + q * 32 + oo * 8) * 2;
        size_t dof = (size_t)q * 20480 + pr * 80 + oo * 16;
        *(uint4*)(ohB + dof) = *(uint4*)((uint8_t*)sH + so);
        *(uint4*)(olB + dof) = *(uint4*)((uint8_t*)sL + so);
    }
}

// ---- Gram GEMM, class-blocked: only same-parity 50x50 blocks are computed. --
// Grid (2,128): ct = class-half {0,1}, b. 512 threads; warp sub<3 -> pair,
// grp -> (cls, miGroup). All 3 tensors staged once; 3 pair-products computed.
__global__ __launch_bounds__(512, 1) void gemm_gram_kernel(
    const uint8_t* __restrict__ Fh, const uint8_t* __restrict__ Fl, float* __restrict__ G)
{
    extern __shared__ __align__(128) uint8_t smem[];
    const int tid = threadIdx.x;
    const int ct = blockIdx.x, b = blockIdx.y;
    const uint32_t sb = smem_u32(smem);
    const int warp = tid >> 5, lane = tid & 31;
    const int sub = warp & 3, grp = warp >> 2;
    const bool active = (sub < 3);
    const int pr = sub;                    // pair 0..2 (f1f2, f1f3, f2f3)
    const int cls = grp >> 1, wm = grp & 1;
    const int pa = (pr == 2) ? 1 : 0, pb = (pr == 0) ? 1 : 2;

    const uint32_t CTRL = sb + G_CTRL;
    if (tid == 0) { MBAR_INIT(CTRL, 1); MBAR_INIT(CTRL + 8, 1); }
    __syncthreads();

    size_t baseT[3];
#pragma unroll
    for (int t = 0; t < 3; t++)
        baseT[t] = ((size_t)t * 128 + b) * 327680 + (size_t)ct * 8000;

    if (tid == 0) {
#pragma unroll
        for (int s = 0; s < 2; s++) {
            const uint32_t st = sb + s * GSTAGE;
            MBAR_EXPECT(CTRL + s * 8, 48000);
#pragma unroll
            for (int t = 0; t < 3; t++) {
                BULK_G2S(st + t * 16000,        Fh + baseT[t] + (size_t)s * 20480, 8000, CTRL + s * 8);
                BULK_G2S(st + t * 16000 + 8000, Fl + baseT[t] + (size_t)s * 20480, 8000, CTRL + s * 8);
            }
        }
    }

    float c[2][7][4];
#pragma unroll
    for (int i = 0; i < 2; i++)
#pragma unroll
        for (int j = 0; j < 7; j++)
#pragma unroll
            for (int k = 0; k < 4; k++) c[i][j][k] = 0.f;

    int phF[2] = {0, 0};
    for (int s = 0; s < 16; s++) {
        const int p = s & 1;
        const uint32_t st = sb + p * GSTAGE;
        MBAR_WAIT(CTRL + p * 8, phF[p]); phF[p] ^= 1;

        if (active) {
            const uint32_t aBase = st + pa * 16000 + (cls * 50 + wm * 32 + (lane & 15)) * 80 + (lane & 16);
            const uint32_t bBase = st + pb * 16000 + (cls * 50 + (lane & 7)) * 80 + (lane & 8) * 2;
#pragma unroll
            for (int ks = 0; ks < 2; ks++) {
                const uint32_t kb = ks * 32;
                uint32_t afh[2][4], afl[2][4];
#pragma unroll
                for (int mi = 0; mi < 2; mi++) {
                    ldsm4(afh[mi], aBase + mi * 1280 + kb);
                    ldsm4(afl[mi], aBase + 8000 + mi * 1280 + kb);
                }
#pragma unroll
                for (int ni = 0; ni < 7; ni++) {
                    uint32_t bfh[2], bfl[2];
                    ldsm2(bfh, bBase + ni * 640 + kb);
                    ldsm2(bfl, bBase + 8000 + ni * 640 + kb);
#pragma unroll
                    for (int mi = 0; mi < 2; mi++) {
                        mma16816(c[mi][ni], afh[mi], bfh);
                        mma16816(c[mi][ni], afh[mi], bfl);
                        mma16816(c[mi][ni], afl[mi], bfh);
                    }
                }
            }
        }
        __syncthreads();
        if (tid == 0 && s + 2 < 16) {
            const int sn = s + 2;
            MBAR_EXPECT(CTRL + p * 8, 48000);
#pragma unroll
            for (int t = 0; t < 3; t++) {
                BULK_G2S(st + t * 16000,        Fh + baseT[t] + (size_t)sn * 20480, 8000, CTRL + p * 8);
                BULK_G2S(st + t * 16000 + 8000, Fl + baseT[t] + (size_t)sn * 20480, 8000, CTRL + p * 8);
            }
        }
    }

    if (active) {
        float* Gb = G + ((size_t)pr * 128 + b) * 10400 + (ct * 2 + cls) * 2600;
#pragma unroll
        for (int mi = 0; mi < 2; mi++) {
            const int m = wm * 32 + mi * 16 + (lane >> 2);
#pragma unroll
            for (int ni = 0; ni < 7; ni++) {
                const int n0 = ni * 8 + (lane & 3) * 2;
                if (n0 >= 50) continue;
                if (m < 50)
                    *(float2*)(Gb + m * 52 + n0) = make_float2(c[mi][ni][0], c[mi][ni][1]);
                if (m + 8 < 50)
                    *(float2*)(Gb + (m + 8) * 52 + n0) = make_float2(c[mi][ni][2], c[mi][ni][3]);
            }
        }
    }
}

// ---- fused heads: y==0 -> corr (dense class-block gather), y==1 -> cat ------
__global__ __launch_bounds__(256)
void heads_kernel(const float* __restrict__ Gram, const float* __restrict__ Wcorr,
                  const float* __restrict__ bcorr, float* __restrict__ corrvec,
                  const uint8_t* __restrict__ Fh, const uint8_t* __restrict__ Fl,
                  const float* __restrict__ Wcat, const float* __restrict__ bcat,
                  float* __restrict__ catvec)
{
    extern __shared__ float sh[];
    const int b = blockIdx.x, tid = threadIdx.x;
    const int y = tid / 20, x = tid - y * 20;
    float acc0 = 0.f, acc1 = 0.f, acc2 = 0.f;

    if (blockIdx.y == 0) {
        float* sG = sh;             // 10400 floats: [cls4][50][52]
        float* sW = sh + 10400;     // 11907
        for (int pair = 0; pair < 3; pair++) {
            __syncthreads();
            const float4* G4 = reinterpret_cast<const float4*>(Gram + ((size_t)pair * 128 + b) * 10400);
            float4* sG4 = reinterpret_cast<float4*>(sG);
            for (int i = tid; i < 2600; i += 256) sG4[i] = G4[i];
            for (int i = tid; i < 11907; i += 256) {
                int o = i / 3969, r = i - o * 3969;
                sW[i] = Wcorr[o * 11907 + pair * 3969 + r];
            }
            __syncthreads();
            if (tid < NPIX) {
                for (int ky = 0; ky < 3; ky++) {
                    int sy = y + ky - 1;
                    if ((unsigned)sy >= 10u) continue;
                    for (int kx = 0; kx < 3; kx++) {
                        int sx = x + kx - 1;
                        if ((unsigned)sx >= 20u) continue;
                        const int cc = (sy & 1) * 2 + (sx & 1);
                        const int i1 = (sy >> 1) * 10 + (sx >> 1);
                        const float* gblk = sG + cc * 2600 + i1 * 52;
                        const int tap = ky * 3 + kx;
                        const int dyi0 = (21 - sy) >> 1, dxi0 = (21 - sx) >> 1;
                        for (int iy = 0; iy < 5; iy++) {
                            const float* grow = gblk + iy * 10;
                            const float* wrow = sW + ((dyi0 + iy) * 21 + dxi0) * 9 + tap;
#pragma unroll
                            for (int ix = 0; ix < 10; ix++) {
                                float g = grow[ix] * (1.f / 512.f);
                                float v = g > 0.f ? g : 0.1f * g;
                                acc0 += v * wrow[ix * 9];
                                acc1 += v * wrow[3969 + ix * 9];
                                acc2 += v * wrow[7938 + ix * 9];
                            }
                        }
                    }
                }
            }
        }
        if (tid < NPIX) {
            corrvec[b * 600 + tid]       = fmaxf(acc0 + bcorr[0], 0.f);
            corrvec[b * 600 + 200 + tid] = fmaxf(acc1 + bcorr[1], 0.f);
            corrvec[b * 600 + 400 + tid] = fmaxf(acc2 + bcorr[2], 0.f);
        }
    } else {
        float* sF = sh;             // [(t*200+p)*68 + c]
        float* sW = sh + 40800;
        for (int cc = 0; cc < 512; cc += 64) {
            __syncthreads();
            for (int g = tid; g < 4800; g += 256) {
                int t = g / 1600, r = g - t * 1600, p = r >> 3, g8 = r & 7;
                int slab = (cc >> 5) + (g8 >> 2);
                int pr = perm_px(p);
                size_t base = (((size_t)t * 128 + b) * 16 + slab) * 20480 + pr * 80 + (g8 & 3) * 16;
                uint4 vh = *(const uint4*)(Fh + base);
                uint4 vl = *(const uint4*)(Fl + base);
                float* d = &sF[(t * 200 + p) * 68 + g8 * 8];
                float2 a0 = bf2f(vh.x), c0 = bf2f(vl.x); d[0] = a0.x + c0.x; d[1] = a0.y + c0.y;
                float2 a1 = bf2f(vh.y), c1 = bf2f(vl.y); d[2] = a1.x + c1.x; d[3] = a1.y + c1.y;
                float2 a2 = bf2f(vh.z), c2 = bf2f(vl.z); d[4] = a2.x + c2.x; d[5] = a2.y + c2.y;
                float2 a3 = bf2f(vh.w), c3 = bf2f(vl.w); d[6] = a3.x + c3.x; d[7] = a3.y + c3.y;
            }
            for (int i = tid; i < 5184; i += 256) {
                int o = i / 1728, r = i - o * 1728, t = r / 576, r2 = r - t * 576;
                int tap = r2 >> 6, cch = r2 & 63;
                sW[i] = Wcat[(size_t)(o * 1536 + t * 512 + cc + cch) * 9 + tap];
            }
            __syncthreads();
            if (tid < NPIX) {
                for (int t = 0; t < 3; t++)
                    for (int ky = 0; ky < 3; ky++) {
                        int sy = y + ky - 1;
                        if ((unsigned)sy >= 10u) continue;
                        for (int kx = 0; kx < 3; kx++) {
                            int sx = x + kx - 1;
                            if ((unsigned)sx >= 20u) continue;
                            const float4* v4 = reinterpret_cast<const float4*>(sF + (t * 200 + sy * 20 + sx) * 68);
                            int tap = ky * 3 + kx;
                            const float4* w0 = reinterpret_cast<const float4*>(sW + (t * 9 + tap) * 64);
                            const float4* w1 = reinterpret_cast<const float4*>(sW + 1728 + (t * 9 + tap) * 64);
                            const float4* w2 = reinterpret_cast<const float4*>(sW + 3456 + (t * 9 + tap) * 64);
#pragma unroll
                            for (int c4 = 0; c4 < 16; c4++) {
                                float4 v = v4[c4];
                                float4 a = w0[c4], bq = w1[c4], cq = w2[c4];
                                acc0 += v.x * a.x + v.y * a.y + v.z * a.z + v.w * a.w;
                                acc1 += v.x * bq.x + v.y * bq.y + v.z * bq.z + v.w * bq.w;
                                acc2 += v.x * cq.x + v.y * cq.y + v.z * cq.z + v.w * cq.w;
                            }
                        }
                    }
            }
        }
        if (tid < NPIX) {
            catvec[b * 600 + tid]       = acc0 + bcat[0];
            catvec[b * 600 + 200 + tid] = acc1 + bcat[1];
            catvec[b * 600 + 400 + tid] = acc2 + bcat[2];
        }
    }
}

// ---- MLP heads + final linear ------------------------------------------------
__global__ __launch_bounds__(256)
void mlp_kernel(const float* __restrict__ corrvec, const float* __restrict__ catvec,
                const float* __restrict__ cf_w1, const float* __restrict__ cf_b1,
                const float* __restrict__ cf_w2, const float* __restrict__ cf_b2,
                const float* __restrict__ ccf_w1, const float* __restrict__ ccf_b1,
                const float* __restrict__ ccf_w2, const float* __restrict__ ccf_b2,
                const float* __restrict__ Wout, const float* __restrict__ bout,
                float* __restrict__ out)
{
    __shared__ float sx[600];
    __shared__ float h1[256];
    __shared__ float h2[2][128];
    const int b = blockIdx.x, tid = threadIdx.x;

    for (int path = 0; path < 2; path++) {
        const float* xv = (path == 0 ? corrvec : catvec) + b * 600;
        const float* w1 = path == 0 ? cf_w1 : ccf_w1;
        const float* b1 = path == 0 ? cf_b1 : ccf_b1;
        const float* w2 = path == 0 ? cf_w2 : ccf_w2;
        const float* b2 = path == 0 ? cf_b2 : ccf_b2;
        __syncthreads();
        for (int i = tid; i < 600; i += 256) sx[i] = xv[i];
        __syncthreads();
        {
            float s = b1[tid];
            const float4* wr = reinterpret_cast<const float4*>(w1 + (size_t)tid * 600);
#pragma unroll 4
            for (int k = 0; k < 150; k++) {
                float4 w = wr[k];
                s += w.x * sx[4*k] + w.y * sx[4*k+1] + w.z * sx[4*k+2] + w.w * sx[4*k+3];
            }
            h1[tid] = fmaxf(s, 0.f);
        }
        __syncthreads();
        if (tid < 128) {
            float s = b2[tid];
            const float4* wr = reinterpret_cast<const float4*>(w2 + (size_t)tid * 256);
#pragma unroll 4
            for (int k = 0; k < 64; k++) {
                float4 w = wr[k];
                s += w.x * h1[4*k] + w.y * h1[4*k+1] + w.z * h1[4*k+2] + w.w * h1[4*k+3];
            }
            h2[path][tid] = fmaxf(s, 0.f);
        }
    }
    __syncthreads();
    if (tid < 2) {
        float s = bout[tid];
        const float* wr = Wout + tid * 256;
        for (int i = 0; i < 128; i++)
            s += h2[0][i] * wr[i] + h2[1][i] * wr[128 + i];
        out[b * 2 + tid] = s;
    }
}

// ---- launch -------------------------------------------------------------------
extern "C" void kernel_launch(void* const* d_in, const int* in_sizes, int n_in,
                              void* d_out, int out_size)
{
    (void)in_sizes; (void)n_in; (void)out_size;
    const float* feat1 = (const float*)d_in[0];
    const float* feat2 = (const float*)d_in[1];
    const float* feat3 = (const float*)d_in[2];
    const float* Wa = (const float*)d_in[3];   const float* ba = (const float*)d_in[4];
    const float* Wb = (const float*)d_in[5];   const float* bb = (const float*)d_in[6];
    const float* Wc = (const float*)d_in[7];   const float* bc = (const float*)d_in[8];
    const float* Wcorr = (const float*)d_in[9];  const float* bcorr = (const float*)d_in[10];
    const float* Wcat = (const float*)d_in[11];  const float* bcat = (const float*)d_in[12];
    const float* cf_w1 = (const float*)d_in[13]; const float* cf_b1 = (const float*)d_in[14];
    const float* cf_w2 = (const float*)d_in[15]; const float* cf_b2 = (const float*)d_in[16];
    const float* ccf_w1 = (const float*)d_in[17]; const float* ccf_b1 = (const float*)d_in[18];
    const float* ccf_w2 = (const float*)d_in[19]; const float* ccf_b2 = (const float*)d_in[20];
    const float* Wout = (const float*)d_in[21];  const float* bout = (const float*)d_in[22];

    uint8_t *wh, *wl, *fih, *fil, *foh, *fol;
    float *G, *cv, *tv;
    cudaGetSymbolAddress((void**)&wh,  g_wh);
    cudaGetSymbolAddress((void**)&wl,  g_wl);
    cudaGetSymbolAddress((void**)&fih, g_finh);
    cudaGetSymbolAddress((void**)&fil, g_finl);
    cudaGetSymbolAddress((void**)&foh, g_fouth);
    cudaGetSymbolAddress((void**)&fol, g_foutl);
    cudaGetSymbolAddress((void**)&G,   g_gram);
    cudaGetSymbolAddress((void**)&cv,  g_corrvec);
    cudaGetSymbolAddress((void**)&tv,  g_catvec);

    cudaFuncSetAttribute(gemm_conv_kernel, cudaFuncAttributeMaxDynamicSharedMemorySize, CONV_SMEM);
    cudaFuncSetAttribute(gemm_gram_kernel, cudaFuncAttributeMaxDynamicSharedMemorySize, GRAM_SMEM);

    convert_feat_kernel<<<dim3(128, 3), 256>>>(feat1, feat2, feat3, fih, fil,
                                               Wa, Wb, Wc, wh, wl);

    // conv1x1 per (mtile4 x ntile2, batch, tensor)
    gemm_conv_kernel<<<dim3(8, 128, 3), 256, CONV_SMEM>>>(
        wh, wl, fih, fil, ba, bb, bc, foh, fol);

    // Gram class-blocks per (class-half, batch); all 3 pairs per CTA
    gemm_gram_kernel<<<dim3(2, 128), 512, GRAM_SMEM>>>(foh, fol, G);

    // fused corr + cat heads (overlapped)
    const int HEADS_SMEM = (40800 + 5184) * 4;   // cat is the max (183936)
    cudaFuncSetAttribute(heads_kernel, cudaFuncAttributeMaxDynamicSharedMemorySize, HEADS_SMEM);
    heads_kernel<<<dim3(128, 2), 256, HEADS_SMEM>>>(G, Wcorr, bcorr, cv,
                                                    foh, fol, Wcat, bcat, tv);

    mlp_kernel<<<128, 256>>>(cv, tv, cf_w1, cf_b1, cf_w2, cf_b2,
                             ccf_w1, ccf_b1, ccf_w2, ccf_b2, Wout, bout, (float*)d_out);
}

// round 12
// speedup vs baseline: 1.7772x; 1.1890x over previous
#include <cuda_runtime.h>
#include <cuda_bf16.h>
#include <cstdint>
#include <cstddef>

#define NPIX 200

// ---- gmem scratch (static; zero-initialized at load — pad rows rely on it) --
__device__ __align__(16) uint8_t g_wh[3u*4*16*10240];          //  2 MB
__device__ __align__(16) uint8_t g_wl[3u*4*16*10240];
__device__ __align__(16) uint8_t g_finh[3u*128*16*17920];      // 110 MB
__device__ __align__(16) uint8_t g_finl[3u*128*16*17920];
__device__ __align__(16) uint8_t g_fouth[3u*128*16*20480];     // 126 MB (class-major rows)
__device__ __align__(16) uint8_t g_foutl[3u*128*16*20480];
__device__ float g_gram[3u*128*10400];                         //  16 MB: [pair][b][cls4][50][52]
__device__ float g_corrpart[3*128*600];                        // per-pair partials
__device__ float g_catpart[16*128*600];                        // per-slab partials

// conv smem: 3 stages of 37120: AH(10240) AL(10240) B(2x up to 8320); ctrl after.
#define CSTAGE 37120
#define C_CTRL 111360
#define CONV_SMEM (C_CTRL + 24)
// gram smem: 2 stages of 49152 (3 tensors x [H8000 L8000] + ldsm overrun pad)
#define GSTAGE 49152
#define G_CTRL (2*GSTAGE)
#define GRAM_SMEM (G_CTRL + 16)
// heads smem: max(corr 10400+11907, cat 21600+2592) floats
#define HEADS_SMEM (24192 * 4)

__device__ __forceinline__ uint32_t smem_u32(const void* p) {
    uint32_t r;
    asm("{ .reg .u64 t; cvta.to.shared.u64 t, %1; cvt.u32.u64 %0, t; }" : "=r"(r) : "l"(p));
    return r;
}
#define MBAR_INIT(a, c) asm volatile("mbarrier.init.shared.b64 [%0], %1;" :: "r"(a), "r"(c) : "memory")
#define MBAR_EXPECT(a, n) asm volatile("mbarrier.arrive.expect_tx.shared.b64 _, [%0], %1;" :: "r"(a), "r"(n) : "memory")
#define MBAR_WAIT(a, ph) \
    asm volatile("{\n\t.reg .pred P;\n\tW_%=:\n\t" \
                 "mbarrier.try_wait.parity.acquire.cta.shared::cta.b64 P, [%0], %1, 0x989680;\n\t" \
                 "@!P bra W_%=;\n\t}" :: "r"(a), "r"(ph) : "memory")
#define BULK_G2S(dst, src, bytes, mbar) \
    asm volatile("cp.async.bulk.shared::cluster.global.mbarrier::complete_tx::bytes [%0], [%1], %2, [%3];" \
                 :: "r"(dst), "l"(src), "r"(bytes), "r"(mbar) : "memory")

__device__ __forceinline__ void ldsm4(uint32_t* r, uint32_t a) {
    asm volatile("ldmatrix.sync.aligned.m8n8.x4.shared.b16 {%0,%1,%2,%3}, [%4];"
        : "=r"(r[0]), "=r"(r[1]), "=r"(r[2]), "=r"(r[3]) : "r"(a));
}
__device__ __forceinline__ void ldsm2(uint32_t* r, uint32_t a) {
    asm volatile("ldmatrix.sync.aligned.m8n8.x2.shared.b16 {%0,%1}, [%2];"
        : "=r"(r[0]), "=r"(r[1]) : "r"(a));
}
__device__ __forceinline__ void mma16816(float* c, const uint32_t* a, const uint32_t* b) {
    asm volatile("mma.sync.aligned.m16n8k16.row.col.f32.bf16.bf16.f32 "
        "{%0,%1,%2,%3}, {%4,%5,%6,%7}, {%8,%9}, {%0,%1,%2,%3};"
        : "+f"(c[0]), "+f"(c[1]), "+f"(c[2]), "+f"(c[3])
        : "r"(a[0]), "r"(a[1]), "r"(a[2]), "r"(a[3]), "r"(b[0]), "r"(b[1]));
}
__device__ __forceinline__ void pack8(const float* v, uint4& h, uint4& l) {
    __align__(16) __nv_bfloat16 hb[8], lb[8];
#pragma unroll
    for (int u = 0; u < 8; u++) {
        hb[u] = __float2bfloat16_rn(v[u]);
        lb[u] = __float2bfloat16_rn(v[u] - __bfloat162float(hb[u]));
    }
    h = *reinterpret_cast<uint4*>(hb);
    l = *reinterpret_cast<uint4*>(lb);
}
__device__ __forceinline__ float2 bf2f(uint32_t u) {
    __nv_bfloat162 h = *reinterpret_cast<__nv_bfloat162*>(&u);
    return __bfloat1622float2(h);
}
// spatial pixel -> class-major row (class = parity pair, idx = halved coords)
__device__ __forceinline__ int perm_px(int p) {
    int y = p / 20, x = p - y * 20;
    return ((y & 1) * 2 + (x & 1)) * 50 + (y >> 1) * 10 + (x >> 1);
}

// ---- feats [b][c][p] -> transposed slab layout; also converts weights -------
__global__ __launch_bounds__(256) void convert_feat_kernel(
    const float* __restrict__ f1, const float* __restrict__ f2, const float* __restrict__ f3,
    uint8_t* __restrict__ oh, uint8_t* __restrict__ ol,
    const float* __restrict__ Wa, const float* __restrict__ Wb, const float* __restrict__ Wc,
    uint8_t* __restrict__ owh, uint8_t* __restrict__ owl)
{
    __shared__ float s[32 * 201];
    const int b = blockIdx.x, t = blockIdx.y, tid = threadIdx.x;

    {
        int idx = (t * 128 + b) * 256 + tid;       // 0..98303 = 3*512*64
        int tt = idx / 32768, rr = idx - tt * 32768;
        int m = rr >> 6, g8 = rr & 63;
        const float* W = (tt == 0) ? Wa : ((tt == 1) ? Wb : Wc);
        float v[8];
#pragma unroll
        for (int u = 0; u < 8; u++) v[u] = W[m * 512 + g8 * 8 + u];
        uint4 vh, vl; pack8(v, vh, vl);
        int mt = m >> 7, mr = m & 127, slab = g8 >> 2, c8 = g8 & 3;
        size_t off = ((size_t)(tt * 4 + mt) * 16 + slab) * 10240 + mr * 80 + c8 * 16;
        *(uint4*)(owh + off) = vh;
        *(uint4*)(owl + off) = vl;
    }

    const float* F = ((t == 0) ? f1 : ((t == 1) ? f2 : f3)) + (size_t)b * 102400;
    uint8_t* obh = oh + ((size_t)t * 128 + b) * 286720;
    uint8_t* obl = ol + ((size_t)t * 128 + b) * 286720;
    for (int c = 0; c < 16; c++) {
        __syncthreads();
        for (int e = tid; e < 32 * 200; e += 256) {
            int kk = e / 200, n = e - kk * 200;
            s[kk * 201 + n] = F[(size_t)(c * 32 + kk) * 200 + n];
        }
        __syncthreads();
        for (int i = tid; i < 800; i += 256) {
            int p = i >> 2, g8 = i & 3;
            float v[8];
#pragma unroll
            for (int u = 0; u < 8; u++) v[u] = s[(g8 * 8 + u) * 201 + p];
            uint4 vh, vl; pack8(v, vh, vl);
            size_t off = (size_t)c * 17920 + p * 80 + g8 * 16;
            *(uint4*)(obh + off) = vh;
            *(uint4*)(obl + off) = vl;
        }
    }
}

// ---- conv1x1 GEMM: hi/lo bf16 mma.sync, 8 warps (4Mx2N), 3-stage pipeline ----
__global__ __launch_bounds__(256, 2) void gemm_conv_kernel(
    const uint8_t* __restrict__ Ah, const uint8_t* __restrict__ Al,
    const uint8_t* __restrict__ Bh, const uint8_t* __restrict__ Bl,
    const float* __restrict__ b0, const float* __restrict__ b1, const float* __restrict__ b2,
    uint8_t* __restrict__ Oh, uint8_t* __restrict__ Ol)
{
    extern __shared__ __align__(128) uint8_t smem[];
    const int tid = threadIdx.x;
    const int mt = blockIdx.x >> 1, nt = blockIdx.x & 1;
    const int b = blockIdx.y, z = blockIdx.z;
    const uint32_t sb = smem_u32(smem);
    const int warp = tid >> 5, lane = tid & 31;
    const int warpM = warp & 3, warpN = warp >> 2;
    const int nvalid = nt ? 96 : 104;
    const uint32_t bBytes = nvalid * 80;
    const uint32_t TXB = 20480 + 2 * bBytes;

    const uint32_t CTRL = sb + C_CTRL;
    if (tid == 0) {
#pragma unroll
        for (int p = 0; p < 3; p++) MBAR_INIT(CTRL + p * 8, 1);
    }
    __syncthreads();

    const uint8_t* pAh = Ah + (size_t)(z * 4 + mt) * 163840;
    const uint8_t* pAl = Al + (size_t)(z * 4 + mt) * 163840;
    const uint8_t* pBh = Bh + (size_t)(z * 128 + b) * 286720 + (size_t)nt * 8320;
    const uint8_t* pBl = Bl + (size_t)(z * 128 + b) * 286720 + (size_t)nt * 8320;

    if (tid == 0) {
#pragma unroll
        for (int s = 0; s < 3; s++) {
            const uint32_t st = sb + s * CSTAGE;
            MBAR_EXPECT(CTRL + s * 8, TXB);
            BULK_G2S(st,         pAh + (size_t)s * 10240, 10240, CTRL + s * 8);
            BULK_G2S(st + 10240, pAl + (size_t)s * 10240, 10240, CTRL + s * 8);
            BULK_G2S(st + 20480,          pBh + (size_t)s * 17920, bBytes, CTRL + s * 8);
            BULK_G2S(st + 20480 + bBytes, pBl + (size_t)s * 17920, bBytes, CTRL + s * 8);
        }
    }

    float c[2][7][4];
#pragma unroll
    for (int i = 0; i < 2; i++)
#pragma unroll
        for (int j = 0; j < 7; j++)
#pragma unroll
            for (int k = 0; k < 4; k++) c[i][j][k] = 0.f;

    int phF[3] = {0, 0, 0};
    int p = 0;
    for (int s = 0; s < 16; s++) {
        const uint32_t st = sb + p * CSTAGE;
        MBAR_WAIT(CTRL + p * 8, phF[p]); phF[p] ^= 1;

        const uint32_t aBase = st + (warpM * 32 + (lane & 15)) * 80 + (lane & 16);
        const uint32_t bBase = st + 20480 + (warpN * 56 + (lane & 7)) * 80 + (lane & 8) * 2;
#pragma unroll
        for (int ks = 0; ks < 2; ks++) {
            const uint32_t kb = ks * 32;
            uint32_t afh[2][4], afl[2][4];
#pragma unroll
            for (int mi = 0; mi < 2; mi++) {
                ldsm4(afh[mi], aBase + mi * 1280 + kb);
                ldsm4(afl[mi], aBase + 10240 + mi * 1280 + kb);
            }
#pragma unroll
            for (int ni = 0; ni < 7; ni++) {
                if (warpN * 56 + ni * 8 >= nvalid) continue;
                uint32_t bfh[2], bfl[2];
                ldsm2(bfh, bBase + ni * 640 + kb);
                ldsm2(bfl, bBase + ni * 640 + kb + bBytes);
#pragma unroll
                for (int mi = 0; mi < 2; mi++) {
                    mma16816(c[mi][ni], afh[mi], bfh);
                    mma16816(c[mi][ni], afh[mi], bfl);
                    mma16816(c[mi][ni], afl[mi], bfh);
                }
            }
        }
        __syncthreads();
        if (tid == 0 && s + 3 < 16) {
            const int sn = s + 3;
            MBAR_EXPECT(CTRL + p * 8, TXB);
            BULK_G2S(st,         pAh + (size_t)sn * 10240, 10240, CTRL + p * 8);
            BULK_G2S(st + 10240, pAl + (size_t)sn * 10240, 10240, CTRL + p * 8);
            BULK_G2S(st + 20480,          pBh + (size_t)sn * 17920, bBytes, CTRL + p * 8);
            BULK_G2S(st + 20480 + bBytes, pBl + (size_t)sn * 17920, bBytes, CTRL + p * 8);
        }
        p = (p == 2) ? 0 : p + 1;
    }
    __syncthreads();

    const float* bias = (z == 0) ? b0 : ((z == 1) ? b1 : b2);
    __nv_bfloat16* sH = reinterpret_cast<__nv_bfloat16*>(smem);   // [pp<104][m128]
    __nv_bfloat16* sL = sH + 13312;
#pragma unroll
    for (int mi = 0; mi < 2; mi++) {
        const int m0 = warpM * 32 + mi * 16 + (lane >> 2);
        const float bv0 = __ldg(bias + mt * 128 + m0);
        const float bv1 = __ldg(bias + mt * 128 + m0 + 8);
#pragma unroll
        for (int ni = 0; ni < 7; ni++) {
            const int p0 = warpN * 56 + ni * 8 + (lane & 3) * 2;
            if (p0 >= nvalid) continue;
            float v[4] = {c[mi][ni][0] + bv0, c[mi][ni][1] + bv0,
                          c[mi][ni][2] + bv1, c[mi][ni][3] + bv1};
#pragma unroll
            for (int q = 0; q < 4; q++) {
                const int pp = p0 + (q & 1), mm = m0 + (q < 2 ? 0 : 8);
                __nv_bfloat16 h = __float2bfloat16_rn(v[q]);
                sH[pp * 128 + mm] = h;
                sL[pp * 128 + mm] = __float2bfloat16_rn(v[q] - __bfloat162float(h));
            }
        }
    }
    __syncthreads();
    uint8_t* ohB = Oh + ((size_t)(z * 128 + b) * 16 + mt * 4) * 20480;
    uint8_t* olB = Ol + ((size_t)(z * 128 + b) * 16 + mt * 4) * 20480;
    const int tot = nvalid * 16;
    for (int g = tid; g < tot; g += 256) {
        int pp = g >> 4, o = g & 15, q = o >> 2, oo = o & 3;
        int pr = perm_px(nt * 104 + pp);
        uint32_t so = (pp * 128 + q * 32 + oo * 8) * 2;
        size_t dof = (size_t)q * 20480 + pr * 80 + oo * 16;
        *(uint4*)(ohB + dof) = *(uint4*)((uint8_t*)sH + so);
        *(uint4*)(olB + dof) = *(uint4*)((uint8_t*)sL + so);
    }
}

// ---- Gram GEMM, class-blocked --------------------------------------------------
__global__ __launch_bounds__(512, 1) void gemm_gram_kernel(
    const uint8_t* __restrict__ Fh, const uint8_t* __restrict__ Fl, float* __restrict__ G)
{
    extern __shared__ __align__(128) uint8_t smem[];
    const int tid = threadIdx.x;
    const int ct = blockIdx.x, b = blockIdx.y;
    const uint32_t sb = smem_u32(smem);
    const int warp = tid >> 5, lane = tid & 31;
    const int sub = warp & 3, grp = warp >> 2;
    const bool active = (sub < 3);
    const int pr = sub;
    const int cls = grp >> 1, wm = grp & 1;
    const int pa = (pr == 2) ? 1 : 0, pb = (pr == 0) ? 1 : 2;

    const uint32_t CTRL = sb + G_CTRL;
    if (tid == 0) { MBAR_INIT(CTRL, 1); MBAR_INIT(CTRL + 8, 1); }
    __syncthreads();

    size_t baseT[3];
#pragma unroll
    for (int t = 0; t < 3; t++)
        baseT[t] = ((size_t)t * 128 + b) * 327680 + (size_t)ct * 8000;

    if (tid == 0) {
#pragma unroll
        for (int s = 0; s < 2; s++) {
            const uint32_t st = sb + s * GSTAGE;
            MBAR_EXPECT(CTRL + s * 8, 48000);
#pragma unroll
            for (int t = 0; t < 3; t++) {
                BULK_G2S(st + t * 16000,        Fh + baseT[t] + (size_t)s * 20480, 8000, CTRL + s * 8);
                BULK_G2S(st + t * 16000 + 8000, Fl + baseT[t] + (size_t)s * 20480, 8000, CTRL + s * 8);
            }
        }
    }

    float c[2][7][4];
#pragma unroll
    for (int i = 0; i < 2; i++)
#pragma unroll
        for (int j = 0; j < 7; j++)
#pragma unroll
            for (int k = 0; k < 4; k++) c[i][j][k] = 0.f;

    int phF[2] = {0, 0};
    for (int s = 0; s < 16; s++) {
        const int p = s & 1;
        const uint32_t st = sb + p * GSTAGE;
        MBAR_WAIT(CTRL + p * 8, phF[p]); phF[p] ^= 1;

        if (active) {
            const uint32_t aBase = st + pa * 16000 + (cls * 50 + wm * 32 + (lane & 15)) * 80 + (lane & 16);
            const uint32_t bBase = st + pb * 16000 + (cls * 50 + (lane & 7)) * 80 + (lane & 8) * 2;
#pragma unroll
            for (int ks = 0; ks < 2; ks++) {
                const uint32_t kb = ks * 32;
                uint32_t afh[2][4], afl[2][4];
#pragma unroll
                for (int mi = 0; mi < 2; mi++) {
                    ldsm4(afh[mi], aBase + mi * 1280 + kb);
                    ldsm4(afl[mi], aBase + 8000 + mi * 1280 + kb);
                }
#pragma unroll
                for (int ni = 0; ni < 7; ni++) {
                    uint32_t bfh[2], bfl[2];
                    ldsm2(bfh, bBase + ni * 640 + kb);
                    ldsm2(bfl, bBase + 8000 + ni * 640 + kb);
#pragma unroll
                    for (int mi = 0; mi < 2; mi++) {
                        mma16816(c[mi][ni], afh[mi], bfh);
                        mma16816(c[mi][ni], afh[mi], bfl);
                        mma16816(c[mi][ni], afl[mi], bfh);
                    }
                }
            }
        }
        __syncthreads();
        if (tid == 0 && s + 2 < 16) {
            const int sn = s + 2;
            MBAR_EXPECT(CTRL + p * 8, 48000);
#pragma unroll
            for (int t = 0; t < 3; t++) {
                BULK_G2S(st + t * 16000,        Fh + baseT[t] + (size_t)sn * 20480, 8000, CTRL + p * 8);
                BULK_G2S(st + t * 16000 + 8000, Fl + baseT[t] + (size_t)sn * 20480, 8000, CTRL + p * 8);
            }
        }
    }

    if (active) {
        float* Gb = G + ((size_t)pr * 128 + b) * 10400 + (ct * 2 + cls) * 2600;
#pragma unroll
        for (int mi = 0; mi < 2; mi++) {
            const int m = wm * 32 + mi * 16 + (lane >> 2);
#pragma unroll
            for (int ni = 0; ni < 7; ni++) {
                const int n0 = ni * 8 + (lane & 3) * 2;
                if (n0 >= 50) continue;
                if (m < 50)
                    *(float2*)(Gb + m * 52 + n0) = make_float2(c[mi][ni][0], c[mi][ni][1]);
                if (m + 8 < 50)
                    *(float2*)(Gb + (m + 8) * 52 + n0) = make_float2(c[mi][ni][2], c[mi][ni][3]);
            }
        }
    }
}

// ---- split heads: y<3 -> corr pair y, y>=3 -> cat slab (y-3). Partial sums. --
__global__ __launch_bounds__(256)
void heads_kernel(const float* __restrict__ Gram, const float* __restrict__ Wcorr,
                  float* __restrict__ corrpart,
                  const uint8_t* __restrict__ Fh, const uint8_t* __restrict__ Fl,
                  const float* __restrict__ Wcat, float* __restrict__ catpart)
{
    extern __shared__ float sh[];
    const int b = blockIdx.x, tid = threadIdx.x;
    const int y = tid / 20, x = tid - y * 20;
    float acc0 = 0.f, acc1 = 0.f, acc2 = 0.f;

    if (blockIdx.y < 3) {
        const int pair = blockIdx.y;
        float* sG = sh;             // 10400 floats: [cls4][50][52]
        float* sW = sh + 10400;     // 11907
        const float4* G4 = reinterpret_cast<const float4*>(Gram + ((size_t)pair * 128 + b) * 10400);
        float4* sG4 = reinterpret_cast<float4*>(sG);
        for (int i = tid; i < 2600; i += 256) sG4[i] = G4[i];
        for (int i = tid; i < 11907; i += 256) {
            int o = i / 3969, r = i - o * 3969;
            sW[i] = Wcorr[o * 11907 + pair * 3969 + r];
        }
        __syncthreads();
        if (tid < NPIX) {
            for (int ky = 0; ky < 3; ky++) {
                int sy = y + ky - 1;
                if ((unsigned)sy >= 10u) continue;
                for (int kx = 0; kx < 3; kx++) {
                    int sx = x + kx - 1;
                    if ((unsigned)sx >= 20u) continue;
                    const int cc = (sy & 1) * 2 + (sx & 1);
                    const int i1 = (sy >> 1) * 10 + (sx >> 1);
                    const float* gblk = sG + cc * 2600 + i1 * 52;
                    const int tap = ky * 3 + kx;
                    const int dyi0 = (21 - sy) >> 1, dxi0 = (21 - sx) >> 1;
                    for (int iy = 0; iy < 5; iy++) {
                        const float* grow = gblk + iy * 10;
                        const float* wrow = sW + ((dyi0 + iy) * 21 + dxi0) * 9 + tap;
#pragma unroll
                        for (int ix = 0; ix < 10; ix++) {
                            float g = grow[ix] * (1.f / 512.f);
                            float v = g > 0.f ? g : 0.1f * g;
                            acc0 += v * wrow[ix * 9];
                            acc1 += v * wrow[3969 + ix * 9];
                            acc2 += v * wrow[7938 + ix * 9];
                        }
                    }
                }
            }
            float* cp = corrpart + ((size_t)pair * 128 + b) * 600;
            cp[tid] = acc0; cp[200 + tid] = acc1; cp[400 + tid] = acc2;
        }
    } else {
        const int ch = blockIdx.y - 3;       // slab 0..15 (32 channels)
        float* sF = sh;             // [(t*200+p)*36 + c], 21600 floats
        float* sW = sh + 21600;     // 2592: [o3][t3][tap9][c32]
        for (int g = tid; g < 2400; g += 256) {
            int t = g / 800, r = g - t * 800, p = r >> 2, g8 = r & 3;
            int pr = perm_px(p);
            size_t base = (((size_t)t * 128 + b) * 16 + ch) * 20480 + pr * 80 + g8 * 16;
            uint4 vh = *(const uint4*)(Fh + base);
            uint4 vl = *(const uint4*)(Fl + base);
            float* d = &sF[(t * 200 + p) * 36 + g8 * 8];
            float2 a0 = bf2f(vh.x), c0 = bf2f(vl.x); d[0] = a0.x + c0.x; d[1] = a0.y + c0.y;
            float2 a1 = bf2f(vh.y), c1 = bf2f(vl.y); d[2] = a1.x + c1.x; d[3] = a1.y + c1.y;
            float2 a2 = bf2f(vh.z), c2 = bf2f(vl.z); d[4] = a2.x + c2.x; d[5] = a2.y + c2.y;
            float2 a3 = bf2f(vh.w), c3 = bf2f(vl.w); d[6] = a3.x + c3.x; d[7] = a3.y + c3.y;
        }
        for (int i = tid; i < 2592; i += 256) {
            int o = i / 864, r = i - o * 864, t = r / 288, r2 = r - t * 288;
            int tap = r2 >> 5, cch = r2 & 31;
            sW[i] = Wcat[(size_t)(o * 1536 + t * 512 + ch * 32 + cch) * 9 + tap];
        }
        __syncthreads();
        if (tid < NPIX) {
            for (int t = 0; t < 3; t++)
                for (int ky = 0; ky < 3; ky++) {
                    int sy = y + ky - 1;
                    if ((unsigned)sy >= 10u) continue;
                    for (int kx = 0; kx < 3; kx++) {
                        int sx = x + kx - 1;
                        if ((unsigned)sx >= 20u) continue;
                        const float4* v4 = reinterpret_cast<const float4*>(sF + (t * 200 + sy * 20 + sx) * 36);
                        int tap = ky * 3 + kx;
                        const float4* w0 = reinterpret_cast<const float4*>(sW + (t * 9 + tap) * 32);
                        const float4* w1 = reinterpret_cast<const float4*>(sW + 864 + (t * 9 + tap) * 32);
                        const float4* w2 = reinterpret_cast<const float4*>(sW + 1728 + (t * 9 + tap) * 32);
#pragma unroll
                        for (int c4 = 0; c4 < 8; c4++) {
                            float4 v = v4[c4];
                            float4 a = w0[c4], bq = w1[c4], cq = w2[c4];
                            acc0 += v.x * a.x + v.y * a.y + v.z * a.z + v.w * a.w;
                            acc1 += v.x * bq.x + v.y * bq.y + v.z * bq.z + v.w * bq.w;
                            acc2 += v.x * cq.x + v.y * cq.y + v.z * cq.z + v.w * cq.w;
                        }
                    }
                }
            float* cp = catpart + ((size_t)ch * 128 + b) * 600;
            cp[tid] = acc0; cp[200 + tid] = acc1; cp[400 + tid] = acc2;
        }
    }
}

// ---- MLP heads + final linear (folds partials + bias + relu) ------------------
__global__ __launch_bounds__(256)
void mlp_kernel(const float* __restrict__ corrpart, const float* __restrict__ catpart,
                const float* __restrict__ bcorr, const float* __restrict__ bcat,
                const float* __restrict__ cf_w1, const float* __restrict__ cf_b1,
                const float* __restrict__ cf_w2, const float* __restrict__ cf_b2,
                const float* __restrict__ ccf_w1, const float* __restrict__ ccf_b1,
                const float* __restrict__ ccf_w2, const float* __restrict__ ccf_b2,
                const float* __restrict__ Wout, const float* __restrict__ bout,
                float* __restrict__ out)
{
    __shared__ float sx[600];
    __shared__ float h1[256];
    __shared__ float h2[2][128];
    const int b = blockIdx.x, tid = threadIdx.x;

    for (int path = 0; path < 2; path++) {
        const float* w1 = path == 0 ? cf_w1 : ccf_w1;
        const float* b1 = path == 0 ? cf_b1 : ccf_b1;
        const float* w2 = path == 0 ? cf_w2 : ccf_w2;
        const float* b2 = path == 0 ? cf_b2 : ccf_b2;
        __syncthreads();
        if (path == 0) {
            for (int i = tid; i < 600; i += 256) {
                float v = bcorr[i / 200];
#pragma unroll
                for (int pr = 0; pr < 3; pr++)
                    v += corrpart[((size_t)pr * 128 + b) * 600 + i];
                sx[i] = fmaxf(v, 0.f);
            }
        } else {
            for (int i = tid; i < 600; i += 256) {
                float v = bcat[i / 200];
#pragma unroll
                for (int ch = 0; ch < 16; ch++)
                    v += catpart[((size_t)ch * 128 + b) * 600 + i];
                sx[i] = v;
            }
        }
        __syncthreads();
        {
            float s = b1[tid];
            const float4* wr = reinterpret_cast<const float4*>(w1 + (size_t)tid * 600);
#pragma unroll 4
            for (int k = 0; k < 150; k++) {
                float4 w = wr[k];
                s += w.x * sx[4*k] + w.y * sx[4*k+1] + w.z * sx[4*k+2] + w.w * sx[4*k+3];
            }
            h1[tid] = fmaxf(s, 0.f);
        }
        __syncthreads();
        if (tid < 128) {
            float s = b2[tid];
            const float4* wr = reinterpret_cast<const float4*>(w2 + (size_t)tid * 256);
#pragma unroll 4
            for (int k = 0; k < 64; k++) {
                float4 w = wr[k];
                s += w.x * h1[4*k] + w.y * h1[4*k+1] + w.z * h1[4*k+2] + w.w * h1[4*k+3];
            }
            h2[path][tid] = fmaxf(s, 0.f);
        }
    }
    __syncthreads();
    if (tid < 2) {
        float s = bout[tid];
        const float* wr = Wout + tid * 256;
        for (int i = 0; i < 128; i++)
            s += h2[0][i] * wr[i] + h2[1][i] * wr[128 + i];
        out[b * 2 + tid] = s;
    }
}

// ---- launch -------------------------------------------------------------------
extern "C" void kernel_launch(void* const* d_in, const int* in_sizes, int n_in,
                              void* d_out, int out_size)
{
    (void)in_sizes; (void)n_in; (void)out_size;
    const float* feat1 = (const float*)d_in[0];
    const float* feat2 = (const float*)d_in[1];
    const float* feat3 = (const float*)d_in[2];
    const float* Wa = (const float*)d_in[3];   const float* ba = (const float*)d_in[4];
    const float* Wb = (const float*)d_in[5];   const float* bb = (const float*)d_in[6];
    const float* Wc = (const float*)d_in[7];   const float* bc = (const float*)d_in[8];
    const float* Wcorr = (const float*)d_in[9];  const float* bcorr = (const float*)d_in[10];
    const float* Wcat = (const float*)d_in[11];  const float* bcat = (const float*)d_in[12];
    const float* cf_w1 = (const float*)d_in[13]; const float* cf_b1 = (const float*)d_in[14];
    const float* cf_w2 = (const float*)d_in[15]; const float* cf_b2 = (const float*)d_in[16];
    const float* ccf_w1 = (const float*)d_in[17]; const float* ccf_b1 = (const float*)d_in[18];
    const float* ccf_w2 = (const float*)d_in[19]; const float* ccf_b2 = (const float*)d_in[20];
    const float* Wout = (const float*)d_in[21];  const float* bout = (const float*)d_in[22];

    uint8_t *wh, *wl, *fih, *fil, *foh, *fol;
    float *G, *cvp, *tvp;
    cudaGetSymbolAddress((void**)&wh,  g_wh);
    cudaGetSymbolAddress((void**)&wl,  g_wl);
    cudaGetSymbolAddress((void**)&fih, g_finh);
    cudaGetSymbolAddress((void**)&fil, g_finl);
    cudaGetSymbolAddress((void**)&foh, g_fouth);
    cudaGetSymbolAddress((void**)&fol, g_foutl);
    cudaGetSymbolAddress((void**)&G,   g_gram);
    cudaGetSymbolAddress((void**)&cvp, g_corrpart);
    cudaGetSymbolAddress((void**)&tvp, g_catpart);

    cudaFuncSetAttribute(gemm_conv_kernel, cudaFuncAttributeMaxDynamicSharedMemorySize, CONV_SMEM);
    cudaFuncSetAttribute(gemm_gram_kernel, cudaFuncAttributeMaxDynamicSharedMemorySize, GRAM_SMEM);
    cudaFuncSetAttribute(heads_kernel, cudaFuncAttributeMaxDynamicSharedMemorySize, HEADS_SMEM);

    convert_feat_kernel<<<dim3(128, 3), 256>>>(feat1, feat2, feat3, fih, fil,
                                               Wa, Wb, Wc, wh, wl);

    gemm_conv_kernel<<<dim3(8, 128, 3), 256, CONV_SMEM>>>(
        wh, wl, fih, fil, ba, bb, bc, foh, fol);

    gemm_gram_kernel<<<dim3(2, 128), 512, GRAM_SMEM>>>(foh, fol, G);

    // split heads: 3 corr-pair blocks + 16 cat-slab blocks per batch
    heads_kernel<<<dim3(128, 19), 256, HEADS_SMEM>>>(G, Wcorr, cvp,
                                                     foh, fol, Wcat, tvp);

    mlp_kernel<<<128, 256>>>(cvp, tvp, bcorr, bcat,
                             cf_w1, cf_b1, cf_w2, cf_b2,
                             ccf_w1, ccf_b1, ccf_w2, ccf_b2, Wout, bout, (float*)d_out);
}

// round 13
// speedup vs baseline: 1.7830x; 1.0033x over previous
#include <cuda_runtime.h>
#include <cuda_bf16.h>
#include <cstdint>
#include <cstddef>

#define NPIX 200

// ---- gmem scratch (static; zero-initialized at load — pad rows rely on it) --
__device__ __align__(16) uint8_t g_wh[3u*4*16*10240];          //  2 MB
__device__ __align__(16) uint8_t g_wl[3u*4*16*10240];
__device__ __align__(16) uint8_t g_finh[3u*128*16*17920];      // 110 MB
__device__ __align__(16) uint8_t g_finl[3u*128*16*17920];
__device__ __align__(16) uint8_t g_fouth[3u*128*16*20480];     // 126 MB (class-major rows)
__device__ __align__(16) uint8_t g_foutl[3u*128*16*20480];
__device__ float g_gram[3u*128*10400];                         //  16 MB: [pair][b][cls4][50][52]
__device__ float g_corrpart[3*128*600];                        // per-pair partials (o-sliced)
__device__ float g_catpart[48*128*600];                        // per-(tensor,slab) partials

// conv smem: 3 stages of 37120: AH(10240) AL(10240) B(2x up to 8320); ctrl after.
#define CSTAGE 37120
#define C_CTRL 111360
#define CONV_SMEM (C_CTRL + 24)
// gram smem: 2 stages of 49152 (3 tensors x [H8000 L8000] + ldsm overrun pad)
#define GSTAGE 49152
#define G_CTRL (2*GSTAGE)
#define GRAM_SMEM (G_CTRL + 16)
// right-sized heads smem
#define CORR_SMEM ((10400 + 3969) * 4)   // 57476
#define CAT_SMEM  ((7200 + 864) * 4)     // 32256

__device__ __forceinline__ uint32_t smem_u32(const void* p) {
    uint32_t r;
    asm("{ .reg .u64 t; cvta.to.shared.u64 t, %1; cvt.u32.u64 %0, t; }" : "=r"(r) : "l"(p));
    return r;
}
#define MBAR_INIT(a, c) asm volatile("mbarrier.init.shared.b64 [%0], %1;" :: "r"(a), "r"(c) : "memory")
#define MBAR_EXPECT(a, n) asm volatile("mbarrier.arrive.expect_tx.shared.b64 _, [%0], %1;" :: "r"(a), "r"(n) : "memory")
#define MBAR_WAIT(a, ph) \
    asm volatile("{\n\t.reg .pred P;\n\tW_%=:\n\t" \
                 "mbarrier.try_wait.parity.acquire.cta.shared::cta.b64 P, [%0], %1, 0x989680;\n\t" \
                 "@!P bra W_%=;\n\t}" :: "r"(a), "r"(ph) : "memory")
#define BULK_G2S(dst, src, bytes, mbar) \
    asm volatile("cp.async.bulk.shared::cluster.global.mbarrier::complete_tx::bytes [%0], [%1], %2, [%3];" \
                 :: "r"(dst), "l"(src), "r"(bytes), "r"(mbar) : "memory")

__device__ __forceinline__ void ldsm4(uint32_t* r, uint32_t a) {
    asm volatile("ldmatrix.sync.aligned.m8n8.x4.shared.b16 {%0,%1,%2,%3}, [%4];"
        : "=r"(r[0]), "=r"(r[1]), "=r"(r[2]), "=r"(r[3]) : "r"(a));
}
__device__ __forceinline__ void ldsm2(uint32_t* r, uint32_t a) {
    asm volatile("ldmatrix.sync.aligned.m8n8.x2.shared.b16 {%0,%1}, [%2];"
        : "=r"(r[0]), "=r"(r[1]) : "r"(a));
}
__device__ __forceinline__ void mma16816(float* c, const uint32_t* a, const uint32_t* b) {
    asm volatile("mma.sync.aligned.m16n8k16.row.col.f32.bf16.bf16.f32 "
        "{%0,%1,%2,%3}, {%4,%5,%6,%7}, {%8,%9}, {%0,%1,%2,%3};"
        : "+f"(c[0]), "+f"(c[1]), "+f"(c[2]), "+f"(c[3])
        : "r"(a[0]), "r"(a[1]), "r"(a[2]), "r"(a[3]), "r"(b[0]), "r"(b[1]));
}
__device__ __forceinline__ void pack8(const float* v, uint4& h, uint4& l) {
    __align__(16) __nv_bfloat16 hb[8], lb[8];
#pragma unroll
    for (int u = 0; u < 8; u++) {
        hb[u] = __float2bfloat16_rn(v[u]);
        lb[u] = __float2bfloat16_rn(v[u] - __bfloat162float(hb[u]));
    }
    h = *reinterpret_cast<uint4*>(hb);
    l = *reinterpret_cast<uint4*>(lb);
}
__device__ __forceinline__ float2 bf2f(uint32_t u) {
    __nv_bfloat162 h = *reinterpret_cast<__nv_bfloat162*>(&u);
    return __bfloat1622float2(h);
}
__device__ __forceinline__ int perm_px(int p) {
    int y = p / 20, x = p - y * 20;
    return ((y & 1) * 2 + (x & 1)) * 50 + (y >> 1) * 10 + (x >> 1);
}

// ---- feats [b][c][p] -> transposed slab layout; also converts weights -------
__global__ __launch_bounds__(256) void convert_feat_kernel(
    const float* __restrict__ f1, const float* __restrict__ f2, const float* __restrict__ f3,
    uint8_t* __restrict__ oh, uint8_t* __restrict__ ol,
    const float* __restrict__ Wa, const float* __restrict__ Wb, const float* __restrict__ Wc,
    uint8_t* __restrict__ owh, uint8_t* __restrict__ owl)
{
    __shared__ float s[32 * 201];
    const int b = blockIdx.x, t = blockIdx.y, tid = threadIdx.x;

    {
        int idx = (t * 128 + b) * 256 + tid;
        int tt = idx / 32768, rr = idx - tt * 32768;
        int m = rr >> 6, g8 = rr & 63;
        const float* W = (tt == 0) ? Wa : ((tt == 1) ? Wb : Wc);
        float v[8];
#pragma unroll
        for (int u = 0; u < 8; u++) v[u] = W[m * 512 + g8 * 8 + u];
        uint4 vh, vl; pack8(v, vh, vl);
        int mt = m >> 7, mr = m & 127, slab = g8 >> 2, c8 = g8 & 3;
        size_t off = ((size_t)(tt * 4 + mt) * 16 + slab) * 10240 + mr * 80 + c8 * 16;
        *(uint4*)(owh + off) = vh;
        *(uint4*)(owl + off) = vl;
    }

    const float* F = ((t == 0) ? f1 : ((t == 1) ? f2 : f3)) + (size_t)b * 102400;
    uint8_t* obh = oh + ((size_t)t * 128 + b) * 286720;
    uint8_t* obl = ol + ((size_t)t * 128 + b) * 286720;
    for (int c = 0; c < 16; c++) {
        __syncthreads();
        for (int e = tid; e < 32 * 200; e += 256) {
            int kk = e / 200, n = e - kk * 200;
            s[kk * 201 + n] = F[(size_t)(c * 32 + kk) * 200 + n];
        }
        __syncthreads();
        for (int i = tid; i < 800; i += 256) {
            int p = i >> 2, g8 = i & 3;
            float v[8];
#pragma unroll
            for (int u = 0; u < 8; u++) v[u] = s[(g8 * 8 + u) * 201 + p];
            uint4 vh, vl; pack8(v, vh, vl);
            size_t off = (size_t)c * 17920 + p * 80 + g8 * 16;
            *(uint4*)(obh + off) = vh;
            *(uint4*)(obl + off) = vl;
        }
    }
}

// ---- conv1x1 GEMM: hi/lo bf16 mma.sync, 8 warps (4Mx2N), 3-stage pipeline ----
__global__ __launch_bounds__(256, 2) void gemm_conv_kernel(
    const uint8_t* __restrict__ Ah, const uint8_t* __restrict__ Al,
    const uint8_t* __restrict__ Bh, const uint8_t* __restrict__ Bl,
    const float* __restrict__ b0, const float* __restrict__ b1, const float* __restrict__ b2,
    uint8_t* __restrict__ Oh, uint8_t* __restrict__ Ol)
{
    extern __shared__ __align__(128) uint8_t smem[];
    const int tid = threadIdx.x;
    const int mt = blockIdx.x >> 1, nt = blockIdx.x & 1;
    const int b = blockIdx.y, z = blockIdx.z;
    const uint32_t sb = smem_u32(smem);
    const int warp = tid >> 5, lane = tid & 31;
    const int warpM = warp & 3, warpN = warp >> 2;
    const int nvalid = nt ? 96 : 104;
    const uint32_t bBytes = nvalid * 80;
    const uint32_t TXB = 20480 + 2 * bBytes;

    const uint32_t CTRL = sb + C_CTRL;
    if (tid == 0) {
#pragma unroll
        for (int p = 0; p < 3; p++) MBAR_INIT(CTRL + p * 8, 1);
    }
    __syncthreads();

    const uint8_t* pAh = Ah + (size_t)(z * 4 + mt) * 163840;
    const uint8_t* pAl = Al + (size_t)(z * 4 + mt) * 163840;
    const uint8_t* pBh = Bh + (size_t)(z * 128 + b) * 286720 + (size_t)nt * 8320;
    const uint8_t* pBl = Bl + (size_t)(z * 128 + b) * 286720 + (size_t)nt * 8320;

    if (tid == 0) {
#pragma unroll
        for (int s = 0; s < 3; s++) {
            const uint32_t st = sb + s * CSTAGE;
            MBAR_EXPECT(CTRL + s * 8, TXB);
            BULK_G2S(st,         pAh + (size_t)s * 10240, 10240, CTRL + s * 8);
            BULK_G2S(st + 10240, pAl + (size_t)s * 10240, 10240, CTRL + s * 8);
            BULK_G2S(st + 20480,          pBh + (size_t)s * 17920, bBytes, CTRL + s * 8);
            BULK_G2S(st + 20480 + bBytes, pBl + (size_t)s * 17920, bBytes, CTRL + s * 8);
        }
    }

    float c[2][7][4];
#pragma unroll
    for (int i = 0; i < 2; i++)
#pragma unroll
        for (int j = 0; j < 7; j++)
#pragma unroll
            for (int k = 0; k < 4; k++) c[i][j][k] = 0.f;

    int phF[3] = {0, 0, 0};
    int p = 0;
    for (int s = 0; s < 16; s++) {
        const uint32_t st = sb + p * CSTAGE;
        MBAR_WAIT(CTRL + p * 8, phF[p]); phF[p] ^= 1;

        const uint32_t aBase = st + (warpM * 32 + (lane & 15)) * 80 + (lane & 16);
        const uint32_t bBase = st + 20480 + (warpN * 56 + (lane & 7)) * 80 + (lane & 8) * 2;
#pragma unroll
        for (int ks = 0; ks < 2; ks++) {
            const uint32_t kb = ks * 32;
            uint32_t afh[2][4], afl[2][4];
#pragma unroll
            for (int mi = 0; mi < 2; mi++) {
                ldsm4(afh[mi], aBase + mi * 1280 + kb);
                ldsm4(afl[mi], aBase + 10240 + mi * 1280 + kb);
            }
#pragma unroll
            for (int ni = 0; ni < 7; ni++) {
                if (warpN * 56 + ni * 8 >= nvalid) continue;
                uint32_t bfh[2], bfl[2];
                ldsm2(bfh, bBase + ni * 640 + kb);
                ldsm2(bfl, bBase + ni * 640 + kb + bBytes);
#pragma unroll
                for (int mi = 0; mi < 2; mi++) {
                    mma16816(c[mi][ni], afh[mi], bfh);
                    mma16816(c[mi][ni], afh[mi], bfl);
                    mma16816(c[mi][ni], afl[mi], bfh);
                }
            }
        }
        __syncthreads();
        if (tid == 0 && s + 3 < 16) {
            const int sn = s + 3;
            MBAR_EXPECT(CTRL + p * 8, TXB);
            BULK_G2S(st,         pAh + (size_t)sn * 10240, 10240, CTRL + p * 8);
            BULK_G2S(st + 10240, pAl + (size_t)sn * 10240, 10240, CTRL + p * 8);
            BULK_G2S(st + 20480,          pBh + (size_t)sn * 17920, bBytes, CTRL + p * 8);
            BULK_G2S(st + 20480 + bBytes, pBl + (size_t)sn * 17920, bBytes, CTRL + p * 8);
        }
        p = (p == 2) ? 0 : p + 1;
    }
    __syncthreads();

    const float* bias = (z == 0) ? b0 : ((z == 1) ? b1 : b2);
    __nv_bfloat16* sH = reinterpret_cast<__nv_bfloat16*>(smem);   // [pp<104][m128]
    __nv_bfloat16* sL = sH + 13312;
#pragma unroll
    for (int mi = 0; mi < 2; mi++) {
        const int m0 = warpM * 32 + mi * 16 + (lane >> 2);
        const float bv0 = __ldg(bias + mt * 128 + m0);
        const float bv1 = __ldg(bias + mt * 128 + m0 + 8);
#pragma unroll
        for (int ni = 0; ni < 7; ni++) {
            const int p0 = warpN * 56 + ni * 8 + (lane & 3) * 2;
            if (p0 >= nvalid) continue;
            float v[4] = {c[mi][ni][0] + bv0, c[mi][ni][1] + bv0,
                          c[mi][ni][2] + bv1, c[mi][ni][3] + bv1};
#pragma unroll
            for (int q = 0; q < 4; q++) {
                const int pp = p0 + (q & 1), mm = m0 + (q < 2 ? 0 : 8);
                __nv_bfloat16 h = __float2bfloat16_rn(v[q]);
                sH[pp * 128 + mm] = h;
                sL[pp * 128 + mm] = __float2bfloat16_rn(v[q] - __bfloat162float(h));
            }
        }
    }
    __syncthreads();
    uint8_t* ohB = Oh + ((size_t)(z * 128 + b) * 16 + mt * 4) * 20480;
    uint8_t* olB = Ol + ((size_t)(z * 128 + b) * 16 + mt * 4) * 20480;
    const int tot = nvalid * 16;
    for (int g = tid; g < tot; g += 256) {
        int pp = g >> 4, o = g & 15, q = o >> 2, oo = o & 3;
        int pr = perm_px(nt * 104 + pp);
        uint32_t so = (pp * 128 + q * 32 + oo * 8) * 2;
        size_t dof = (size_t)q * 20480 + pr * 80 + oo * 16;
        *(uint4*)(ohB + dof) = *(uint4*)((uint8_t*)sH + so);
        *(uint4*)(olB + dof) = *(uint4*)((uint8_t*)sL + so);
    }
}

// ---- Gram GEMM, class-blocked --------------------------------------------------
__global__ __launch_bounds__(512, 1) void gemm_gram_kernel(
    const uint8_t* __restrict__ Fh, const uint8_t* __restrict__ Fl, float* __restrict__ G)
{
    extern __shared__ __align__(128) uint8_t smem[];
    const int tid = threadIdx.x;
    const int ct = blockIdx.x, b = blockIdx.y;
    const uint32_t sb = smem_u32(smem);
    const int warp = tid >> 5, lane = tid & 31;
    const int sub = warp & 3, grp = warp >> 2;
    const bool active = (sub < 3);
    const int pr = sub;
    const int cls = grp >> 1, wm = grp & 1;
    const int pa = (pr == 2) ? 1 : 0, pb = (pr == 0) ? 1 : 2;

    const uint32_t CTRL = sb + G_CTRL;
    if (tid == 0) { MBAR_INIT(CTRL, 1); MBAR_INIT(CTRL + 8, 1); }
    __syncthreads();

    size_t baseT[3];
#pragma unroll
    for (int t = 0; t < 3; t++)
        baseT[t] = ((size_t)t * 128 + b) * 327680 + (size_t)ct * 8000;

    if (tid == 0) {
#pragma unroll
        for (int s = 0; s < 2; s++) {
            const uint32_t st = sb + s * GSTAGE;
            MBAR_EXPECT(CTRL + s * 8, 48000);
#pragma unroll
            for (int t = 0; t < 3; t++) {
                BULK_G2S(st + t * 16000,        Fh + baseT[t] + (size_t)s * 20480, 8000, CTRL + s * 8);
                BULK_G2S(st + t * 16000 + 8000, Fl + baseT[t] + (size_t)s * 20480, 8000, CTRL + s * 8);
            }
        }
    }

    float c[2][7][4];
#pragma unroll
    for (int i = 0; i < 2; i++)
#pragma unroll
        for (int j = 0; j < 7; j++)
#pragma unroll
            for (int k = 0; k < 4; k++) c[i][j][k] = 0.f;

    int phF[2] = {0, 0};
    for (int s = 0; s < 16; s++) {
        const int p = s & 1;
        const uint32_t st = sb + p * GSTAGE;
        MBAR_WAIT(CTRL + p * 8, phF[p]); phF[p] ^= 1;

        if (active) {
            const uint32_t aBase = st + pa * 16000 + (cls * 50 + wm * 32 + (lane & 15)) * 80 + (lane & 16);
            const uint32_t bBase = st + pb * 16000 + (cls * 50 + (lane & 7)) * 80 + (lane & 8) * 2;
#pragma unroll
            for (int ks = 0; ks < 2; ks++) {
                const uint32_t kb = ks * 32;
                uint32_t afh[2][4], afl[2][4];
#pragma unroll
                for (int mi = 0; mi < 2; mi++) {
                    ldsm4(afh[mi], aBase + mi * 1280 + kb);
                    ldsm4(afl[mi], aBase + 8000 + mi * 1280 + kb);
                }
#pragma unroll
                for (int ni = 0; ni < 7; ni++) {
                    uint32_t bfh[2], bfl[2];
                    ldsm2(bfh, bBase + ni * 640 + kb);
                    ldsm2(bfl, bBase + 8000 + ni * 640 + kb);
#pragma unroll
                    for (int mi = 0; mi < 2; mi++) {
                        mma16816(c[mi][ni], afh[mi], bfh);
                        mma16816(c[mi][ni], afh[mi], bfl);
                        mma16816(c[mi][ni], afl[mi], bfh);
                    }
                }
            }
        }
        __syncthreads();
        if (tid == 0 && s + 2 < 16) {
            const int sn = s + 2;
            MBAR_EXPECT(CTRL + p * 8, 48000);
#pragma unroll
            for (int t = 0; t < 3; t++) {
                BULK_G2S(st + t * 16000,        Fh + baseT[t] + (size_t)sn * 20480, 8000, CTRL + p * 8);
                BULK_G2S(st + t * 16000 + 8000, Fl + baseT[t] + (size_t)sn * 20480, 8000, CTRL + p * 8);
            }
        }
    }

    if (active) {
        float* Gb = G + ((size_t)pr * 128 + b) * 10400 + (ct * 2 + cls) * 2600;
#pragma unroll
        for (int mi = 0; mi < 2; mi++) {
            const int m = wm * 32 + mi * 16 + (lane >> 2);
#pragma unroll
            for (int ni = 0; ni < 7; ni++) {
                const int n0 = ni * 8 + (lane & 3) * 2;
                if (n0 >= 50) continue;
                if (m < 50)
                    *(float2*)(Gb + m * 52 + n0) = make_float2(c[mi][ni][0], c[mi][ni][1]);
                if (m + 8 < 50)
                    *(float2*)(Gb + (m + 8) * 52 + n0) = make_float2(c[mi][ni][2], c[mi][ni][3]);
            }
        }
    }
}

// ---- corr head: grid (128, 9) = (b, pair*3+o). Each block: one pair, one out.
__global__ __launch_bounds__(256)
void corr_kernel(const float* __restrict__ Gram, const float* __restrict__ Wcorr,
                 float* __restrict__ corrpart)
{
    extern __shared__ float sh[];
    float* sG = sh;            // 10400: [cls4][50][52]
    float* sW = sh + 10400;    // 3969
    const int b = blockIdx.x;
    const int pair = blockIdx.y / 3, o = blockIdx.y - pair * 3;
    const int tid = threadIdx.x;
    const int y = tid / 20, x = tid - y * 20;

    const float4* G4 = reinterpret_cast<const float4*>(Gram + ((size_t)pair * 128 + b) * 10400);
    float4* sG4 = reinterpret_cast<float4*>(sG);
    for (int i = tid; i < 2600; i += 256) sG4[i] = G4[i];
    const float* Wsrc = Wcorr + o * 11907 + pair * 3969;
    for (int i = tid; i < 3969; i += 256) sW[i] = Wsrc[i];
    __syncthreads();

    if (tid < NPIX) {
        float acc = 0.f;
        for (int ky = 0; ky < 3; ky++) {
            int sy = y + ky - 1;
            if ((unsigned)sy >= 10u) continue;
            for (int kx = 0; kx < 3; kx++) {
                int sx = x + kx - 1;
                if ((unsigned)sx >= 20u) continue;
                const int cc = (sy & 1) * 2 + (sx & 1);
                const int i1 = (sy >> 1) * 10 + (sx >> 1);
                const float* gblk = sG + cc * 2600 + i1 * 52;
                const int tap = ky * 3 + kx;
                const int dyi0 = (21 - sy) >> 1, dxi0 = (21 - sx) >> 1;
                for (int iy = 0; iy < 5; iy++) {
                    const float* grow = gblk + iy * 10;
                    const float* wrow = sW + ((dyi0 + iy) * 21 + dxi0) * 9 + tap;
#pragma unroll
                    for (int ix = 0; ix < 10; ix++) {
                        float g = grow[ix] * (1.f / 512.f);
                        float v = g > 0.f ? g : 0.1f * g;
                        acc += v * wrow[ix * 9];
                    }
                }
            }
        }
        corrpart[((size_t)pair * 128 + b) * 600 + o * 200 + tid] = acc;
    }
}

// ---- cat head: grid (128, 48) = (b, t*16+ch). One tensor, one 32-ch slab. ----
__global__ __launch_bounds__(256)
void cat_kernel(const uint8_t* __restrict__ Fh, const uint8_t* __restrict__ Fl,
                const float* __restrict__ Wcat, float* __restrict__ catpart)
{
    extern __shared__ float sh[];
    float* sF = sh;            // 200 x 36 (32 ch + pad)
    float* sW = sh + 7200;     // 864: [o3][tap9][c32]
    const int b = blockIdx.x;
    const int t = blockIdx.y / 16, ch = blockIdx.y - t * 16;
    const int tid = threadIdx.x;
    const int y = tid / 20, x = tid - y * 20;

    for (int g = tid; g < 800; g += 256) {
        int p = g >> 2, g8 = g & 3;
        int pr = perm_px(p);
        size_t base = (((size_t)t * 128 + b) * 16 + ch) * 20480 + pr * 80 + g8 * 16;
        uint4 vh = *(const uint4*)(Fh + base);
        uint4 vl = *(const uint4*)(Fl + base);
        float* d = &sF[p * 36 + g8 * 8];
        float2 a0 = bf2f(vh.x), c0 = bf2f(vl.x); d[0] = a0.x + c0.x; d[1] = a0.y + c0.y;
        float2 a1 = bf2f(vh.y), c1 = bf2f(vl.y); d[2] = a1.x + c1.x; d[3] = a1.y + c1.y;
        float2 a2 = bf2f(vh.z), c2 = bf2f(vl.z); d[4] = a2.x + c2.x; d[5] = a2.y + c2.y;
        float2 a3 = bf2f(vh.w), c3 = bf2f(vl.w); d[6] = a3.x + c3.x; d[7] = a3.y + c3.y;
    }
    for (int i = tid; i < 864; i += 256) {
        int o = i / 288, r = i - o * 288;
        int tap = r >> 5, cch = r & 31;
        sW[i] = Wcat[(size_t)(o * 1536 + t * 512 + ch * 32 + cch) * 9 + tap];
    }
    __syncthreads();

    if (tid < NPIX) {
        float acc0 = 0.f, acc1 = 0.f, acc2 = 0.f;
        for (int ky = 0; ky < 3; ky++) {
            int sy = y + ky - 1;
            if ((unsigned)sy >= 10u) continue;
            for (int kx = 0; kx < 3; kx++) {
                int sx = x + kx - 1;
                if ((unsigned)sx >= 20u) continue;
                const float4* v4 = reinterpret_cast<const float4*>(sF + (sy * 20 + sx) * 36);
                int tap = ky * 3 + kx;
                const float4* w0 = reinterpret_cast<const float4*>(sW + tap * 32);
                const float4* w1 = reinterpret_cast<const float4*>(sW + 288 + tap * 32);
                const float4* w2 = reinterpret_cast<const float4*>(sW + 576 + tap * 32);
#pragma unroll
                for (int c4 = 0; c4 < 8; c4++) {
                    float4 v = v4[c4];
                    float4 a = w0[c4], bq = w1[c4], cq = w2[c4];
                    acc0 += v.x * a.x + v.y * a.y + v.z * a.z + v.w * a.w;
                    acc1 += v.x * bq.x + v.y * bq.y + v.z * bq.z + v.w * bq.w;
                    acc2 += v.x * cq.x + v.y * cq.y + v.z * cq.z + v.w * cq.w;
                }
            }
        }
        float* cp = catpart + ((size_t)blockIdx.y * 128 + b) * 600;
        cp[tid] = acc0; cp[200 + tid] = acc1; cp[400 + tid] = acc2;
    }
}

// ---- MLP heads + final linear (folds partials + bias + relu) ------------------
__global__ __launch_bounds__(256)
void mlp_kernel(const float* __restrict__ corrpart, const float* __restrict__ catpart,
                const float* __restrict__ bcorr, const float* __restrict__ bcat,
                const float* __restrict__ cf_w1, const float* __restrict__ cf_b1,
                const float* __restrict__ cf_w2, const float* __restrict__ cf_b2,
                const float* __restrict__ ccf_w1, const float* __restrict__ ccf_b1,
                const float* __restrict__ ccf_w2, const float* __restrict__ ccf_b2,
                const float* __restrict__ Wout, const float* __restrict__ bout,
                float* __restrict__ out)
{
    __shared__ float sx[600];
    __shared__ float h1[256];
    __shared__ float h2[2][128];
    const int b = blockIdx.x, tid = threadIdx.x;

    for (int path = 0; path < 2; path++) {
        const float* w1 = path == 0 ? cf_w1 : ccf_w1;
        const float* b1 = path == 0 ? cf_b1 : ccf_b1;
        const float* w2 = path == 0 ? cf_w2 : ccf_w2;
        const float* b2 = path == 0 ? cf_b2 : ccf_b2;
        __syncthreads();
        if (path == 0) {
            for (int i = tid; i < 600; i += 256) {
                float v = bcorr[i / 200];
#pragma unroll
                for (int pr = 0; pr < 3; pr++)
                    v += corrpart[((size_t)pr * 128 + b) * 600 + i];
                sx[i] = fmaxf(v, 0.f);
            }
        } else {
            for (int i = tid; i < 600; i += 256) {
                float v = bcat[i / 200];
#pragma unroll
                for (int ch = 0; ch < 48; ch++)
                    v += catpart[((size_t)ch * 128 + b) * 600 + i];
                sx[i] = v;
            }
        }
        __syncthreads();
        {
            float s = b1[tid];
            const float4* wr = reinterpret_cast<const float4*>(w1 + (size_t)tid * 600);
#pragma unroll 4
            for (int k = 0; k < 150; k++) {
                float4 w = wr[k];
                s += w.x * sx[4*k] + w.y * sx[4*k+1] + w.z * sx[4*k+2] + w.w * sx[4*k+3];
            }
            h1[tid] = fmaxf(s, 0.f);
        }
        __syncthreads();
        if (tid < 128) {
            float s = b2[tid];
            const float4* wr = reinterpret_cast<const float4*>(w2 + (size_t)tid * 256);
#pragma unroll 4
            for (int k = 0; k < 64; k++) {
                float4 w = wr[k];
                s += w.x * h1[4*k] + w.y * h1[4*k+1] + w.z * h1[4*k+2] + w.w * h1[4*k+3];
            }
            h2[path][tid] = fmaxf(s, 0.f);
        }
    }
    __syncthreads();
    if (tid < 2) {
        float s = bout[tid];
        const float* wr = Wout + tid * 256;
        for (int i = 0; i < 128; i++)
            s += h2[0][i] * wr[i] + h2[1][i] * wr[128 + i];
        out[b * 2 + tid] = s;
    }
}

// ---- launch -------------------------------------------------------------------
extern "C" void kernel_launch(void* const* d_in, const int* in_sizes, int n_in,
                              void* d_out, int out_size)
{
    (void)in_sizes; (void)n_in; (void)out_size;
    const float* feat1 = (const float*)d_in[0];
    const float* feat2 = (const float*)d_in[1];
    const float* feat3 = (const float*)d_in[2];
    const float* Wa = (const float*)d_in[3];   const float* ba = (const float*)d_in[4];
    const float* Wb = (const float*)d_in[5];   const float* bb = (const float*)d_in[6];
    const float* Wc = (const float*)d_in[7];   const float* bc = (const float*)d_in[8];
    const float* Wcorr = (const float*)d_in[9];  const float* bcorr = (const float*)d_in[10];
    const float* Wcat = (const float*)d_in[11];  const float* bcat = (const float*)d_in[12];
    const float* cf_w1 = (const float*)d_in[13]; const float* cf_b1 = (const float*)d_in[14];
    const float* cf_w2 = (const float*)d_in[15]; const float* cf_b2 = (const float*)d_in[16];
    const float* ccf_w1 = (const float*)d_in[17]; const float* ccf_b1 = (const float*)d_in[18];
    const float* ccf_w2 = (const float*)d_in[19]; const float* ccf_b2 = (const float*)d_in[20];
    const float* Wout = (const float*)d_in[21];  const float* bout = (const float*)d_in[22];

    uint8_t *wh, *wl, *fih, *fil, *foh, *fol;
    float *G, *cvp, *tvp;
    cudaGetSymbolAddress((void**)&wh,  g_wh);
    cudaGetSymbolAddress((void**)&wl,  g_wl);
    cudaGetSymbolAddress((void**)&fih, g_finh);
    cudaGetSymbolAddress((void**)&fil, g_finl);
    cudaGetSymbolAddress((void**)&foh, g_fouth);
    cudaGetSymbolAddress((void**)&fol, g_foutl);
    cudaGetSymbolAddress((void**)&G,   g_gram);
    cudaGetSymbolAddress((void**)&cvp, g_corrpart);
    cudaGetSymbolAddress((void**)&tvp, g_catpart);

    cudaFuncSetAttribute(gemm_conv_kernel, cudaFuncAttributeMaxDynamicSharedMemorySize, CONV_SMEM);
    cudaFuncSetAttribute(gemm_gram_kernel, cudaFuncAttributeMaxDynamicSharedMemorySize, GRAM_SMEM);
    cudaFuncSetAttribute(corr_kernel, cudaFuncAttributeMaxDynamicSharedMemorySize, CORR_SMEM);

    convert_feat_kernel<<<dim3(128, 3), 256>>>(feat1, feat2, feat3, fih, fil,
                                               Wa, Wb, Wc, wh, wl);

    gemm_conv_kernel<<<dim3(8, 128, 3), 256, CONV_SMEM>>>(
        wh, wl, fih, fil, ba, bb, bc, foh, fol);

    gemm_gram_kernel<<<dim3(2, 128), 512, GRAM_SMEM>>>(foh, fol, G);

    corr_kernel<<<dim3(128, 9), 256, CORR_SMEM>>>(G, Wcorr, cvp);
    cat_kernel<<<dim3(128, 48), 256, CAT_SMEM>>>(foh, fol, Wcat, tvp);

    mlp_kernel<<<128, 256>>>(cvp, tvp, bcorr, bcat,
                             cf_w1, cf_b1, cf_w2, cf_b2,
                             ccf_w1, ccf_b1, ccf_w2, ccf_b2, Wout, bout, (float*)d_out);
}

// round 15
// speedup vs baseline: 1.8650x; 1.0460x over previous
#include <cuda_runtime.h>
#include <cuda_bf16.h>
#include <cstdint>
#include <cstddef>

#define NPIX 200

// ---- gmem scratch (static; zero-initialized at load) -------------------------
__device__ __align__(16) uint8_t g_wh[3u*4*16*10240];          //  2 MB
__device__ __align__(16) uint8_t g_wl[3u*4*16*10240];
__device__ __align__(16) uint8_t g_finh[3u*128*16*17920];      // 110 MB
__device__ __align__(16) uint8_t g_finl[3u*128*16*17920];
__device__ __align__(16) uint8_t g_fouth[3u*128*16*20480];     // 126 MB (class-major rows)
__device__ __align__(16) uint8_t g_foutl[3u*128*16*20480];
__device__ float g_gram[3u*128*10400];                         //  16 MB: [pair][b][cls4][50][52]
__device__ float g_corrpart[3*128*600];
__device__ float g_catpart[48*128*600];

#define CSTAGE 37120
#define C_CTRL 111360
#define CONV_SMEM (C_CTRL + 24)
#define GSTAGE 49152
#define G_CTRL (2*GSTAGE)
#define GRAM_SMEM (G_CTRL + 16)
#define CORR_SMEM ((10400 + 3969) * 4)
#define CAT_SMEM  ((7200 + 864) * 4)

__device__ __forceinline__ uint32_t smem_u32(const void* p) {
    uint32_t r;
    asm("{ .reg .u64 t; cvta.to.shared.u64 t, %1; cvt.u32.u64 %0, t; }" : "=r"(r) : "l"(p));
    return r;
}
#define MBAR_INIT(a, c) asm volatile("mbarrier.init.shared.b64 [%0], %1;" :: "r"(a), "r"(c) : "memory")
#define MBAR_EXPECT(a, n) asm volatile("mbarrier.arrive.expect_tx.shared.b64 _, [%0], %1;" :: "r"(a), "r"(n) : "memory")
#define MBAR_WAIT(a, ph) \
    asm volatile("{\n\t.reg .pred P;\n\tW_%=:\n\t" \
                 "mbarrier.try_wait.parity.acquire.cta.shared::cta.b64 P, [%0], %1, 0x989680;\n\t" \
                 "@!P bra W_%=;\n\t}" :: "r"(a), "r"(ph) : "memory")
#define BULK_G2S(dst, src, bytes, mbar) \
    asm volatile("cp.async.bulk.shared::cluster.global.mbarrier::complete_tx::bytes [%0], [%1], %2, [%3];" \
                 :: "r"(dst), "l"(src), "r"(bytes), "r"(mbar) : "memory")

__device__ __forceinline__ void ldsm4(uint32_t* r, uint32_t a) {
    asm volatile("ldmatrix.sync.aligned.m8n8.x4.shared.b16 {%0,%1,%2,%3}, [%4];"
        : "=r"(r[0]), "=r"(r[1]), "=r"(r[2]), "=r"(r[3]) : "r"(a));
}
__device__ __forceinline__ void ldsm2(uint32_t* r, uint32_t a) {
    asm volatile("ldmatrix.sync.aligned.m8n8.x2.shared.b16 {%0,%1}, [%2];"
        : "=r"(r[0]), "=r"(r[1]) : "r"(a));
}
__device__ __forceinline__ void mma16816(float* c, const uint32_t* a, const uint32_t* b) {
    asm volatile("mma.sync.aligned.m16n8k16.row.col.f32.bf16.bf16.f32 "
        "{%0,%1,%2,%3}, {%4,%5,%6,%7}, {%8,%9}, {%0,%1,%2,%3};"
        : "+f"(c[0]), "+f"(c[1]), "+f"(c[2]), "+f"(c[3])
        : "r"(a[0]), "r"(a[1]), "r"(a[2]), "r"(a[3]), "r"(b[0]), "r"(b[1]));
}
__device__ __forceinline__ void pack8(const float* v, uint4& h, uint4& l) {
    __align__(16) __nv_bfloat16 hb[8], lb[8];
#pragma unroll
    for (int u = 0; u < 8; u++) {
        hb[u] = __float2bfloat16_rn(v[u]);
        lb[u] = __float2bfloat16_rn(v[u] - __bfloat162float(hb[u]));
    }
    h = *reinterpret_cast<uint4*>(hb);
    l = *reinterpret_cast<uint4*>(lb);
}
__device__ __forceinline__ float2 bf2f(uint32_t u) {
    __nv_bfloat162 h = *reinterpret_cast<__nv_bfloat162*>(&u);
    return __bfloat1622float2(h);
}
__device__ __forceinline__ int perm_px(int p) {
    int y = p / 20, x = p - y * 20;
    return ((y & 1) * 2 + (x & 1)) * 50 + (y >> 1) * 10 + (x >> 1);
}

// ---- feats [b][c][p] -> transposed slab layout (z-split); weights on z==0 ----
__global__ __launch_bounds__(256) void convert_feat_kernel(
    const float* __restrict__ f1, const float* __restrict__ f2, const float* __restrict__ f3,
    uint8_t* __restrict__ oh, uint8_t* __restrict__ ol,
    const float* __restrict__ Wa, const float* __restrict__ Wb, const float* __restrict__ Wc,
    uint8_t* __restrict__ owh, uint8_t* __restrict__ owl)
{
    __shared__ float s[32 * 201];
    const int b = blockIdx.x, t = blockIdx.y, zc = blockIdx.z, tid = threadIdx.x;

    if (zc == 0) {
        int idx = (t * 128 + b) * 256 + tid;
        int tt = idx / 32768, rr = idx - tt * 32768;
        int m = rr >> 6, g8 = rr & 63;
        const float* W = (tt == 0) ? Wa : ((tt == 1) ? Wb : Wc);
        float v[8];
#pragma unroll
        for (int u = 0; u < 8; u++) v[u] = W[m * 512 + g8 * 8 + u];
        uint4 vh, vl; pack8(v, vh, vl);
        int mt = m >> 7, mr = m & 127, slab = g8 >> 2, c8 = g8 & 3;
        size_t off = ((size_t)(tt * 4 + mt) * 16 + slab) * 10240 + mr * 80 + c8 * 16;
        *(uint4*)(owh + off) = vh;
        *(uint4*)(owl + off) = vl;
    }

    const float* F = ((t == 0) ? f1 : ((t == 1) ? f2 : f3)) + (size_t)b * 102400;
    uint8_t* obh = oh + ((size_t)t * 128 + b) * 286720;
    uint8_t* obl = ol + ((size_t)t * 128 + b) * 286720;
    for (int c = zc * 4; c < zc * 4 + 4; c++) {
        __syncthreads();
        for (int e = tid; e < 32 * 200; e += 256) {
            int kk = e / 200, n = e - kk * 200;
            s[kk * 201 + n] = F[(size_t)(c * 32 + kk) * 200 + n];
        }
        __syncthreads();
        for (int i = tid; i < 800; i += 256) {
            int p = i >> 2, g8 = i & 3;
            float v[8];
#pragma unroll
            for (int u = 0; u < 8; u++) v[u] = s[(g8 * 8 + u) * 201 + p];
            uint4 vh, vl; pack8(v, vh, vl);
            size_t off = (size_t)c * 17920 + p * 80 + g8 * 16;
            *(uint4*)(obh + off) = vh;
            *(uint4*)(obl + off) = vl;
        }
    }
}

// ---- conv1x1 GEMM: paired-ldsm4 B loads (row-clamped), 8 warps, 3 stages -----
__global__ __launch_bounds__(256, 2) void gemm_conv_kernel(
    const uint8_t* __restrict__ Ah, const uint8_t* __restrict__ Al,
    const uint8_t* __restrict__ Bh, const uint8_t* __restrict__ Bl,
    const float* __restrict__ b0, const float* __restrict__ b1, const float* __restrict__ b2,
    uint8_t* __restrict__ Oh, uint8_t* __restrict__ Ol)
{
    extern __shared__ __align__(128) uint8_t smem[];
    const int tid = threadIdx.x;
    const int mt = blockIdx.x >> 1, nt = blockIdx.x & 1;
    const int b = blockIdx.y, z = blockIdx.z;
    const uint32_t sb = smem_u32(smem);
    const int warp = tid >> 5, lane = tid & 31;
    const int warpM = warp & 3, warpN = warp >> 2;
    const int nvalid = nt ? 96 : 104;
    const uint32_t bBytes = nvalid * 80;
    const uint32_t TXB = 20480 + 2 * bBytes;

    const uint32_t CTRL = sb + C_CTRL;
    if (tid == 0) {
#pragma unroll
        for (int p = 0; p < 3; p++) MBAR_INIT(CTRL + p * 8, 1);
    }
    __syncthreads();

    const uint8_t* pAh = Ah + (size_t)(z * 4 + mt) * 163840;
    const uint8_t* pAl = Al + (size_t)(z * 4 + mt) * 163840;
    const uint8_t* pBh = Bh + (size_t)(z * 128 + b) * 286720 + (size_t)nt * 8320;
    const uint8_t* pBl = Bl + (size_t)(z * 128 + b) * 286720 + (size_t)nt * 8320;

    if (tid == 0) {
#pragma unroll
        for (int s = 0; s < 3; s++) {
            const uint32_t st = sb + s * CSTAGE;
            MBAR_EXPECT(CTRL + s * 8, TXB);
            BULK_G2S(st,         pAh + (size_t)s * 10240, 10240, CTRL + s * 8);
            BULK_G2S(st + 10240, pAl + (size_t)s * 10240, 10240, CTRL + s * 8);
            BULK_G2S(st + 20480,          pBh + (size_t)s * 17920, bBytes, CTRL + s * 8);
            BULK_G2S(st + 20480 + bBytes, pBl + (size_t)s * 17920, bBytes, CTRL + s * 8);
        }
    }

    float c[2][7][4];
#pragma unroll
    for (int i = 0; i < 2; i++)
#pragma unroll
        for (int j = 0; j < 7; j++)
#pragma unroll
            for (int k = 0; k < 4; k++) c[i][j][k] = 0.f;

    // per-lane B rows, clamped into the staged buffer when out of range
    const int rB4 = warpN * 56 + (lane & 7) + ((lane >> 4) & 1) * 8;
    const int rB2 = warpN * 56 + (lane & 7) + 48;
    const uint32_t colOff = (uint32_t)(lane & 8) * 2;

    int phF[3] = {0, 0, 0};
    int p = 0;
    for (int s = 0; s < 16; s++) {
        const uint32_t st = sb + p * CSTAGE;
        MBAR_WAIT(CTRL + p * 8, phF[p]); phF[p] ^= 1;

        const uint32_t aBase = st + (warpM * 32 + (lane & 15)) * 80 + (lane & 16);
#pragma unroll
        for (int ks = 0; ks < 2; ks++) {
            const uint32_t kb = ks * 32;
            uint32_t afh[2][4], afl[2][4];
#pragma unroll
            for (int mi = 0; mi < 2; mi++) {
                ldsm4(afh[mi], aBase + mi * 1280 + kb);
                ldsm4(afl[mi], aBase + 10240 + mi * 1280 + kb);
            }
#pragma unroll
            for (int np = 0; np < 4; np++) {
                uint32_t bh[4], bl[4];
                if (np < 3) {
                    int r = rB4 + np * 16;
                    if (r >= nvalid) r = lane & 7;          // clamp OOB lanes
                    const uint32_t ad = st + 20480 + (uint32_t)r * 80 + colOff + kb;
                    ldsm4(bh, ad);
                    ldsm4(bl, ad + bBytes);
                } else {
                    int r = rB2;
                    if (r >= nvalid) r = lane & 7;
                    const uint32_t ad = st + 20480 + (uint32_t)r * 80 + colOff + kb;
                    ldsm2(bh, ad);
                    ldsm2(bl, ad + bBytes);
                }
#pragma unroll
                for (int u = 0; u < 2; u++) {
                    const int ni = 2 * np + u;
                    if (ni >= 7) break;
                    if (warpN * 56 + ni * 8 >= nvalid) continue;
#pragma unroll
                    for (int mi = 0; mi < 2; mi++) {
                        mma16816(c[mi][ni], afh[mi], &bh[2 * u]);
                        mma16816(c[mi][ni], afh[mi], &bl[2 * u]);
                        mma16816(c[mi][ni], afl[mi], &bh[2 * u]);
                    }
                }
            }
        }
        __syncthreads();
        if (tid == 0 && s + 3 < 16) {
            const int sn = s + 3;
            MBAR_EXPECT(CTRL + p * 8, TXB);
            BULK_G2S(st,         pAh + (size_t)sn * 10240, 10240, CTRL + p * 8);
            BULK_G2S(st + 10240, pAl + (size_t)sn * 10240, 10240, CTRL + p * 8);
            BULK_G2S(st + 20480,          pBh + (size_t)sn * 17920, bBytes, CTRL + p * 8);
            BULK_G2S(st + 20480 + bBytes, pBl + (size_t)sn * 17920, bBytes, CTRL + p * 8);
        }
        p = (p == 2) ? 0 : p + 1;
    }
    __syncthreads();

    const float* bias = (z == 0) ? b0 : ((z == 1) ? b1 : b2);
    __nv_bfloat16* sH = reinterpret_cast<__nv_bfloat16*>(smem);   // [pp<104][m128]
    __nv_bfloat16* sL = sH + 13312;
#pragma unroll
    for (int mi = 0; mi < 2; mi++) {
        const int m0 = warpM * 32 + mi * 16 + (lane >> 2);
        const float bv0 = __ldg(bias + mt * 128 + m0);
        const float bv1 = __ldg(bias + mt * 128 + m0 + 8);
#pragma unroll
        for (int ni = 0; ni < 7; ni++) {
            const int p0 = warpN * 56 + ni * 8 + (lane & 3) * 2;
            if (p0 >= nvalid) continue;
            float v[4] = {c[mi][ni][0] + bv0, c[mi][ni][1] + bv0,
                          c[mi][ni][2] + bv1, c[mi][ni][3] + bv1};
#pragma unroll
            for (int q = 0; q < 4; q++) {
                const int pp = p0 + (q & 1), mm = m0 + (q < 2 ? 0 : 8);
                __nv_bfloat16 h = __float2bfloat16_rn(v[q]);
                sH[pp * 128 + mm] = h;
                sL[pp * 128 + mm] = __float2bfloat16_rn(v[q] - __bfloat162float(h));
            }
        }
    }
    __syncthreads();
    uint8_t* ohB = Oh + ((size_t)(z * 128 + b) * 16 + mt * 4) * 20480;
    uint8_t* olB = Ol + ((size_t)(z * 128 + b) * 16 + mt * 4) * 20480;
    const int tot = nvalid * 16;
    for (int g = tid; g < tot; g += 256) {
        int pp = g >> 4, o = g & 15, q = o >> 2, oo = o & 3;
        int pr = perm_px(nt * 104 + pp);
        uint32_t so = (pp * 128 + q * 32 + oo * 8) * 2;
        size_t dof = (size_t)q * 20480 + pr * 80 + oo * 16;
        *(uint4*)(ohB + dof) = *(uint4*)((uint8_t*)sH + so);
        *(uint4*)(olB + dof) = *(uint4*)((uint8_t*)sL + so);
    }
}

// ---- Gram GEMM, class-blocked, paired-ldsm4 B loads (in-bounds by layout) -----
__global__ __launch_bounds__(512, 1) void gemm_gram_kernel(
    const uint8_t* __restrict__ Fh, const uint8_t* __restrict__ Fl, float* __restrict__ G)
{
    extern __shared__ __align__(128) uint8_t smem[];
    const int tid = threadIdx.x;
    const int ct = blockIdx.x, b = blockIdx.y;
    const uint32_t sb = smem_u32(smem);
    const int warp = tid >> 5, lane = tid & 31;
    const int sub = warp & 3, grp = warp >> 2;
    const bool active = (sub < 3);
    const int pr = sub;
    const int cls = grp >> 1, wm = grp & 1;
    const int pa = (pr == 2) ? 1 : 0, pb = (pr == 0) ? 1 : 2;

    const uint32_t CTRL = sb + G_CTRL;
    if (tid == 0) { MBAR_INIT(CTRL, 1); MBAR_INIT(CTRL + 8, 1); }
    __syncthreads();

    size_t baseT[3];
#pragma unroll
    for (int t = 0; t < 3; t++)
        baseT[t] = ((size_t)t * 128 + b) * 327680 + (size_t)ct * 8000;

    if (tid == 0) {
#pragma unroll
        for (int s = 0; s < 2; s++) {
            const uint32_t st = sb + s * GSTAGE;
            MBAR_EXPECT(CTRL + s * 8, 48000);
#pragma unroll
            for (int t = 0; t < 3; t++) {
                BULK_G2S(st + t * 16000,        Fh + baseT[t] + (size_t)s * 20480, 8000, CTRL + s * 8);
                BULK_G2S(st + t * 16000 + 8000, Fl + baseT[t] + (size_t)s * 20480, 8000, CTRL + s * 8);
            }
        }
    }

    float c[2][7][4];
#pragma unroll
    for (int i = 0; i < 2; i++)
#pragma unroll
        for (int j = 0; j < 7; j++)
#pragma unroll
            for (int k = 0; k < 4; k++) c[i][j][k] = 0.f;

    // B rows: cls*50 + (lane&7) (+8 for upper half-warp in x4); max overrun row
    // 55+48=103 < 200-row (16000B) tensor block -> stays in smem, results masked.
    const int rB4 = cls * 50 + (lane & 7) + ((lane >> 4) & 1) * 8;
    const int rB2 = cls * 50 + (lane & 7) + 48;
    const uint32_t colOff = (uint32_t)(lane & 8) * 2;

    int phF[2] = {0, 0};
    for (int s = 0; s < 16; s++) {
        const int p = s & 1;
        const uint32_t st = sb + p * GSTAGE;
        MBAR_WAIT(CTRL + p * 8, phF[p]); phF[p] ^= 1;

        if (active) {
            const uint32_t aBase = st + pa * 16000 + (cls * 50 + wm * 32 + (lane & 15)) * 80 + (lane & 16);
            const uint32_t bBase = st + pb * 16000;
#pragma unroll
            for (int ks = 0; ks < 2; ks++) {
                const uint32_t kb = ks * 32;
                uint32_t afh[2][4], afl[2][4];
#pragma unroll
                for (int mi = 0; mi < 2; mi++) {
                    ldsm4(afh[mi], aBase + mi * 1280 + kb);
                    ldsm4(afl[mi], aBase + 8000 + mi * 1280 + kb);
                }
#pragma unroll
                for (int np = 0; np < 4; np++) {
                    uint32_t bh[4], bl[4];
                    if (np < 3) {
                        const uint32_t ad = bBase + (uint32_t)(rB4 + np * 16) * 80 + colOff + kb;
                        ldsm4(bh, ad);
                        ldsm4(bl, ad + 8000);
                    } else {
                        const uint32_t ad = bBase + (uint32_t)rB2 * 80 + colOff + kb;
                        ldsm2(bh, ad);
                        ldsm2(bl, ad + 8000);
                    }
#pragma unroll
                    for (int u = 0; u < 2; u++) {
                        const int ni = 2 * np + u;
                        if (ni >= 7) break;
#pragma unroll
                        for (int mi = 0; mi < 2; mi++) {
                            mma16816(c[mi][ni], afh[mi], &bh[2 * u]);
                            mma16816(c[mi][ni], afh[mi], &bl[2 * u]);
                            mma16816(c[mi][ni], afl[mi], &bh[2 * u]);
                        }
                    }
                }
            }
        }
        __syncthreads();
        if (tid == 0 && s + 2 < 16) {
            const int sn = s + 2;
            MBAR_EXPECT(CTRL + p * 8, 48000);
#pragma unroll
            for (int t = 0; t < 3; t++) {
                BULK_G2S(st + t * 16000,        Fh + baseT[t] + (size_t)sn * 20480, 8000, CTRL + p * 8);
                BULK_G2S(st + t * 16000 + 8000, Fl + baseT[t] + (size_t)sn * 20480, 8000, CTRL + p * 8);
            }
        }
    }

    if (active) {
        float* Gb = G + ((size_t)pr * 128 + b) * 10400 + (ct * 2 + cls) * 2600;
#pragma unroll
        for (int mi = 0; mi < 2; mi++) {
            const int m = wm * 32 + mi * 16 + (lane >> 2);
#pragma unroll
            for (int ni = 0; ni < 7; ni++) {
                const int n0 = ni * 8 + (lane & 3) * 2;
                if (n0 >= 50) continue;
                if (m < 50)
                    *(float2*)(Gb + m * 52 + n0) = make_float2(c[mi][ni][0], c[mi][ni][1]);
                if (m + 8 < 50)
                    *(float2*)(Gb + (m + 8) * 52 + n0) = make_float2(c[mi][ni][2], c[mi][ni][3]);
            }
        }
    }
}

// ---- corr head: grid (128, 9) = (b, pair*3+o) --------------------------------
__global__ __launch_bounds__(256)
void corr_kernel(const float* __restrict__ Gram, const float* __restrict__ Wcorr,
                 float* __restrict__ corrpart)
{
    extern __shared__ float sh[];
    float* sG = sh;            // 10400: [cls4][50][52]
    float* sW = sh + 10400;    // 3969
    const int b = blockIdx.x;
    const int pair = blockIdx.y / 3, o = blockIdx.y - pair * 3;
    const int tid = threadIdx.x;
    const int y = tid / 20, x = tid - y * 20;

    const float4* G4 = reinterpret_cast<const float4*>(Gram + ((size_t)pair * 128 + b) * 10400);
    float4* sG4 = reinterpret_cast<float4*>(sG);
    for (int i = tid; i < 2600; i += 256) sG4[i] = G4[i];
    const float* Wsrc = Wcorr + o * 11907 + pair * 3969;
    for (int i = tid; i < 3969; i += 256) sW[i] = Wsrc[i];
    __syncthreads();

    if (tid < NPIX) {
        float acc = 0.f;
        for (int ky = 0; ky < 3; ky++) {
            int sy = y + ky - 1;
            if ((unsigned)sy >= 10u) continue;
            for (int kx = 0; kx < 3; kx++) {
                int sx = x + kx - 1;
                if ((unsigned)sx >= 20u) continue;
                const int cc = (sy & 1) * 2 + (sx & 1);
                const int i1 = (sy >> 1) * 10 + (sx >> 1);
                const float* gblk = sG + cc * 2600 + i1 * 52;
                const int tap = ky * 3 + kx;
                const int dyi0 = (21 - sy) >> 1, dxi0 = (21 - sx) >> 1;
                for (int iy = 0; iy < 5; iy++) {
                    const float* grow = gblk + iy * 10;
                    const float* wrow = sW + ((dyi0 + iy) * 21 + dxi0) * 9 + tap;
#pragma unroll
                    for (int ix = 0; ix < 10; ix++) {
                        float g = grow[ix] * (1.f / 512.f);
                        float v = g > 0.f ? g : 0.1f * g;
                        acc += v * wrow[ix * 9];
                    }
                }
            }
        }
        corrpart[((size_t)pair * 128 + b) * 600 + o * 200 + tid] = acc;
    }
}

// ---- cat head: grid (128, 48) = (b, t*16+ch) ----------------------------------
__global__ __launch_bounds__(256)
void cat_kernel(const uint8_t* __restrict__ Fh, const uint8_t* __restrict__ Fl,
                const float* __restrict__ Wcat, float* __restrict__ catpart)
{
    extern __shared__ float sh[];
    float* sF = sh;            // 200 x 36
    float* sW = sh + 7200;     // 864
    const int b = blockIdx.x;
    const int t = blockIdx.y / 16, ch = blockIdx.y - t * 16;
    const int tid = threadIdx.x;
    const int y = tid / 20, x = tid - y * 20;

    for (int g = tid; g < 800; g += 256) {
        int p = g >> 2, g8 = g & 3;
        int pr = perm_px(p);
        size_t base = (((size_t)t * 128 + b) * 16 + ch) * 20480 + pr * 80 + g8 * 16;
        uint4 vh = *(const uint4*)(Fh + base);
        uint4 vl = *(const uint4*)(Fl + base);
        float* d = &sF[p * 36 + g8 * 8];
        float2 a0 = bf2f(vh.x), c0 = bf2f(vl.x); d[0] = a0.x + c0.x; d[1] = a0.y + c0.y;
        float2 a1 = bf2f(vh.y), c1 = bf2f(vl.y); d[2] = a1.x + c1.x; d[3] = a1.y + c1.y;
        float2 a2 = bf2f(vh.z), c2 = bf2f(vl.z); d[4] = a2.x + c2.x; d[5] = a2.y + c2.y;
        float2 a3 = bf2f(vh.w), c3 = bf2f(vl.w); d[6] = a3.x + c3.x; d[7] = a3.y + c3.y;
    }
    for (int i = tid; i < 864; i += 256) {
        int o = i / 288, r = i - o * 288;
        int tap = r >> 5, cch = r & 31;
        sW[i] = Wcat[(size_t)(o * 1536 + t * 512 + ch * 32 + cch) * 9 + tap];
    }
    __syncthreads();

    if (tid < NPIX) {
        float acc0 = 0.f, acc1 = 0.f, acc2 = 0.f;
        for (int ky = 0; ky < 3; ky++) {
            int sy = y + ky - 1;
            if ((unsigned)sy >= 10u) continue;
            for (int kx = 0; kx < 3; kx++) {
                int sx = x + kx - 1;
                if ((unsigned)sx >= 20u) continue;
                const float4* v4 = reinterpret_cast<const float4*>(sF + (sy * 20 + sx) * 36);
                int tap = ky * 3 + kx;
                const float4* w0 = reinterpret_cast<const float4*>(sW + tap * 32);
                const float4* w1 = reinterpret_cast<const float4*>(sW + 288 + tap * 32);
                const float4* w2 = reinterpret_cast<const float4*>(sW + 576 + tap * 32);
#pragma unroll
                for (int c4 = 0; c4 < 8; c4++) {
                    float4 v = v4[c4];
                    float4 a = w0[c4], bq = w1[c4], cq = w2[c4];
                    acc0 += v.x * a.x + v.y * a.y + v.z * a.z + v.w * a.w;
                    acc1 += v.x * bq.x + v.y * bq.y + v.z * bq.z + v.w * bq.w;
                    acc2 += v.x * cq.x + v.y * cq.y + v.z * cq.z + v.w * cq.w;
                }
            }
        }
        float* cp = catpart + ((size_t)blockIdx.y * 128 + b) * 600;
        cp[tid] = acc0; cp[200 + tid] = acc1; cp[400 + tid] = acc2;
    }
}

// ---- MLP heads + final linear (folds partials + bias + relu) ------------------
__global__ __launch_bounds__(256)
void mlp_kernel(const float* __restrict__ corrpart, const float* __restrict__ catpart,
                const float* __restrict__ bcorr, const float* __restrict__ bcat,
                const float* __restrict__ cf_w1, const float* __restrict__ cf_b1,
                const float* __restrict__ cf_w2, const float* __restrict__ cf_b2,
                const float* __restrict__ ccf_w1, const float* __restrict__ ccf_b1,
                const float* __restrict__ ccf_w2, const float* __restrict__ ccf_b2,
                const float* __restrict__ Wout, const float* __restrict__ bout,
                float* __restrict__ out)
{
    __shared__ float sx[600];
    __shared__ float h1[256];
    __shared__ float h2[2][128];
    const int b = blockIdx.x, tid = threadIdx.x;

    for (int path = 0; path < 2; path++) {
        const float* w1 = path == 0 ? cf_w1 : ccf_w1;
        const float* b1 = path == 0 ? cf_b1 : ccf_b1;
        const float* w2 = path == 0 ? cf_w2 : ccf_w2;
        const float* b2 = path == 0 ? cf_b2 : ccf_b2;
        __syncthreads();
        if (path == 0) {
            for (int i = tid; i < 600; i += 256) {
                float v = bcorr[i / 200];
#pragma unroll
                for (int pr = 0; pr < 3; pr++)
                    v += corrpart[((size_t)pr * 128 + b) * 600 + i];
                sx[i] = fmaxf(v, 0.f);
            }
        } else {
            for (int i = tid; i < 600; i += 256) {
                float v = bcat[i / 200];
#pragma unroll
                for (int ch = 0; ch < 48; ch++)
                    v += catpart[((size_t)ch * 128 + b) * 600 + i];
                sx[i] = v;
            }
        }
        __syncthreads();
        {
            float s = b1[tid];
            const float4* wr = reinterpret_cast<const float4*>(w1 + (size_t)tid * 600);
#pragma unroll 4
            for (int k = 0; k < 150; k++) {
                float4 w = wr[k];
                s += w.x * sx[4*k] + w.y * sx[4*k+1] + w.z * sx[4*k+2] + w.w * sx[4*k+3];
            }
            h1[tid] = fmaxf(s, 0.f);
        }
        __syncthreads();
        if (tid < 128) {
            float s = b2[tid];
            const float4* wr = reinterpret_cast<const float4*>(w2 + (size_t)tid * 256);
#pragma unroll 4
            for (int k = 0; k < 64; k++) {
                float4 w = wr[k];
                s += w.x * h1[4*k] + w.y * h1[4*k+1] + w.z * h1[4*k+2] + w.w * h1[4*k+3];
            }
            h2[path][tid] = fmaxf(s, 0.f);
        }
    }
    __syncthreads();
    if (tid < 2) {
        float s = bout[tid];
        const float* wr = Wout + tid * 256;
        for (int i = 0; i < 128; i++)
            s += h2[0][i] * wr[i] + h2[1][i] * wr[128 + i];
        out[b * 2 + tid] = s;
    }
}

// ---- launch -------------------------------------------------------------------
extern "C" void kernel_launch(void* const* d_in, const int* in_sizes, int n_in,
                              void* d_out, int out_size)
{
    (void)in_sizes; (void)n_in; (void)out_size;
    const float* feat1 = (const float*)d_in[0];
    const float* feat2 = (const float*)d_in[1];
    const float* feat3 = (const float*)d_in[2];
    const float* Wa = (const float*)d_in[3];   const float* ba = (const float*)d_in[4];
    const float* Wb = (const float*)d_in[5];   const float* bb = (const float*)d_in[6];
    const float* Wc = (const float*)d_in[7];   const float* bc = (const float*)d_in[8];
    const float* Wcorr = (const float*)d_in[9];  const float* bcorr = (const float*)d_in[10];
    const float* Wcat = (const float*)d_in[11];  const float* bcat = (const float*)d_in[12];
    const float* cf_w1 = (const float*)d_in[13]; const float* cf_b1 = (const float*)d_in[14];
    const float* cf_w2 = (const float*)d_in[15]; const float* cf_b2 = (const float*)d_in[16];
    const float* ccf_w1 = (const float*)d_in[17]; const float* ccf_b1 = (const float*)d_in[18];
    const float* ccf_w2 = (const float*)d_in[19]; const float* ccf_b2 = (const float*)d_in[20];
    const float* Wout = (const float*)d_in[21];  const float* bout = (const float*)d_in[22];

    uint8_t *wh, *wl, *fih, *fil, *foh, *fol;
    float *G, *cvp, *tvp;
    cudaGetSymbolAddress((void**)&wh,  g_wh);
    cudaGetSymbolAddress((void**)&wl,  g_wl);
    cudaGetSymbolAddress((void**)&fih, g_finh);
    cudaGetSymbolAddress((void**)&fil, g_finl);
    cudaGetSymbolAddress((void**)&foh, g_fouth);
    cudaGetSymbolAddress((void**)&fol, g_foutl);
    cudaGetSymbolAddress((void**)&G,   g_gram);
    cudaGetSymbolAddress((void**)&cvp, g_corrpart);
    cudaGetSymbolAddress((void**)&tvp, g_catpart);

    cudaFuncSetAttribute(gemm_conv_kernel, cudaFuncAttributeMaxDynamicSharedMemorySize, CONV_SMEM);
    cudaFuncSetAttribute(gemm_gram_kernel, cudaFuncAttributeMaxDynamicSharedMemorySize, GRAM_SMEM);
    cudaFuncSetAttribute(corr_kernel, cudaFuncAttributeMaxDynamicSharedMemorySize, CORR_SMEM);

    convert_feat_kernel<<<dim3(128, 3, 4), 256>>>(feat1, feat2, feat3, fih, fil,
                                                  Wa, Wb, Wc, wh, wl);

    gemm_conv_kernel<<<dim3(8, 128, 3), 256, CONV_SMEM>>>(
        wh, wl, fih, fil, ba, bb, bc, foh, fol);

    gemm_gram_kernel<<<dim3(2, 128), 512, GRAM_SMEM>>>(foh, fol, G);

    corr_kernel<<<dim3(128, 9), 256, CORR_SMEM>>>(G, Wcorr, cvp);
    cat_kernel<<<dim3(128, 48), 256, CAT_SMEM>>>(foh, fol, Wcat, tvp);

    mlp_kernel<<<128, 256>>>(cvp, tvp, bcorr, bcat,
                             cf_w1, cf_b1, cf_w2, cf_b2,
                             ccf_w1, ccf_b1, ccf_w2, ccf_b2, Wout, bout, (float*)d_out);
}

// round 16
// speedup vs baseline: 1.9028x; 1.0203x over previous
#include <cuda_runtime.h>
#include <cuda_bf16.h>
#include <cstdint>
#include <cstddef>

#define NPIX 200

// ---- gmem scratch (static; zero-initialized at load) -------------------------
__device__ __align__(16) uint8_t g_wh[3u*4*16*10240];          //  2 MB
__device__ __align__(16) uint8_t g_wl[3u*4*16*10240];
__device__ __align__(16) uint8_t g_finh[3u*128*16*17920];      // 110 MB
__device__ __align__(16) uint8_t g_finl[3u*128*16*17920];
__device__ __align__(16) uint8_t g_fouth[3u*128*16*20480];     // 126 MB (class-major rows)
__device__ __align__(16) uint8_t g_foutl[3u*128*16*20480];
__device__ float g_gram[3u*128*10400];                         //  16 MB: [pair][b][cls4][50][52]
__device__ float g_corrpart[3*128*600];
__device__ float g_catpart[48*128*600];

#define CSTAGE 37120
#define C_CTRL 111360
#define CONV_SMEM (C_CTRL + 24)
#define GSTAGE 49152
#define G_CTRL (2*GSTAGE)
#define GRAM_SMEM (G_CTRL + 16)
#define CORR_SMEM ((10400 + 3969) * 4)
#define CAT_SMEM  ((7200 + 864) * 4)

__device__ __forceinline__ uint32_t smem_u32(const void* p) {
    uint32_t r;
    asm("{ .reg .u64 t; cvta.to.shared.u64 t, %1; cvt.u32.u64 %0, t; }" : "=r"(r) : "l"(p));
    return r;
}
#define MBAR_INIT(a, c) asm volatile("mbarrier.init.shared.b64 [%0], %1;" :: "r"(a), "r"(c) : "memory")
#define MBAR_EXPECT(a, n) asm volatile("mbarrier.arrive.expect_tx.shared.b64 _, [%0], %1;" :: "r"(a), "r"(n) : "memory")
#define MBAR_WAIT(a, ph) \
    asm volatile("{\n\t.reg .pred P;\n\tW_%=:\n\t" \
                 "mbarrier.try_wait.parity.acquire.cta.shared::cta.b64 P, [%0], %1, 0x989680;\n\t" \
                 "@!P bra W_%=;\n\t}" :: "r"(a), "r"(ph) : "memory")
#define BULK_G2S(dst, src, bytes, mbar) \
    asm volatile("cp.async.bulk.shared::cluster.global.mbarrier::complete_tx::bytes [%0], [%1], %2, [%3];" \
                 :: "r"(dst), "l"(src), "r"(bytes), "r"(mbar) : "memory")

__device__ __forceinline__ void ldsm4(uint32_t* r, uint32_t a) {
    asm volatile("ldmatrix.sync.aligned.m8n8.x4.shared.b16 {%0,%1,%2,%3}, [%4];"
        : "=r"(r[0]), "=r"(r[1]), "=r"(r[2]), "=r"(r[3]) : "r"(a));
}
__device__ __forceinline__ void ldsm2(uint32_t* r, uint32_t a) {
    asm volatile("ldmatrix.sync.aligned.m8n8.x2.shared.b16 {%0,%1}, [%2];"
        : "=r"(r[0]), "=r"(r[1]) : "r"(a));
}
__device__ __forceinline__ void mma16816(float* c, const uint32_t* a, const uint32_t* b) {
    asm volatile("mma.sync.aligned.m16n8k16.row.col.f32.bf16.bf16.f32 "
        "{%0,%1,%2,%3}, {%4,%5,%6,%7}, {%8,%9}, {%0,%1,%2,%3};"
        : "+f"(c[0]), "+f"(c[1]), "+f"(c[2]), "+f"(c[3])
        : "r"(a[0]), "r"(a[1]), "r"(a[2]), "r"(a[3]), "r"(b[0]), "r"(b[1]));
}
__device__ __forceinline__ void pack8(const float* v, uint4& h, uint4& l) {
    __align__(16) __nv_bfloat16 hb[8], lb[8];
#pragma unroll
    for (int u = 0; u < 8; u++) {
        hb[u] = __float2bfloat16_rn(v[u]);
        lb[u] = __float2bfloat16_rn(v[u] - __bfloat162float(hb[u]));
    }
    h = *reinterpret_cast<uint4*>(hb);
    l = *reinterpret_cast<uint4*>(lb);
}
__device__ __forceinline__ float2 bf2f(uint32_t u) {
    __nv_bfloat162 h = *reinterpret_cast<__nv_bfloat162*>(&u);
    return __bfloat1622float2(h);
}
__device__ __forceinline__ int perm_px(int p) {
    int y = p / 20, x = p - y * 20;
    return ((y & 1) * 2 + (x & 1)) * 50 + (y >> 1) * 10 + (x >> 1);
}

// ---- feats [b][c][p] -> transposed slab layout (z-split); weights on z==0 ----
__global__ __launch_bounds__(256) void convert_feat_kernel(
    const float* __restrict__ f1, const float* __restrict__ f2, const float* __restrict__ f3,
    uint8_t* __restrict__ oh, uint8_t* __restrict__ ol,
    const float* __restrict__ Wa, const float* __restrict__ Wb, const float* __restrict__ Wc,
    uint8_t* __restrict__ owh, uint8_t* __restrict__ owl)
{
    __shared__ float s[32 * 201];
    const int b = blockIdx.x, t = blockIdx.y, zc = blockIdx.z, tid = threadIdx.x;

    if (zc == 0) {
        int idx = (t * 128 + b) * 256 + tid;
        int tt = idx / 32768, rr = idx - tt * 32768;
        int m = rr >> 6, g8 = rr & 63;
        const float* W = (tt == 0) ? Wa : ((tt == 1) ? Wb : Wc);
        float v[8];
#pragma unroll
        for (int u = 0; u < 8; u++) v[u] = W[m * 512 + g8 * 8 + u];
        uint4 vh, vl; pack8(v, vh, vl);
        int mt = m >> 7, mr = m & 127, slab = g8 >> 2, c8 = g8 & 3;
        size_t off = ((size_t)(tt * 4 + mt) * 16 + slab) * 10240 + mr * 80 + c8 * 16;
        *(uint4*)(owh + off) = vh;
        *(uint4*)(owl + off) = vl;
    }

    const float* F = ((t == 0) ? f1 : ((t == 1) ? f2 : f3)) + (size_t)b * 102400;
    uint8_t* obh = oh + ((size_t)t * 128 + b) * 286720;
    uint8_t* obl = ol + ((size_t)t * 128 + b) * 286720;
    for (int c = zc * 4; c < zc * 4 + 4; c++) {
        __syncthreads();
        for (int e = tid; e < 32 * 200; e += 256) {
            int kk = e / 200, n = e - kk * 200;
            s[kk * 201 + n] = F[(size_t)(c * 32 + kk) * 200 + n];
        }
        __syncthreads();
        for (int i = tid; i < 800; i += 256) {
            int p = i >> 2, g8 = i & 3;
            float v[8];
#pragma unroll
            for (int u = 0; u < 8; u++) v[u] = s[(g8 * 8 + u) * 201 + p];
            uint4 vh, vl; pack8(v, vh, vl);
            size_t off = (size_t)c * 17920 + p * 80 + g8 * 16;
            *(uint4*)(obh + off) = vh;
            *(uint4*)(obl + off) = vl;
        }
    }
}

// ---- conv1x1 GEMM: paired-ldsm4 B loads (row-clamped), 8 warps, 3 stages -----
__global__ __launch_bounds__(256, 2) void gemm_conv_kernel(
    const uint8_t* __restrict__ Ah, const uint8_t* __restrict__ Al,
    const uint8_t* __restrict__ Bh, const uint8_t* __restrict__ Bl,
    const float* __restrict__ b0, const float* __restrict__ b1, const float* __restrict__ b2,
    uint8_t* __restrict__ Oh, uint8_t* __restrict__ Ol)
{
    extern __shared__ __align__(128) uint8_t smem[];
    const int tid = threadIdx.x;
    const int mt = blockIdx.x >> 1, nt = blockIdx.x & 1;
    const int b = blockIdx.y, z = blockIdx.z;
    const uint32_t sb = smem_u32(smem);
    const int warp = tid >> 5, lane = tid & 31;
    const int warpM = warp & 3, warpN = warp >> 2;
    const int nvalid = nt ? 96 : 104;
    const uint32_t bBytes = nvalid * 80;
    const uint32_t TXB = 20480 + 2 * bBytes;

    const uint32_t CTRL = sb + C_CTRL;
    if (tid == 0) {
#pragma unroll
        for (int p = 0; p < 3; p++) MBAR_INIT(CTRL + p * 8, 1);
    }
    __syncthreads();

    const uint8_t* pAh = Ah + (size_t)(z * 4 + mt) * 163840;
    const uint8_t* pAl = Al + (size_t)(z * 4 + mt) * 163840;
    const uint8_t* pBh = Bh + (size_t)(z * 128 + b) * 286720 + (size_t)nt * 8320;
    const uint8_t* pBl = Bl + (size_t)(z * 128 + b) * 286720 + (size_t)nt * 8320;

    if (tid == 0) {
#pragma unroll
        for (int s = 0; s < 3; s++) {
            const uint32_t st = sb + s * CSTAGE;
            MBAR_EXPECT(CTRL + s * 8, TXB);
            BULK_G2S(st,         pAh + (size_t)s * 10240, 10240, CTRL + s * 8);
            BULK_G2S(st + 10240, pAl + (size_t)s * 10240, 10240, CTRL + s * 8);
            BULK_G2S(st + 20480,          pBh + (size_t)s * 17920, bBytes, CTRL + s * 8);
            BULK_G2S(st + 20480 + bBytes, pBl + (size_t)s * 17920, bBytes, CTRL + s * 8);
        }
    }

    float c[2][7][4];
#pragma unroll
    for (int i = 0; i < 2; i++)
#pragma unroll
        for (int j = 0; j < 7; j++)
#pragma unroll
            for (int k = 0; k < 4; k++) c[i][j][k] = 0.f;

    const int rB4 = warpN * 56 + (lane & 7) + ((lane >> 4) & 1) * 8;
    const int rB2 = warpN * 56 + (lane & 7) + 48;
    const uint32_t colOff = (uint32_t)(lane & 8) * 2;

    int phF[3] = {0, 0, 0};
    int p = 0;
    for (int s = 0; s < 16; s++) {
        const uint32_t st = sb + p * CSTAGE;
        MBAR_WAIT(CTRL + p * 8, phF[p]); phF[p] ^= 1;

        const uint32_t aBase = st + (warpM * 32 + (lane & 15)) * 80 + (lane & 16);
#pragma unroll
        for (int ks = 0; ks < 2; ks++) {
            const uint32_t kb = ks * 32;
            uint32_t afh[2][4], afl[2][4];
#pragma unroll
            for (int mi = 0; mi < 2; mi++) {
                ldsm4(afh[mi], aBase + mi * 1280 + kb);
                ldsm4(afl[mi], aBase + 10240 + mi * 1280 + kb);
            }
#pragma unroll
            for (int np = 0; np < 4; np++) {
                uint32_t bh[4], bl[4];
                if (np < 3) {
                    int r = rB4 + np * 16;
                    if (r >= nvalid) r = lane & 7;
                    const uint32_t ad = st + 20480 + (uint32_t)r * 80 + colOff + kb;
                    ldsm4(bh, ad);
                    ldsm4(bl, ad + bBytes);
                } else {
                    int r = rB2;
                    if (r >= nvalid) r = lane & 7;
                    const uint32_t ad = st + 20480 + (uint32_t)r * 80 + colOff + kb;
                    ldsm2(bh, ad);
                    ldsm2(bl, ad + bBytes);
                }
#pragma unroll
                for (int u = 0; u < 2; u++) {
                    const int ni = 2 * np + u;
                    if (ni >= 7) break;
                    if (warpN * 56 + ni * 8 >= nvalid) continue;
#pragma unroll
                    for (int mi = 0; mi < 2; mi++) {
                        mma16816(c[mi][ni], afh[mi], &bh[2 * u]);
                        mma16816(c[mi][ni], afh[mi], &bl[2 * u]);
                        mma16816(c[mi][ni], afl[mi], &bh[2 * u]);
                    }
                }
            }
        }
        __syncthreads();
        if (tid == 0 && s + 3 < 16) {
            const int sn = s + 3;
            MBAR_EXPECT(CTRL + p * 8, TXB);
            BULK_G2S(st,         pAh + (size_t)sn * 10240, 10240, CTRL + p * 8);
            BULK_G2S(st + 10240, pAl + (size_t)sn * 10240, 10240, CTRL + p * 8);
            BULK_G2S(st + 20480,          pBh + (size_t)sn * 17920, bBytes, CTRL + p * 8);
            BULK_G2S(st + 20480 + bBytes, pBl + (size_t)sn * 17920, bBytes, CTRL + p * 8);
        }
        p = (p == 2) ? 0 : p + 1;
    }
    __syncthreads();

    const float* bias = (z == 0) ? b0 : ((z == 1) ? b1 : b2);
    __nv_bfloat16* sH = reinterpret_cast<__nv_bfloat16*>(smem);   // [pp<104][m128]
    __nv_bfloat16* sL = sH + 13312;
#pragma unroll
    for (int mi = 0; mi < 2; mi++) {
        const int m0 = warpM * 32 + mi * 16 + (lane >> 2);
        const float bv0 = __ldg(bias + mt * 128 + m0);
        const float bv1 = __ldg(bias + mt * 128 + m0 + 8);
#pragma unroll
        for (int ni = 0; ni < 7; ni++) {
            const int p0 = warpN * 56 + ni * 8 + (lane & 3) * 2;
            if (p0 >= nvalid) continue;
            float v[4] = {c[mi][ni][0] + bv0, c[mi][ni][1] + bv0,
                          c[mi][ni][2] + bv1, c[mi][ni][3] + bv1};
#pragma unroll
            for (int q = 0; q < 4; q++) {
                const int pp = p0 + (q & 1), mm = m0 + (q < 2 ? 0 : 8);
                __nv_bfloat16 h = __float2bfloat16_rn(v[q]);
                sH[pp * 128 + mm] = h;
                sL[pp * 128 + mm] = __float2bfloat16_rn(v[q] - __bfloat162float(h));
            }
        }
    }
    __syncthreads();
    uint8_t* ohB = Oh + ((size_t)(z * 128 + b) * 16 + mt * 4) * 20480;
    uint8_t* olB = Ol + ((size_t)(z * 128 + b) * 16 + mt * 4) * 20480;
    const int tot = nvalid * 16;
    for (int g = tid; g < tot; g += 256) {
        int pp = g >> 4, o = g & 15, q = o >> 2, oo = o & 3;
        int pr = perm_px(nt * 104 + pp);
        uint32_t so = (pp * 128 + q * 32 + oo * 8) * 2;
        size_t dof = (size_t)q * 20480 + pr * 80 + oo * 16;
        *(uint4*)(ohB + dof) = *(uint4*)((uint8_t*)sH + so);
        *(uint4*)(olB + dof) = *(uint4*)((uint8_t*)sL + so);
    }
}

// ---- Gram GEMM: 256-thr CTAs (2/SM), grid (4,128): x = zh*2+ct.  Each CTA
//      stages all 3 tensors; 6 active warps cover half the 12 (pr,cls,wm) units.
__global__ __launch_bounds__(256, 2) void gemm_gram_kernel(
    const uint8_t* __restrict__ Fh, const uint8_t* __restrict__ Fl, float* __restrict__ G)
{
    extern __shared__ __align__(128) uint8_t smem[];
    const int tid = threadIdx.x;
    const int ct = blockIdx.x & 1, zh = blockIdx.x >> 1, b = blockIdx.y;
    const uint32_t sb = smem_u32(smem);
    const int warp = tid >> 5, lane = tid & 31;
    const bool active = (warp < 6);
    const int u = zh * 6 + warp;               // 0..11 (warp<6)
    const int pr = u >> 2, rem = u & 3;
    const int cls = rem >> 1, wm = rem & 1;
    const int pa = (pr == 2) ? 1 : 0, pb = (pr == 0) ? 1 : 2;

    const uint32_t CTRL = sb + G_CTRL;
    if (tid == 0) { MBAR_INIT(CTRL, 1); MBAR_INIT(CTRL + 8, 1); }
    __syncthreads();

    size_t baseT[3];
#pragma unroll
    for (int t = 0; t < 3; t++)
        baseT[t] = ((size_t)t * 128 + b) * 327680 + (size_t)ct * 8000;

    if (tid == 0) {
#pragma unroll
        for (int s = 0; s < 2; s++) {
            const uint32_t st = sb + s * GSTAGE;
            MBAR_EXPECT(CTRL + s * 8, 48000);
#pragma unroll
            for (int t = 0; t < 3; t++) {
                BULK_G2S(st + t * 16000,        Fh + baseT[t] + (size_t)s * 20480, 8000, CTRL + s * 8);
                BULK_G2S(st + t * 16000 + 8000, Fl + baseT[t] + (size_t)s * 20480, 8000, CTRL + s * 8);
            }
        }
    }

    float c[2][7][4];
#pragma unroll
    for (int i = 0; i < 2; i++)
#pragma unroll
        for (int j = 0; j < 7; j++)
#pragma unroll
            for (int k = 0; k < 4; k++) c[i][j][k] = 0.f;

    const int rB4 = cls * 50 + (lane & 7) + ((lane >> 4) & 1) * 8;
    const int rB2 = cls * 50 + (lane & 7) + 48;
    const uint32_t colOff = (uint32_t)(lane & 8) * 2;

    int phF[2] = {0, 0};
    for (int s = 0; s < 16; s++) {
        const int p = s & 1;
        const uint32_t st = sb + p * GSTAGE;
        MBAR_WAIT(CTRL + p * 8, phF[p]); phF[p] ^= 1;

        if (active) {
            const uint32_t aBase = st + pa * 16000 + (cls * 50 + wm * 32 + (lane & 15)) * 80 + (lane & 16);
            const uint32_t bBase = st + pb * 16000;
#pragma unroll
            for (int ks = 0; ks < 2; ks++) {
                const uint32_t kb = ks * 32;
                uint32_t afh[2][4], afl[2][4];
#pragma unroll
                for (int mi = 0; mi < 2; mi++) {
                    ldsm4(afh[mi], aBase + mi * 1280 + kb);
                    ldsm4(afl[mi], aBase + 8000 + mi * 1280 + kb);
                }
#pragma unroll
                for (int np = 0; np < 4; np++) {
                    uint32_t bh[4], bl[4];
                    if (np < 3) {
                        const uint32_t ad = bBase + (uint32_t)(rB4 + np * 16) * 80 + colOff + kb;
                        ldsm4(bh, ad);
                        ldsm4(bl, ad + 8000);
                    } else {
                        const uint32_t ad = bBase + (uint32_t)rB2 * 80 + colOff + kb;
                        ldsm2(bh, ad);
                        ldsm2(bl, ad + 8000);
                    }
#pragma unroll
                    for (int v = 0; v < 2; v++) {
                        const int ni = 2 * np + v;
                        if (ni >= 7) break;
#pragma unroll
                        for (int mi = 0; mi < 2; mi++) {
                            mma16816(c[mi][ni], afh[mi], &bh[2 * v]);
                            mma16816(c[mi][ni], afh[mi], &bl[2 * v]);
                            mma16816(c[mi][ni], afl[mi], &bh[2 * v]);
                        }
                    }
                }
            }
        }
        __syncthreads();
        if (tid == 0 && s + 2 < 16) {
            const int sn = s + 2;
            MBAR_EXPECT(CTRL + p * 8, 48000);
#pragma unroll
            for (int t = 0; t < 3; t++) {
                BULK_G2S(st + t * 16000,        Fh + baseT[t] + (size_t)sn * 20480, 8000, CTRL + p * 8);
                BULK_G2S(st + t * 16000 + 8000, Fl + baseT[t] + (size_t)sn * 20480, 8000, CTRL + p * 8);
            }
        }
    }

    if (active) {
        float* Gb = G + ((size_t)pr * 128 + b) * 10400 + (ct * 2 + cls) * 2600;
#pragma unroll
        for (int mi = 0; mi < 2; mi++) {
            const int m = wm * 32 + mi * 16 + (lane >> 2);
#pragma unroll
            for (int ni = 0; ni < 7; ni++) {
                const int n0 = ni * 8 + (lane & 3) * 2;
                if (n0 >= 50) continue;
                if (m < 50)
                    *(float2*)(Gb + m * 52 + n0) = make_float2(c[mi][ni][0], c[mi][ni][1]);
                if (m + 8 < 50)
                    *(float2*)(Gb + (m + 8) * 52 + n0) = make_float2(c[mi][ni][2], c[mi][ni][3]);
            }
        }
    }
}

// ---- corr head: transposed weights, stride-1 unrolled inner loop --------------
__global__ __launch_bounds__(256)
void corr_kernel(const float* __restrict__ Gram, const float* __restrict__ Wcorr,
                 float* __restrict__ corrpart)
{
    extern __shared__ float sh[];
    float* sG = sh;            // 10400: [cls4][50][52]
    float* sW = sh + 10400;    // 3969 transposed: [tap9][dyi21 x dxi21]
    const int b = blockIdx.x;
    const int pair = blockIdx.y / 3, o = blockIdx.y - pair * 3;
    const int tid = threadIdx.x;
    const int y = tid / 20, x = tid - y * 20;

    const float4* G4 = reinterpret_cast<const float4*>(Gram + ((size_t)pair * 128 + b) * 10400);
    float4* sG4 = reinterpret_cast<float4*>(sG);
    for (int i = tid; i < 2600; i += 256) sG4[i] = G4[i];
    const float* Wsrc = Wcorr + o * 11907 + pair * 3969;
    for (int i = tid; i < 3969; i += 256) {
        int tap = i / 441, d = i - tap * 441;
        sW[i] = Wsrc[d * 9 + tap];
    }
    __syncthreads();

    if (tid < NPIX) {
        float acc = 0.f;
        for (int ky = 0; ky < 3; ky++) {
            for (int kx = 0; kx < 3; kx++) {
                int sy = y + ky - 1, sx = x + kx - 1;
                if ((unsigned)sy >= 10u || (unsigned)sx >= 20u) continue;
                const int qy = sy >> 1, qx = sx >> 1;
                const int cc = (sy & 1) * 2 + (sx & 1);
                const float* g = sG + cc * 2600 + (qy * 10 + qx) * 52;
                const float* w = sW + (ky * 3 + kx) * 441 + (10 - qy) * 21 + (10 - qx);
#pragma unroll
                for (int iy = 0; iy < 5; iy++) {
#pragma unroll
                    for (int ix = 0; ix < 10; ix++) {
                        float gg = g[iy * 10 + ix] * (1.f / 512.f);
                        float v = gg > 0.f ? gg : 0.1f * gg;
                        acc += v * w[iy * 21 + ix];
                    }
                }
            }
        }
        corrpart[((size_t)pair * 128 + b) * 600 + o * 200 + tid] = acc;
    }
}

// ---- cat head: grid (128, 48) = (b, t*16+ch) ----------------------------------
__global__ __launch_bounds__(256)
void cat_kernel(const uint8_t* __restrict__ Fh, const uint8_t* __restrict__ Fl,
                const float* __restrict__ Wcat, float* __restrict__ catpart)
{
    extern __shared__ float sh[];
    float* sF = sh;            // 200 x 36
    float* sW = sh + 7200;     // 864
    const int b = blockIdx.x;
    const int t = blockIdx.y / 16, ch = blockIdx.y - t * 16;
    const int tid = threadIdx.x;
    const int y = tid / 20, x = tid - y * 20;

    for (int g = tid; g < 800; g += 256) {
        int p = g >> 2, g8 = g & 3;
        int pr = perm_px(p);
        size_t base = (((size_t)t * 128 + b) * 16 + ch) * 20480 + pr * 80 + g8 * 16;
        uint4 vh = *(const uint4*)(Fh + base);
        uint4 vl = *(const uint4*)(Fl + base);
        float* d = &sF[p * 36 + g8 * 8];
        float2 a0 = bf2f(vh.x), c0 = bf2f(vl.x); d[0] = a0.x + c0.x; d[1] = a0.y + c0.y;
        float2 a1 = bf2f(vh.y), c1 = bf2f(vl.y); d[2] = a1.x + c1.x; d[3] = a1.y + c1.y;
        float2 a2 = bf2f(vh.z), c2 = bf2f(vl.z); d[4] = a2.x + c2.x; d[5] = a2.y + c2.y;
        float2 a3 = bf2f(vh.w), c3 = bf2f(vl.w); d[6] = a3.x + c3.x; d[7] = a3.y + c3.y;
    }
    for (int i = tid; i < 864; i += 256) {
        int o = i / 288, r = i - o * 288;
        int tap = r >> 5, cch = r & 31;
        sW[i] = Wcat[(size_t)(o * 1536 + t * 512 + ch * 32 + cch) * 9 + tap];
    }
    __syncthreads();

    if (tid < NPIX) {
        float acc0 = 0.f, acc1 = 0.f, acc2 = 0.f;
        for (int ky = 0; ky < 3; ky++) {
            int sy = y + ky - 1;
            if ((unsigned)sy >= 10u) continue;
            for (int kx = 0; kx < 3; kx++) {
                int sx = x + kx - 1;
                if ((unsigned)sx >= 20u) continue;
                const float4* v4 = reinterpret_cast<const float4*>(sF + (sy * 20 + sx) * 36);
                int tap = ky * 3 + kx;
                const float4* w0 = reinterpret_cast<const float4*>(sW + tap * 32);
                const float4* w1 = reinterpret_cast<const float4*>(sW + 288 + tap * 32);
                const float4* w2 = reinterpret_cast<const float4*>(sW + 576 + tap * 32);
#pragma unroll
                for (int c4 = 0; c4 < 8; c4++) {
                    float4 v = v4[c4];
                    float4 a = w0[c4], bq = w1[c4], cq = w2[c4];
                    acc0 += v.x * a.x + v.y * a.y + v.z * a.z + v.w * a.w;
                    acc1 += v.x * bq.x + v.y * bq.y + v.z * bq.z + v.w * bq.w;
                    acc2 += v.x * cq.x + v.y * cq.y + v.z * cq.z + v.w * cq.w;
                }
            }
        }
        float* cp = catpart + ((size_t)blockIdx.y * 128 + b) * 600;
        cp[tid] = acc0; cp[200 + tid] = acc1; cp[400 + tid] = acc2;
    }
}

// ---- MLP heads + final linear (folds partials + bias + relu) ------------------
__global__ __launch_bounds__(256)
void mlp_kernel(const float* __restrict__ corrpart, const float* __restrict__ catpart,
                const float* __restrict__ bcorr, const float* __restrict__ bcat,
                const float* __restrict__ cf_w1, const float* __restrict__ cf_b1,
                const float* __restrict__ cf_w2, const float* __restrict__ cf_b2,
                const float* __restrict__ ccf_w1, const float* __restrict__ ccf_b1,
                const float* __restrict__ ccf_w2, const float* __restrict__ ccf_b2,
                const float* __restrict__ Wout, const float* __restrict__ bout,
                float* __restrict__ out)
{
    __shared__ float sx[600];
    __shared__ float h1[256];
    __shared__ float h2[2][128];
    const int b = blockIdx.x, tid = threadIdx.x;

    for (int path = 0; path < 2; path++) {
        const float* w1 = path == 0 ? cf_w1 : ccf_w1;
        const float* b1 = path == 0 ? cf_b1 : ccf_b1;
        const float* w2 = path == 0 ? cf_w2 : ccf_w2;
        const float* b2 = path == 0 ? cf_b2 : ccf_b2;
        __syncthreads();
        if (path == 0) {
            for (int i = tid; i < 600; i += 256) {
                float v = bcorr[i / 200];
#pragma unroll
                for (int pr = 0; pr < 3; pr++)
                    v += corrpart[((size_t)pr * 128 + b) * 600 + i];
                sx[i] = fmaxf(v, 0.f);
            }
        } else {
            for (int i = tid; i < 600; i += 256) {
                float v = bcat[i / 200];
#pragma unroll
                for (int ch = 0; ch < 48; ch++)
                    v += catpart[((size_t)ch * 128 + b) * 600 + i];
                sx[i] = v;
            }
        }
        __syncthreads();
        {
            float s = b1[tid];
            const float4* wr = reinterpret_cast<const float4*>(w1 + (size_t)tid * 600);
#pragma unroll 4
            for (int k = 0; k < 150; k++) {
                float4 w = wr[k];
                s += w.x * sx[4*k] + w.y * sx[4*k+1] + w.z * sx[4*k+2] + w.w * sx[4*k+3];
            }
            h1[tid] = fmaxf(s, 0.f);
        }
        __syncthreads();
        if (tid < 128) {
            float s = b2[tid];
            const float4* wr = reinterpret_cast<const float4*>(w2 + (size_t)tid * 256);
#pragma unroll 4
            for (int k = 0; k < 64; k++) {
                float4 w = wr[k];
                s += w.x * h1[4*k] + w.y * h1[4*k+1] + w.z * h1[4*k+2] + w.w * h1[4*k+3];
            }
            h2[path][tid] = fmaxf(s, 0.f);
        }
    }
    __syncthreads();
    if (tid < 2) {
        float s = bout[tid];
        const float* wr = Wout + tid * 256;
        for (int i = 0; i < 128; i++)
            s += h2[0][i] * wr[i] + h2[1][i] * wr[128 + i];
        out[b * 2 + tid] = s;
    }
}

// ---- launch -------------------------------------------------------------------
extern "C" void kernel_launch(void* const* d_in, const int* in_sizes, int n_in,
                              void* d_out, int out_size)
{
    (void)in_sizes; (void)n_in; (void)out_size;
    const float* feat1 = (const float*)d_in[0];
    const float* feat2 = (const float*)d_in[1];
    const float* feat3 = (const float*)d_in[2];
    const float* Wa = (const float*)d_in[3];   const float* ba = (const float*)d_in[4];
    const float* Wb = (const float*)d_in[5];   const float* bb = (const float*)d_in[6];
    const float* Wc = (const float*)d_in[7];   const float* bc = (const float*)d_in[8];
    const float* Wcorr = (const float*)d_in[9];  const float* bcorr = (const float*)d_in[10];
    const float* Wcat = (const float*)d_in[11];  const float* bcat = (const float*)d_in[12];
    const float* cf_w1 = (const float*)d_in[13]; const float* cf_b1 = (const float*)d_in[14];
    const float* cf_w2 = (const float*)d_in[15]; const float* cf_b2 = (const float*)d_in[16];
    const float* ccf_w1 = (const float*)d_in[17]; const float* ccf_b1 = (const float*)d_in[18];
    const float* ccf_w2 = (const float*)d_in[19]; const float* ccf_b2 = (const float*)d_in[20];
    const float* Wout = (const float*)d_in[21];  const float* bout = (const float*)d_in[22];

    uint8_t *wh, *wl, *fih, *fil, *foh, *fol;
    float *G, *cvp, *tvp;
    cudaGetSymbolAddress((void**)&wh,  g_wh);
    cudaGetSymbolAddress((void**)&wl,  g_wl);
    cudaGetSymbolAddress((void**)&fih, g_finh);
    cudaGetSymbolAddress((void**)&fil, g_finl);
    cudaGetSymbolAddress((void**)&foh, g_fouth);
    cudaGetSymbolAddress((void**)&fol, g_foutl);
    cudaGetSymbolAddress((void**)&G,   g_gram);
    cudaGetSymbolAddress((void**)&cvp, g_corrpart);
    cudaGetSymbolAddress((void**)&tvp, g_catpart);

    cudaFuncSetAttribute(gemm_conv_kernel, cudaFuncAttributeMaxDynamicSharedMemorySize, CONV_SMEM);
    cudaFuncSetAttribute(gemm_gram_kernel, cudaFuncAttributeMaxDynamicSharedMemorySize, GRAM_SMEM);
    cudaFuncSetAttribute(corr_kernel, cudaFuncAttributeMaxDynamicSharedMemorySize, CORR_SMEM);

    convert_feat_kernel<<<dim3(128, 3, 4), 256>>>(feat1, feat2, feat3, fih, fil,
                                                  Wa, Wb, Wc, wh, wl);

    gemm_conv_kernel<<<dim3(8, 128, 3), 256, CONV_SMEM>>>(
        wh, wl, fih, fil, ba, bb, bc, foh, fol);

    gemm_gram_kernel<<<dim3(4, 128), 256, GRAM_SMEM>>>(foh, fol, G);

    corr_kernel<<<dim3(128, 9), 256, CORR_SMEM>>>(G, Wcorr, cvp);
    cat_kernel<<<dim3(128, 48), 256, CAT_SMEM>>>(foh, fol, Wcat, tvp);

    mlp_kernel<<<128, 256>>>(cvp, tvp, bcorr, bcat,
                             cf_w1, cf_b1, cf_w2, cf_b2,
                             ccf_w1, ccf_b1, ccf_w2, ccf_b2, Wout, bout, (float*)d_out);
}